// round 1
// baseline (speedup 1.0000x reference)
#include <cuda_runtime.h>
#include <cuda_bf16.h>
#include <math.h>

#define S_LEN   2048
#define HIDDEN  3584
#define NH      28
#define NKV     4
#define HD      128
#define GROUPS  7
#define SCALING 0.08838834764831845f

// ---------------- scratch (device globals, no allocation) ----------------
__device__ float g_q [NH  * S_LEN * HD];   // [h][s][d]
__device__ float g_k [NKV * S_LEN * HD];   // [kh][s][d]
__device__ float g_v [NKV * S_LEN * HD];   // [kh][s][d]
__device__ float g_ao[S_LEN * NH * HD];    // [s][h*128+d]

// ---------------- SGEMM: C = A[M,K] * W[N,K]^T (+bias) ----------------
// 128x128 tile, BK=8, 256 threads, 8x8 micro-tile per thread.
// out_mode 0: head-major  C[(n/128)][m][n%128]   (for Q/K/V)
// out_mode 1: row-major   C[m][n]                (for O proj)
__global__ void __launch_bounds__(256, 2)
gemm_xwT(const float* __restrict__ A, const float* __restrict__ W,
         const float* __restrict__ bias, float* __restrict__ C,
         int M, int N, int K, int out_mode)
{
    __shared__ float As[8][128];
    __shared__ float Bs[8][128];

    const int bm = blockIdx.y * 128;
    const int bn = blockIdx.x * 128;
    const int tid = threadIdx.x;

    const int lr = tid >> 1;          // 0..127
    const int lc = (tid & 1) * 4;     // 0 or 4
    const float* Aptr = A + (size_t)(bm + lr) * K + lc;
    const float* Wptr = W + (size_t)(bn + lr) * K + lc;

    const int ty = tid >> 4;          // 0..15
    const int tx = tid & 15;          // 0..15

    float acc[8][8];
#pragma unroll
    for (int i = 0; i < 8; i++)
#pragma unroll
        for (int j = 0; j < 8; j++) acc[i][j] = 0.f;

    for (int k0 = 0; k0 < K; k0 += 8) {
        float4 a4 = *(const float4*)(Aptr + k0);
        float4 b4 = *(const float4*)(Wptr + k0);
        __syncthreads();
        As[lc + 0][lr] = a4.x; As[lc + 1][lr] = a4.y;
        As[lc + 2][lr] = a4.z; As[lc + 3][lr] = a4.w;
        Bs[lc + 0][lr] = b4.x; Bs[lc + 1][lr] = b4.y;
        Bs[lc + 2][lr] = b4.z; Bs[lc + 3][lr] = b4.w;
        __syncthreads();

#pragma unroll
        for (int kk = 0; kk < 8; kk++) {
            float ar[8], br[8];
            *(float4*)(ar)     = *(const float4*)&As[kk][ty * 8];
            *(float4*)(ar + 4) = *(const float4*)&As[kk][ty * 8 + 4];
            *(float4*)(br)     = *(const float4*)&Bs[kk][tx * 8];
            *(float4*)(br + 4) = *(const float4*)&Bs[kk][tx * 8 + 4];
#pragma unroll
            for (int i = 0; i < 8; i++)
#pragma unroll
                for (int j = 0; j < 8; j++)
                    acc[i][j] += ar[i] * br[j];
        }
    }

    // epilogue
    float bj[8];
#pragma unroll
    for (int j = 0; j < 8; j++)
        bj[j] = bias ? bias[bn + tx * 8 + j] : 0.f;

    if (out_mode == 0) {
        // head-major: head fixed per block (bn multiple of 128)
        float* out = C + (size_t)(bn >> 7) * M * HD;
#pragma unroll
        for (int i = 0; i < 8; i++) {
            int m = bm + ty * 8 + i;
            float4 v0, v1;
            v0.x = acc[i][0] + bj[0]; v0.y = acc[i][1] + bj[1];
            v0.z = acc[i][2] + bj[2]; v0.w = acc[i][3] + bj[3];
            v1.x = acc[i][4] + bj[4]; v1.y = acc[i][5] + bj[5];
            v1.z = acc[i][6] + bj[6]; v1.w = acc[i][7] + bj[7];
            *(float4*)(out + (size_t)m * HD + tx * 8)     = v0;
            *(float4*)(out + (size_t)m * HD + tx * 8 + 4) = v1;
        }
    } else {
#pragma unroll
        for (int i = 0; i < 8; i++) {
            int m = bm + ty * 8 + i;
            float4 v0, v1;
            v0.x = acc[i][0] + bj[0]; v0.y = acc[i][1] + bj[1];
            v0.z = acc[i][2] + bj[2]; v0.w = acc[i][3] + bj[3];
            v1.x = acc[i][4] + bj[4]; v1.y = acc[i][5] + bj[5];
            v1.z = acc[i][6] + bj[6]; v1.w = acc[i][7] + bj[7];
            *(float4*)(C + (size_t)m * N + bn + tx * 8)     = v0;
            *(float4*)(C + (size_t)m * N + bn + tx * 8 + 4) = v1;
        }
    }
}

// ---------------- RoPE (in place on [h][s][128] buffers) ----------------
__global__ void rope_kernel(float* __restrict__ buf,
                            const float* __restrict__ cosb,
                            const float* __restrict__ sinb,
                            int nheads)
{
    int i = blockIdx.x * blockDim.x + threadIdx.x;
    int total = nheads * S_LEN * 64;
    if (i >= total) return;
    int d = i & 63;
    int s = (i >> 6) & (S_LEN - 1);
    int h = i >> 17;
    float* row = buf + ((size_t)h * S_LEN + s) * HD;
    float c1 = cosb[s * HD + d];
    float c2 = cosb[s * HD + d + 64];
    float s1 = sinb[s * HD + d];
    float s2 = sinb[s * HD + d + 64];
    float x1 = row[d];
    float x2 = row[d + 64];
    row[d]      = x1 * c1 - x2 * s1;
    row[d + 64] = x2 * c2 + x1 * s2;
}

// ---------------- flash attention (causal, GQA) ----------------
// BM = BN = 64, 256 threads. smem: Q/K/V [64][132] + S [64][68]
#define QKV_STRIDE 132
#define S_STRIDE   68
#define ATTN_SMEM  ((3 * 64 * QKV_STRIDE + 64 * S_STRIDE) * 4)

__global__ void __launch_bounds__(256, 1)
attn_kernel(const float* __restrict__ Q, const float* __restrict__ K,
            const float* __restrict__ V, float* __restrict__ Oout)
{
    extern __shared__ float sm[];
    float* Qs = sm;
    float* Ks = Qs + 64 * QKV_STRIDE;
    float* Vs = Ks + 64 * QKV_STRIDE;
    float* Ss = Vs + 64 * QKV_STRIDE;

    const int qb  = blockIdx.x;          // query block (64 rows)
    const int h   = blockIdx.y;          // head
    const int kvh = h / GROUPS;
    const int tid = threadIdx.x;

    // load Q tile
    const float* Qg = Q + ((size_t)h * S_LEN + qb * 64) * HD;
    for (int i = tid; i < 64 * 32; i += 256) {
        int r  = i >> 5;
        int c4 = (i & 31) << 2;
        *(float4*)(Qs + r * QKV_STRIDE + c4) = *(const float4*)(Qg + r * HD + c4);
    }

    float acc[32];
#pragma unroll
    for (int c = 0; c < 32; c++) acc[c] = 0.f;
    float m_r = -1e30f, l_r = 0.f;

    const int ty  = tid >> 4, tx = tid & 15;   // S-compute mapping (4x4 tiles)
    const int row = tid >> 2;                  // softmax / PV mapping
    const int cg  = tid & 3;

    for (int kt = 0; kt <= qb; kt++) {
        const float* Kg = K + ((size_t)kvh * S_LEN + kt * 64) * HD;
        const float* Vg = V + ((size_t)kvh * S_LEN + kt * 64) * HD;

        __syncthreads();   // previous iteration done with Ks/Vs/Ss
        for (int i = tid; i < 64 * 32; i += 256) {
            int r  = i >> 5;
            int c4 = (i & 31) << 2;
            *(float4*)(Ks + r * QKV_STRIDE + c4) = *(const float4*)(Kg + r * HD + c4);
            *(float4*)(Vs + r * QKV_STRIDE + c4) = *(const float4*)(Vg + r * HD + c4);
        }
        __syncthreads();

        // S = Q K^T  (64x64), thread does 4x4
        float sacc[4][4];
#pragma unroll
        for (int i = 0; i < 4; i++)
#pragma unroll
            for (int j = 0; j < 4; j++) sacc[i][j] = 0.f;

#pragma unroll 8
        for (int d4 = 0; d4 < HD; d4 += 4) {
            float4 qa[4], kb[4];
#pragma unroll
            for (int i = 0; i < 4; i++)
                qa[i] = *(const float4*)(Qs + (ty * 4 + i) * QKV_STRIDE + d4);
#pragma unroll
            for (int j = 0; j < 4; j++)
                kb[j] = *(const float4*)(Ks + (tx * 4 + j) * QKV_STRIDE + d4);
#pragma unroll
            for (int i = 0; i < 4; i++)
#pragma unroll
                for (int j = 0; j < 4; j++) {
                    sacc[i][j] += qa[i].x * kb[j].x;
                    sacc[i][j] += qa[i].y * kb[j].y;
                    sacc[i][j] += qa[i].z * kb[j].z;
                    sacc[i][j] += qa[i].w * kb[j].w;
                }
        }

        const bool diag = (kt == qb);
#pragma unroll
        for (int i = 0; i < 4; i++)
#pragma unroll
            for (int j = 0; j < 4; j++) {
                float v = sacc[i][j] * SCALING;
                if (diag) {
                    int qr = ty * 4 + i;
                    int kc = tx * 4 + j;
                    if (kc > qr) v = -1e30f;
                }
                Ss[(ty * 4 + i) * S_STRIDE + tx * 4 + j] = v;
            }
        __syncthreads();

        // online softmax: 4 threads per row, 16 cols each
        const int cb = cg * 16;
        float svals[16];
        float pmax = -1e30f;
#pragma unroll
        for (int j = 0; j < 16; j++) {
            svals[j] = Ss[row * S_STRIDE + cb + j];
            pmax = fmaxf(pmax, svals[j]);
        }
        pmax = fmaxf(pmax, __shfl_xor_sync(0xffffffffu, pmax, 1));
        pmax = fmaxf(pmax, __shfl_xor_sync(0xffffffffu, pmax, 2));
        float m_new = fmaxf(m_r, pmax);
        float corr  = __expf(m_r - m_new);
        float psum = 0.f;
#pragma unroll
        for (int j = 0; j < 16; j++) {
            float p = __expf(svals[j] - m_new);
            psum += p;
            Ss[row * S_STRIDE + cb + j] = p;
        }
        psum += __shfl_xor_sync(0xffffffffu, psum, 1);
        psum += __shfl_xor_sync(0xffffffffu, psum, 2);
        l_r = l_r * corr + psum;
        m_r = m_new;
#pragma unroll
        for (int c = 0; c < 32; c++) acc[c] *= corr;
        __syncthreads();   // all p values stored

        // O += P @ V  (thread: 1 row x 32 cols)
        const int ob = cg * 32;
#pragma unroll 4
        for (int kk = 0; kk < 64; kk++) {
            float p = Ss[row * S_STRIDE + kk];
            const float4* vrow = (const float4*)(Vs + kk * QKV_STRIDE + ob);
#pragma unroll
            for (int c4 = 0; c4 < 8; c4++) {
                float4 vv = vrow[c4];
                acc[c4 * 4 + 0] += p * vv.x;
                acc[c4 * 4 + 1] += p * vv.y;
                acc[c4 * 4 + 2] += p * vv.z;
                acc[c4 * 4 + 3] += p * vv.w;
            }
        }
    }

    // write out: g_ao[s][h*128 + c]
    float inv = 1.f / l_r;
    float* Og = Oout + (size_t)(qb * 64 + row) * (NH * HD) + h * HD + cg * 32;
#pragma unroll
    for (int c4 = 0; c4 < 8; c4++) {
        float4 v;
        v.x = acc[c4 * 4 + 0] * inv;
        v.y = acc[c4 * 4 + 1] * inv;
        v.z = acc[c4 * 4 + 2] * inv;
        v.w = acc[c4 * 4 + 3] * inv;
        *(float4*)(Og + c4 * 4) = v;
    }
}

// ---------------- launch ----------------
extern "C" void kernel_launch(void* const* d_in, const int* in_sizes, int n_in,
                              void* d_out, int out_size)
{
    const float* hs   = (const float*)d_in[0];
    const float* cosb = (const float*)d_in[1];
    const float* sinb = (const float*)d_in[2];
    const float* Wq   = (const float*)d_in[3];
    const float* bq   = (const float*)d_in[4];
    const float* Wk   = (const float*)d_in[5];
    const float* bk   = (const float*)d_in[6];
    const float* Wv   = (const float*)d_in[7];
    const float* bv   = (const float*)d_in[8];
    const float* Wo   = (const float*)d_in[9];
    float* out = (float*)d_out;

    float *pq, *pk, *pv, *pao;
    cudaGetSymbolAddress((void**)&pq,  g_q);
    cudaGetSymbolAddress((void**)&pk,  g_k);
    cudaGetSymbolAddress((void**)&pv,  g_v);
    cudaGetSymbolAddress((void**)&pao, g_ao);

    // QKV projections (head-major outputs)
    gemm_xwT<<<dim3(NH,  S_LEN / 128), 256>>>(hs, Wq, bq, pq, S_LEN, NH  * HD, HIDDEN, 0);
    gemm_xwT<<<dim3(NKV, S_LEN / 128), 256>>>(hs, Wk, bk, pk, S_LEN, NKV * HD, HIDDEN, 0);
    gemm_xwT<<<dim3(NKV, S_LEN / 128), 256>>>(hs, Wv, bv, pv, S_LEN, NKV * HD, HIDDEN, 0);

    // RoPE on Q and K
    rope_kernel<<<(NH  * S_LEN * 64 + 255) / 256, 256>>>(pq, cosb, sinb, NH);
    rope_kernel<<<(NKV * S_LEN * 64 + 255) / 256, 256>>>(pk, cosb, sinb, NKV);

    // flash attention
    cudaFuncSetAttribute(attn_kernel, cudaFuncAttributeMaxDynamicSharedMemorySize, ATTN_SMEM);
    attn_kernel<<<dim3(S_LEN / 64, NH), 256, ATTN_SMEM>>>(pq, pk, pv, pao);

    // output projection (row-major, no bias)
    gemm_xwT<<<dim3(NH, S_LEN / 128), 256>>>(pao, Wo, nullptr, out, S_LEN, HIDDEN, HIDDEN, 1);
}

// round 4
// speedup vs baseline: 1.3616x; 1.3616x over previous
#include <cuda_runtime.h>
#include <cuda_bf16.h>
#include <math.h>
#include <stdint.h>

#define S_LEN   2048
#define HIDDEN  3584
#define NH      28
#define NKV     4
#define HD      128
#define GROUPS  7
#define SCALING 0.08838834764831845f

// ---------------- scratch (device globals, no allocation) ----------------
__device__ float g_q [NH  * S_LEN * HD];
__device__ float g_k [NKV * S_LEN * HD];
__device__ float g_v [NKV * S_LEN * HD];
__device__ float g_ao[S_LEN * NH * HD];

__device__ __nv_bfloat16 g_hs_hi[S_LEN * HIDDEN];
__device__ __nv_bfloat16 g_hs_lo[S_LEN * HIDDEN];
__device__ __nv_bfloat16 g_wq_hi[NH * HD * HIDDEN];
__device__ __nv_bfloat16 g_wq_lo[NH * HD * HIDDEN];
__device__ __nv_bfloat16 g_wk_hi[NKV * HD * HIDDEN];
__device__ __nv_bfloat16 g_wk_lo[NKV * HD * HIDDEN];
__device__ __nv_bfloat16 g_wv_hi[NKV * HD * HIDDEN];
__device__ __nv_bfloat16 g_wv_lo[NKV * HD * HIDDEN];
__device__ __nv_bfloat16 g_wo_hi[HIDDEN * NH * HD];
__device__ __nv_bfloat16 g_wo_lo[HIDDEN * NH * HD];
__device__ __nv_bfloat16 g_ao_hi[S_LEN * NH * HD];
__device__ __nv_bfloat16 g_ao_lo[S_LEN * NH * HD];

// ---------------- PTX helpers ----------------
__device__ __forceinline__ uint32_t smem_u32(const void* p) {
    uint32_t a;
    asm("{ .reg .u64 t; cvta.to.shared.u64 t, %1; cvt.u32.u64 %0, t; }" : "=r"(a) : "l"(p));
    return a;
}
__device__ __forceinline__ void mma16816(float* c, const uint32_t* a, const uint32_t* b) {
    asm volatile("mma.sync.aligned.m16n8k16.row.col.f32.bf16.bf16.f32 "
        "{%0,%1,%2,%3}, {%4,%5,%6,%7}, {%8,%9}, {%0,%1,%2,%3};"
        : "+f"(c[0]), "+f"(c[1]), "+f"(c[2]), "+f"(c[3])
        : "r"(a[0]), "r"(a[1]), "r"(a[2]), "r"(a[3]), "r"(b[0]), "r"(b[1]));
}
__device__ __forceinline__ void ldsm4(uint32_t* r, uint32_t addr) {
    asm volatile("ldmatrix.sync.aligned.m8n8.x4.shared.b16 {%0,%1,%2,%3}, [%4];"
        : "=r"(r[0]), "=r"(r[1]), "=r"(r[2]), "=r"(r[3]) : "r"(addr));
}

#define GEMM_SMEM (64 * 1024)

// ---------------- GEMM: C = A[M,K] * W[N,K]^T (+bias), bf16x3, fp32 out ----------------
// HMMA path (mma.sync m16n8k16 bf16). 128x128 tile, BK=64, double-buffered.
// out_mode 0: head-major  C[(n/128)][m][n%128] ; out_mode 1: row-major C[m][n]
__global__ void __launch_bounds__(256, 1)
gemm_tc(const __nv_bfloat16* __restrict__ Ahi, const __nv_bfloat16* __restrict__ Alo,
        const __nv_bfloat16* __restrict__ Bhi, const __nv_bfloat16* __restrict__ Blo,
        const float* __restrict__ bias, float* __restrict__ C,
        int M, int N, int K, int out_mode)
{
    extern __shared__ __align__(1024) char smc[];
    const int tid = threadIdx.x, wid = tid >> 5, lane = tid & 31;
    const int bm = blockIdx.y << 7, bn = blockIdx.x << 7;
    const uint32_t sbase = smem_u32(smc);
    const int NC = K >> 6;         // 64-wide K chunks per pass
    const int total = NC * 3;      // 3 passes: AhiBhi, AloBhi, AhiBlo

    // cooperative load mapping: 1024 16B-vectors per (A or B) chunk, 4 per thread
    int rowj[4], c8j[4];
    uint32_t soffj[4];
#pragma unroll
    for (int j = 0; j < 4; j++) {
        int idx = tid + j * 256;
        rowj[j] = idx >> 3;          // 0..127
        c8j[j]  = idx & 7;           // 16B column within 128B row
        uint32_t so = (uint32_t)(rowj[j] * 128 + c8j[j] * 16);
        soffj[j] = so ^ ((so >> 3) & 0x70);   // SW128 swizzle
    }

    // warp tiling: 4 m-warps x 2 n-warps; each warp 32(m) x 64(n)
    const int wm = wid & 3;
    const int wn = wid >> 2;

    uint32_t a_base[2], aswz[2], b_base[4], bswz[4];
    const uint32_t acol = (uint32_t)((lane >> 4) << 4);          // k half for A
    const uint32_t bcol = (uint32_t)(((lane >> 3) & 1) << 4);    // k half for B
#pragma unroll
    for (int mi = 0; mi < 2; mi++) {
        int r = wm * 32 + mi * 16 + (lane & 15);
        a_base[mi] = sbase + r * 128;
        aswz[mi]   = (uint32_t)((r & 7) << 4);
    }
#pragma unroll
    for (int p = 0; p < 4; p++) {
        int r = wn * 64 + p * 16 + ((lane >> 4) & 1) * 8 + (lane & 7);
        b_base[p] = sbase + 16384 + r * 128;
        bswz[p]   = (uint32_t)((r & 7) << 4);
    }

    float acc[2][8][4];
#pragma unroll
    for (int mi = 0; mi < 2; mi++)
#pragma unroll
        for (int ni = 0; ni < 8; ni++)
#pragma unroll
            for (int q = 0; q < 4; q++) acc[mi][ni][q] = 0.f;

    // prologue: chunk 0 -> buf0
#pragma unroll
    for (int j = 0; j < 4; j++) {
        uint4 ra = *(const uint4*)(Ahi + (size_t)(bm + rowj[j]) * K + c8j[j] * 8);
        uint4 rb = *(const uint4*)(Bhi + (size_t)(bn + rowj[j]) * K + c8j[j] * 8);
        *(uint4*)(smc + soffj[j])         = ra;
        *(uint4*)(smc + 16384 + soffj[j]) = rb;
    }
    // reg-prefetch chunk 1
    uint4 pra[4], prb[4];
    if (total > 1) {
        int cn = 1, kc = 1;
        const __nv_bfloat16 *pa = Ahi, *pb = Bhi;
        if (cn >= 2 * NC)  { pb = Blo; kc = cn - 2 * NC; }
        else if (cn >= NC) { pa = Alo; kc = cn - NC; }
#pragma unroll
        for (int j = 0; j < 4; j++) {
            pra[j] = *(const uint4*)(pa + (size_t)(bm + rowj[j]) * K + kc * 64 + c8j[j] * 8);
            prb[j] = *(const uint4*)(pb + (size_t)(bn + rowj[j]) * K + kc * 64 + c8j[j] * 8);
        }
    }
    __syncthreads();

    for (int c = 0; c < total; c++) {
        const int buf = c & 1;
        if (c + 1 < total) {
            const uint32_t nboff = (uint32_t)((buf ^ 1) * 32768);
#pragma unroll
            for (int j = 0; j < 4; j++) {
                *(uint4*)(smc + nboff + soffj[j])         = pra[j];
                *(uint4*)(smc + nboff + 16384 + soffj[j]) = prb[j];
            }
        }
        if (c + 2 < total) {
            int cn = c + 2, kc = cn;
            const __nv_bfloat16 *pa = Ahi, *pb = Bhi;
            if (cn >= 2 * NC)  { pb = Blo; kc = cn - 2 * NC; }
            else if (cn >= NC) { pa = Alo; kc = cn - NC; }
#pragma unroll
            for (int j = 0; j < 4; j++) {
                pra[j] = *(const uint4*)(pa + (size_t)(bm + rowj[j]) * K + kc * 64 + c8j[j] * 8);
                prb[j] = *(const uint4*)(pb + (size_t)(bn + rowj[j]) * K + kc * 64 + c8j[j] * 8);
            }
        }
        const uint32_t bufoff = (uint32_t)(buf * 32768);
#pragma unroll
        for (int s = 0; s < 4; s++) {
            uint32_t af[2][4], bfr[4][4];
#pragma unroll
            for (int mi = 0; mi < 2; mi++)
                ldsm4(af[mi], a_base[mi] + bufoff + (uint32_t)(((uint32_t)(s * 32) + acol) ^ aswz[mi]));
#pragma unroll
            for (int p = 0; p < 4; p++)
                ldsm4(bfr[p], b_base[p] + bufoff + (uint32_t)(((uint32_t)(s * 32) + bcol) ^ bswz[p]));
#pragma unroll
            for (int mi = 0; mi < 2; mi++)
#pragma unroll
                for (int ni = 0; ni < 8; ni++)
                    mma16816(acc[mi][ni], af[mi], &bfr[ni >> 1][(ni & 1) * 2]);
        }
        __syncthreads();
    }

    // epilogue
#pragma unroll
    for (int mi = 0; mi < 2; mi++) {
        int r0 = wm * 32 + mi * 16 + (lane >> 2);
#pragma unroll
        for (int ni = 0; ni < 8; ni++) {
            int ncol = wn * 64 + ni * 8 + (lane & 3) * 2;
            float b0 = bias ? bias[bn + ncol]     : 0.f;
            float b1 = bias ? bias[bn + ncol + 1] : 0.f;
            float2 v0 = make_float2(acc[mi][ni][0] + b0, acc[mi][ni][1] + b1);
            float2 v1 = make_float2(acc[mi][ni][2] + b0, acc[mi][ni][3] + b1);
            if (out_mode == 0) {
                float* base = C + (size_t)(bn >> 7) * M * HD;
                *(float2*)(base + (size_t)(bm + r0) * HD + ncol)     = v0;
                *(float2*)(base + (size_t)(bm + r0 + 8) * HD + ncol) = v1;
            } else {
                *(float2*)(C + (size_t)(bm + r0) * N + bn + ncol)     = v0;
                *(float2*)(C + (size_t)(bm + r0 + 8) * N + bn + ncol) = v1;
            }
        }
    }
}

// ---------------- fp32 -> bf16 hi/lo split ----------------
__global__ void split_kernel(const float* __restrict__ x,
                             __nv_bfloat16* __restrict__ hi,
                             __nv_bfloat16* __restrict__ lo, int n4)
{
    int i = blockIdx.x * blockDim.x + threadIdx.x;
    if (i >= n4) return;
    float4 v = ((const float4*)x)[i];
    __nv_bfloat16 h0 = __float2bfloat16(v.x), h1 = __float2bfloat16(v.y);
    __nv_bfloat16 h2 = __float2bfloat16(v.z), h3 = __float2bfloat16(v.w);
    __nv_bfloat16 l0 = __float2bfloat16(v.x - __bfloat162float(h0));
    __nv_bfloat16 l1 = __float2bfloat16(v.y - __bfloat162float(h1));
    __nv_bfloat16 l2 = __float2bfloat16(v.z - __bfloat162float(h2));
    __nv_bfloat16 l3 = __float2bfloat16(v.w - __bfloat162float(h3));
    __nv_bfloat162* hp = (__nv_bfloat162*)hi;
    __nv_bfloat162* lp = (__nv_bfloat162*)lo;
    hp[i*2]   = __halves2bfloat162(h0, h1);
    hp[i*2+1] = __halves2bfloat162(h2, h3);
    lp[i*2]   = __halves2bfloat162(l0, l1);
    lp[i*2+1] = __halves2bfloat162(l2, l3);
}

// ---------------- RoPE (in place on [h][s][128] buffers) ----------------
__global__ void rope_kernel(float* __restrict__ buf,
                            const float* __restrict__ cosb,
                            const float* __restrict__ sinb,
                            int nheads)
{
    int i = blockIdx.x * blockDim.x + threadIdx.x;
    int total = nheads * S_LEN * 64;
    if (i >= total) return;
    int d = i & 63;
    int s = (i >> 6) & (S_LEN - 1);
    int h = i >> 17;
    float* row = buf + ((size_t)h * S_LEN + s) * HD;
    float c1 = cosb[s * HD + d];
    float c2 = cosb[s * HD + d + 64];
    float s1 = sinb[s * HD + d];
    float s2 = sinb[s * HD + d + 64];
    float x1 = row[d];
    float x2 = row[d + 64];
    row[d]      = x1 * c1 - x2 * s1;
    row[d + 64] = x2 * c2 + x1 * s2;
}

// ---------------- flash attention (causal, GQA), fp32 ----------------
#define QKV_STRIDE 132
#define S_STRIDE   68
#define ATTN_SMEM  ((3 * 64 * QKV_STRIDE + 64 * S_STRIDE) * 4)

__global__ void __launch_bounds__(256, 1)
attn_kernel(const float* __restrict__ Q, const float* __restrict__ K,
            const float* __restrict__ V, float* __restrict__ Oout)
{
    extern __shared__ float sm[];
    float* Qs = sm;
    float* Ks = Qs + 64 * QKV_STRIDE;
    float* Vs = Ks + 64 * QKV_STRIDE;
    float* Ss = Vs + 64 * QKV_STRIDE;

    const int qb  = (int)gridDim.x - 1 - (int)blockIdx.x;
    const int h   = blockIdx.y;
    const int kvh = h / GROUPS;
    const int tid = threadIdx.x;

    const float* Qg = Q + ((size_t)h * S_LEN + qb * 64) * HD;
    for (int i = tid; i < 64 * 32; i += 256) {
        int r  = i >> 5;
        int c4 = (i & 31) << 2;
        *(float4*)(Qs + r * QKV_STRIDE + c4) = *(const float4*)(Qg + r * HD + c4);
    }

    float acc[32];
#pragma unroll
    for (int c = 0; c < 32; c++) acc[c] = 0.f;
    float m_r = -1e30f, l_r = 0.f;

    const int ty  = tid >> 4, tx = tid & 15;
    const int row = tid >> 2;
    const int cg  = tid & 3;

    for (int kt = 0; kt <= qb; kt++) {
        const float* Kg = K + ((size_t)kvh * S_LEN + kt * 64) * HD;
        const float* Vg = V + ((size_t)kvh * S_LEN + kt * 64) * HD;

        __syncthreads();
        for (int i = tid; i < 64 * 32; i += 256) {
            int r  = i >> 5;
            int c4 = (i & 31) << 2;
            *(float4*)(Ks + r * QKV_STRIDE + c4) = *(const float4*)(Kg + r * HD + c4);
            *(float4*)(Vs + r * QKV_STRIDE + c4) = *(const float4*)(Vg + r * HD + c4);
        }
        __syncthreads();

        float sacc[4][4];
#pragma unroll
        for (int i = 0; i < 4; i++)
#pragma unroll
            for (int j = 0; j < 4; j++) sacc[i][j] = 0.f;

#pragma unroll 8
        for (int d4 = 0; d4 < HD; d4 += 4) {
            float4 qa[4], kb[4];
#pragma unroll
            for (int i = 0; i < 4; i++)
                qa[i] = *(const float4*)(Qs + (ty * 4 + i) * QKV_STRIDE + d4);
#pragma unroll
            for (int j = 0; j < 4; j++)
                kb[j] = *(const float4*)(Ks + (tx * 4 + j) * QKV_STRIDE + d4);
#pragma unroll
            for (int i = 0; i < 4; i++)
#pragma unroll
                for (int j = 0; j < 4; j++) {
                    sacc[i][j] += qa[i].x * kb[j].x;
                    sacc[i][j] += qa[i].y * kb[j].y;
                    sacc[i][j] += qa[i].z * kb[j].z;
                    sacc[i][j] += qa[i].w * kb[j].w;
                }
        }

        const bool diag = (kt == qb);
#pragma unroll
        for (int i = 0; i < 4; i++)
#pragma unroll
            for (int j = 0; j < 4; j++) {
                float v = sacc[i][j] * SCALING;
                if (diag) {
                    int qr = ty * 4 + i;
                    int kc = tx * 4 + j;
                    if (kc > qr) v = -1e30f;
                }
                Ss[(ty * 4 + i) * S_STRIDE + tx * 4 + j] = v;
            }
        __syncthreads();

        const int cb = cg * 16;
        float svals[16];
        float pmax = -1e30f;
#pragma unroll
        for (int j = 0; j < 16; j++) {
            svals[j] = Ss[row * S_STRIDE + cb + j];
            pmax = fmaxf(pmax, svals[j]);
        }
        pmax = fmaxf(pmax, __shfl_xor_sync(0xffffffffu, pmax, 1));
        pmax = fmaxf(pmax, __shfl_xor_sync(0xffffffffu, pmax, 2));
        float m_new = fmaxf(m_r, pmax);
        float corr  = __expf(m_r - m_new);
        float psum = 0.f;
#pragma unroll
        for (int j = 0; j < 16; j++) {
            float p = __expf(svals[j] - m_new);
            psum += p;
            Ss[row * S_STRIDE + cb + j] = p;
        }
        psum += __shfl_xor_sync(0xffffffffu, psum, 1);
        psum += __shfl_xor_sync(0xffffffffu, psum, 2);
        l_r = l_r * corr + psum;
        m_r = m_new;
#pragma unroll
        for (int c = 0; c < 32; c++) acc[c] *= corr;
        __syncthreads();

        const int ob = cg * 32;
#pragma unroll 4
        for (int kk = 0; kk < 64; kk++) {
            float p = Ss[row * S_STRIDE + kk];
            const float4* vrow = (const float4*)(Vs + kk * QKV_STRIDE + ob);
#pragma unroll
            for (int c4 = 0; c4 < 8; c4++) {
                float4 vv = vrow[c4];
                acc[c4 * 4 + 0] += p * vv.x;
                acc[c4 * 4 + 1] += p * vv.y;
                acc[c4 * 4 + 2] += p * vv.z;
                acc[c4 * 4 + 3] += p * vv.w;
            }
        }
    }

    float inv = 1.f / l_r;
    float* Og = Oout + (size_t)(qb * 64 + row) * (NH * HD) + h * HD + cg * 32;
#pragma unroll
    for (int c4 = 0; c4 < 8; c4++) {
        float4 v;
        v.x = acc[c4 * 4 + 0] * inv;
        v.y = acc[c4 * 4 + 1] * inv;
        v.z = acc[c4 * 4 + 2] * inv;
        v.w = acc[c4 * 4 + 3] * inv;
        *(float4*)(Og + c4 * 4) = v;
    }
}

// ---------------- launch ----------------
extern "C" void kernel_launch(void* const* d_in, const int* in_sizes, int n_in,
                              void* d_out, int out_size)
{
    const float* hs   = (const float*)d_in[0];
    const float* cosb = (const float*)d_in[1];
    const float* sinb = (const float*)d_in[2];
    const float* Wq   = (const float*)d_in[3];
    const float* bq   = (const float*)d_in[4];
    const float* Wk   = (const float*)d_in[5];
    const float* bk   = (const float*)d_in[6];
    const float* Wv   = (const float*)d_in[7];
    const float* bv   = (const float*)d_in[8];
    const float* Wo   = (const float*)d_in[9];
    float* out = (float*)d_out;

    float *pq, *pk, *pv, *pao;
    cudaGetSymbolAddress((void**)&pq,  g_q);
    cudaGetSymbolAddress((void**)&pk,  g_k);
    cudaGetSymbolAddress((void**)&pv,  g_v);
    cudaGetSymbolAddress((void**)&pao, g_ao);

    __nv_bfloat16 *hs_hi, *hs_lo, *wq_hi, *wq_lo, *wk_hi, *wk_lo;
    __nv_bfloat16 *wv_hi, *wv_lo, *wo_hi, *wo_lo, *ao_hi, *ao_lo;
    cudaGetSymbolAddress((void**)&hs_hi, g_hs_hi);
    cudaGetSymbolAddress((void**)&hs_lo, g_hs_lo);
    cudaGetSymbolAddress((void**)&wq_hi, g_wq_hi);
    cudaGetSymbolAddress((void**)&wq_lo, g_wq_lo);
    cudaGetSymbolAddress((void**)&wk_hi, g_wk_hi);
    cudaGetSymbolAddress((void**)&wk_lo, g_wk_lo);
    cudaGetSymbolAddress((void**)&wv_hi, g_wv_hi);
    cudaGetSymbolAddress((void**)&wv_lo, g_wv_lo);
    cudaGetSymbolAddress((void**)&wo_hi, g_wo_hi);
    cudaGetSymbolAddress((void**)&wo_lo, g_wo_lo);
    cudaGetSymbolAddress((void**)&ao_hi, g_ao_hi);
    cudaGetSymbolAddress((void**)&ao_lo, g_ao_lo);

    auto split = [&](const float* x, __nv_bfloat16* h, __nv_bfloat16* l, int n) {
        int n4 = n / 4;
        split_kernel<<<(n4 + 255) / 256, 256>>>(x, h, l, n4);
    };

    split(hs, hs_hi, hs_lo, S_LEN * HIDDEN);
    split(Wq, wq_hi, wq_lo, NH  * HD * HIDDEN);
    split(Wk, wk_hi, wk_lo, NKV * HD * HIDDEN);
    split(Wv, wv_hi, wv_lo, NKV * HD * HIDDEN);
    split(Wo, wo_hi, wo_lo, HIDDEN * NH * HD);

    cudaFuncSetAttribute(gemm_tc, cudaFuncAttributeMaxDynamicSharedMemorySize, GEMM_SMEM);

    gemm_tc<<<dim3(NH,  16), 256, GEMM_SMEM>>>(hs_hi, hs_lo, wq_hi, wq_lo, bq, pq,
                                               S_LEN, NH  * HD, HIDDEN, 0);
    gemm_tc<<<dim3(NKV, 16), 256, GEMM_SMEM>>>(hs_hi, hs_lo, wk_hi, wk_lo, bk, pk,
                                               S_LEN, NKV * HD, HIDDEN, 0);
    gemm_tc<<<dim3(NKV, 16), 256, GEMM_SMEM>>>(hs_hi, hs_lo, wv_hi, wv_lo, bv, pv,
                                               S_LEN, NKV * HD, HIDDEN, 0);

    rope_kernel<<<(NH  * S_LEN * 64 + 255) / 256, 256>>>(pq, cosb, sinb, NH);
    rope_kernel<<<(NKV * S_LEN * 64 + 255) / 256, 256>>>(pk, cosb, sinb, NKV);

    cudaFuncSetAttribute(attn_kernel, cudaFuncAttributeMaxDynamicSharedMemorySize, ATTN_SMEM);
    attn_kernel<<<dim3(S_LEN / 64, NH), 256, ATTN_SMEM>>>(pq, pk, pv, pao);

    split(pao, ao_hi, ao_lo, S_LEN * NH * HD);
    gemm_tc<<<dim3(NH, 16), 256, GEMM_SMEM>>>(ao_hi, ao_lo, wo_hi, wo_lo, nullptr, out,
                                              S_LEN, HIDDEN, NH * HD, 1);
}

// round 7
// speedup vs baseline: 5.3406x; 3.9222x over previous
#include <cuda_runtime.h>
#include <cuda_fp16.h>
#include <math.h>
#include <stdint.h>

#define S_LEN   2048
#define HIDDEN  3584
#define NH      28
#define NKV     4
#define HD      128
#define GROUPS  7
#define SCALING 0.08838834764831845f

// ---------------- scratch (device globals, no allocation) ----------------
__device__ float g_q [NH  * S_LEN * HD];   // fp32 pre-rope Q
__device__ float g_k [NKV * S_LEN * HD];   // fp32 pre-rope K

__device__ __half g_qh[NH  * S_LEN * HD];
__device__ __half g_ql[NH  * S_LEN * HD];
__device__ __half g_kh[NKV * S_LEN * HD];
__device__ __half g_kl[NKV * S_LEN * HD];
__device__ __half g_v16[NKV * S_LEN * HD];
__device__ __half g_aoh[S_LEN * NH * HD];
__device__ __half g_aol[S_LEN * NH * HD];

__device__ __half g_hs_hi[S_LEN * HIDDEN];
__device__ __half g_hs_lo[S_LEN * HIDDEN];
__device__ __half g_wq_hi[NH * HD * HIDDEN];
__device__ __half g_wq_lo[NH * HD * HIDDEN];
__device__ __half g_wk_hi[NKV * HD * HIDDEN];
__device__ __half g_wk_lo[NKV * HD * HIDDEN];
__device__ __half g_wv_hi[NKV * HD * HIDDEN];
__device__ __half g_wv_lo[NKV * HD * HIDDEN];
__device__ __half g_wo_hi[HIDDEN * NH * HD];
__device__ __half g_wo_lo[HIDDEN * NH * HD];   // written but unused (2-pass O proj)

// ---------------- PTX helpers ----------------
__device__ __forceinline__ uint32_t smem_u32(const void* p) {
    uint32_t a;
    asm("{ .reg .u64 t; cvta.to.shared.u64 t, %1; cvt.u32.u64 %0, t; }" : "=r"(a) : "l"(p));
    return a;
}
__device__ __forceinline__ void mma16816(float* c, const uint32_t* a, const uint32_t* b) {
    asm volatile("mma.sync.aligned.m16n8k16.row.col.f32.f16.f16.f32 "
        "{%0,%1,%2,%3}, {%4,%5,%6,%7}, {%8,%9}, {%0,%1,%2,%3};"
        : "+f"(c[0]), "+f"(c[1]), "+f"(c[2]), "+f"(c[3])
        : "r"(a[0]), "r"(a[1]), "r"(a[2]), "r"(a[3]), "r"(b[0]), "r"(b[1]));
}
__device__ __forceinline__ void ldsm4(uint32_t* r, uint32_t addr) {
    asm volatile("ldmatrix.sync.aligned.m8n8.x4.shared.b16 {%0,%1,%2,%3}, [%4];"
        : "=r"(r[0]), "=r"(r[1]), "=r"(r[2]), "=r"(r[3]) : "r"(addr));
}
__device__ __forceinline__ void ldsm4t(uint32_t* r, uint32_t addr) {
    asm volatile("ldmatrix.sync.aligned.m8n8.x4.trans.shared.b16 {%0,%1,%2,%3}, [%4];"
        : "=r"(r[0]), "=r"(r[1]), "=r"(r[2]), "=r"(r[3]) : "r"(addr));
}
__device__ __forceinline__ uint32_t packh2(__half a, __half b) {
    __half2 t = __halves2half2(a, b);
    return *(uint32_t*)&t;
}

#define GEMM_SMEM (64 * 1024)

// ---------------- GEMM: C = A[M,K] * W[N,K]^T (+bias), fp16 split, fp32 accum ----------------
// passes: Blo != nullptr -> 3 (AhiBhi, AloBhi, AhiBlo); Blo == nullptr -> 2 (AhiBhi, AloBhi)
// out_mode 0: fp32 head-major Cf[(n/128)][m][n%128]
// out_mode 1: fp32 row-major  Cf[m][n]
// out_mode 2: fp16 head-major Ch[(n/128)][m][n%128]
__global__ void __launch_bounds__(256, 1)
gemm_tc(const __half* __restrict__ Ahi, const __half* __restrict__ Alo,
        const __half* __restrict__ Bhi, const __half* __restrict__ Blo,
        const float* __restrict__ bias, float* __restrict__ Cf, __half* __restrict__ Ch,
        int M, int N, int K, int out_mode)
{
    extern __shared__ __align__(1024) char smc[];
    const int tid = threadIdx.x, wid = tid >> 5, lane = tid & 31;
    const int bm = blockIdx.y << 7, bn = blockIdx.x << 7;
    const uint32_t sbase = smem_u32(smc);
    const int NC = K >> 6;
    const int total = NC * (Blo ? 3 : 2);

    int rowj[4], c8j[4];
    uint32_t soffj[4];
#pragma unroll
    for (int j = 0; j < 4; j++) {
        int idx = tid + j * 256;
        rowj[j] = idx >> 3;
        c8j[j]  = idx & 7;
        uint32_t so = (uint32_t)(rowj[j] * 128 + c8j[j] * 16);
        soffj[j] = so ^ ((so >> 3) & 0x70);
    }

    const int wm = wid & 3;
    const int wn = wid >> 2;

    uint32_t a_base[2], aswz[2], b_base[4], bswz[4];
    const uint32_t acol = (uint32_t)((lane >> 4) << 4);
    const uint32_t bcol = (uint32_t)(((lane >> 3) & 1) << 4);
#pragma unroll
    for (int mi = 0; mi < 2; mi++) {
        int r = wm * 32 + mi * 16 + (lane & 15);
        a_base[mi] = sbase + r * 128;
        aswz[mi]   = (uint32_t)((r & 7) << 4);
    }
#pragma unroll
    for (int p = 0; p < 4; p++) {
        int r = wn * 64 + p * 16 + ((lane >> 4) & 1) * 8 + (lane & 7);
        b_base[p] = sbase + 16384 + r * 128;
        bswz[p]   = (uint32_t)((r & 7) << 4);
    }

    float acc[2][8][4];
#pragma unroll
    for (int mi = 0; mi < 2; mi++)
#pragma unroll
        for (int ni = 0; ni < 8; ni++)
#pragma unroll
            for (int q = 0; q < 4; q++) acc[mi][ni][q] = 0.f;

    // prologue: chunk 0 -> buf0 (pass 0)
#pragma unroll
    for (int j = 0; j < 4; j++) {
        uint4 ra = *(const uint4*)(Ahi + (size_t)(bm + rowj[j]) * K + c8j[j] * 8);
        uint4 rb = *(const uint4*)(Bhi + (size_t)(bn + rowj[j]) * K + c8j[j] * 8);
        *(uint4*)(smc + soffj[j])         = ra;
        *(uint4*)(smc + 16384 + soffj[j]) = rb;
    }
    uint4 pra[4], prb[4];
    if (total > 1) {
        int cn = 1, p = cn / NC, kc = cn - p * NC;
        const __half* pa = (p == 1) ? Alo : Ahi;
        const __half* pb = (p == 2) ? Blo : Bhi;
#pragma unroll
        for (int j = 0; j < 4; j++) {
            pra[j] = *(const uint4*)(pa + (size_t)(bm + rowj[j]) * K + kc * 64 + c8j[j] * 8);
            prb[j] = *(const uint4*)(pb + (size_t)(bn + rowj[j]) * K + kc * 64 + c8j[j] * 8);
        }
    }
    __syncthreads();

    for (int c = 0; c < total; c++) {
        const int buf = c & 1;
        if (c + 1 < total) {
            const uint32_t nboff = (uint32_t)((buf ^ 1) * 32768);
#pragma unroll
            for (int j = 0; j < 4; j++) {
                *(uint4*)(smc + nboff + soffj[j])         = pra[j];
                *(uint4*)(smc + nboff + 16384 + soffj[j]) = prb[j];
            }
        }
        if (c + 2 < total) {
            int cn = c + 2, p = cn / NC, kc = cn - p * NC;
            const __half* pa = (p == 1) ? Alo : Ahi;
            const __half* pb = (p == 2) ? Blo : Bhi;
#pragma unroll
            for (int j = 0; j < 4; j++) {
                pra[j] = *(const uint4*)(pa + (size_t)(bm + rowj[j]) * K + kc * 64 + c8j[j] * 8);
                prb[j] = *(const uint4*)(pb + (size_t)(bn + rowj[j]) * K + kc * 64 + c8j[j] * 8);
            }
        }
        const uint32_t bufoff = (uint32_t)(buf * 32768);
#pragma unroll
        for (int s = 0; s < 4; s++) {
            uint32_t af[2][4], bfr[4][4];
#pragma unroll
            for (int mi = 0; mi < 2; mi++)
                ldsm4(af[mi], a_base[mi] + bufoff + (uint32_t)(((uint32_t)(s * 32) + acol) ^ aswz[mi]));
#pragma unroll
            for (int p = 0; p < 4; p++)
                ldsm4(bfr[p], b_base[p] + bufoff + (uint32_t)(((uint32_t)(s * 32) + bcol) ^ bswz[p]));
#pragma unroll
            for (int mi = 0; mi < 2; mi++)
#pragma unroll
                for (int ni = 0; ni < 8; ni++)
                    mma16816(acc[mi][ni], af[mi], &bfr[ni >> 1][(ni & 1) * 2]);
        }
        __syncthreads();
    }

    // epilogue
#pragma unroll
    for (int mi = 0; mi < 2; mi++) {
        int r0 = wm * 32 + mi * 16 + (lane >> 2);
#pragma unroll
        for (int ni = 0; ni < 8; ni++) {
            int ncol = wn * 64 + ni * 8 + (lane & 3) * 2;
            float b0 = bias ? bias[bn + ncol]     : 0.f;
            float b1 = bias ? bias[bn + ncol + 1] : 0.f;
            float v00 = acc[mi][ni][0] + b0, v01 = acc[mi][ni][1] + b1;
            float v10 = acc[mi][ni][2] + b0, v11 = acc[mi][ni][3] + b1;
            if (out_mode == 0) {
                float* base = Cf + (size_t)(bn >> 7) * M * HD;
                *(float2*)(base + (size_t)(bm + r0) * HD + ncol)     = make_float2(v00, v01);
                *(float2*)(base + (size_t)(bm + r0 + 8) * HD + ncol) = make_float2(v10, v11);
            } else if (out_mode == 1) {
                *(float2*)(Cf + (size_t)(bm + r0) * N + bn + ncol)     = make_float2(v00, v01);
                *(float2*)(Cf + (size_t)(bm + r0 + 8) * N + bn + ncol) = make_float2(v10, v11);
            } else {
                __half* base = Ch + (size_t)(bn >> 7) * M * HD;
                *(__half2*)(base + (size_t)(bm + r0) * HD + ncol) =
                    __halves2half2(__float2half_rn(v00), __float2half_rn(v01));
                *(__half2*)(base + (size_t)(bm + r0 + 8) * HD + ncol) =
                    __halves2half2(__float2half_rn(v10), __float2half_rn(v11));
            }
        }
    }
}

// ---------------- fp32 -> fp16 hi/lo split ----------------
__global__ void split_kernel(const float* __restrict__ x,
                             __half* __restrict__ hi,
                             __half* __restrict__ lo, int n4)
{
    int i = blockIdx.x * blockDim.x + threadIdx.x;
    if (i >= n4) return;
    float4 v = ((const float4*)x)[i];
    __half h0 = __float2half_rn(v.x), h1 = __float2half_rn(v.y);
    __half h2 = __float2half_rn(v.z), h3 = __float2half_rn(v.w);
    __half l0 = __float2half_rn(v.x - __half2float(h0));
    __half l1 = __float2half_rn(v.y - __half2float(h1));
    __half l2 = __float2half_rn(v.z - __half2float(h2));
    __half l3 = __float2half_rn(v.w - __half2float(h3));
    __half2* hp = (__half2*)hi;
    __half2* lp = (__half2*)lo;
    hp[i*2]   = __halves2half2(h0, h1);
    hp[i*2+1] = __halves2half2(h2, h3);
    lp[i*2]   = __halves2half2(l0, l1);
    lp[i*2+1] = __halves2half2(l2, l3);
}

// ---------------- RoPE + split: fp32 [h][s][128] -> fp16 hi/lo ----------------
__global__ void rope_split(const float* __restrict__ buf,
                           const float* __restrict__ cosb,
                           const float* __restrict__ sinb,
                           __half* __restrict__ hi, __half* __restrict__ lo,
                           int nheads)
{
    int i = blockIdx.x * blockDim.x + threadIdx.x;
    int total = nheads * S_LEN * 64;
    if (i >= total) return;
    int d = i & 63;
    int s = (i >> 6) & (S_LEN - 1);
    int h = i >> 17;
    const float* row = buf + ((size_t)h * S_LEN + s) * HD;
    float c1 = cosb[s * HD + d];
    float c2 = cosb[s * HD + d + 64];
    float s1 = sinb[s * HD + d];
    float s2 = sinb[s * HD + d + 64];
    float x1 = row[d];
    float x2 = row[d + 64];
    float y1 = x1 * c1 - x2 * s1;
    float y2 = x2 * c2 + x1 * s2;
    size_t o = ((size_t)h * S_LEN + s) * HD;
    __half a1 = __float2half_rn(y1);
    __half a2 = __float2half_rn(y2);
    hi[o + d]      = a1;
    hi[o + d + 64] = a2;
    lo[o + d]      = __float2half_rn(y1 - __half2float(a1));
    lo[o + d + 64] = __float2half_rn(y2 - __half2float(a2));
}

// ---------------- HMMA flash attention (causal, GQA) ----------------
// 128 threads = 4 warps; warp w owns q rows [w*16, w*16+16). BM=BN=64, D=128.
// QK^T: 3-pass fp16 split. PV: 2-pass (P split, V single fp16).
#define ATT_STRIDE  136                       // halves per smem row (272 B, conflict-free)
#define ATT_ROWB    (ATT_STRIDE * 2)          // bytes per row
#define ATT_BUF     (64 * ATT_STRIDE)         // halves per buffer
#define ATT_SMEM    (3 * ATT_BUF * 2)         // bytes

__global__ void __launch_bounds__(128, 1)
attn_hmma(const __half* __restrict__ Qh, const __half* __restrict__ Ql,
          const __half* __restrict__ Kh, const __half* __restrict__ Kl,
          const __half* __restrict__ V,
          __half* __restrict__ AOh, __half* __restrict__ AOl)
{
    extern __shared__ __align__(1024) __half sa[];
    __half* sKh = sa;
    __half* sKl = sa + ATT_BUF;
    __half* sV  = sa + 2 * ATT_BUF;

    const int qb  = (int)gridDim.x - 1 - (int)blockIdx.x;   // longest first
    const int h   = blockIdx.y;
    const int kvh = h / GROUPS;
    const int tid = threadIdx.x, wid = tid >> 5, lane = tid & 31;

    const uint32_t skh = smem_u32(sKh);
    const uint32_t skl = smem_u32(sKl);
    const uint32_t sv  = smem_u32(sV);

    // ---- stage Q (hi then lo) through sKh, extract A-fragments ----
    uint32_t qhf[8][4], qlf[8][4];
    const uint32_t a_addr = skh + (uint32_t)((wid * 16 + (lane & 15)) * ATT_ROWB + ((lane >> 4) * 8) * 2);
    {
        const __half* Qg = Qh + ((size_t)h * S_LEN + qb * 64) * HD;
#pragma unroll
        for (int j = 0; j < 8; j++) {
            int v = tid + j * 128;
            int row = v >> 4, c16 = v & 15;
            *(uint4*)((char*)sKh + row * ATT_ROWB + c16 * 16) = *(const uint4*)(Qg + (size_t)row * HD + c16 * 8);
        }
        __syncthreads();
#pragma unroll
        for (int k = 0; k < 8; k++) ldsm4(qhf[k], a_addr + k * 32);
        __syncthreads();
        const __half* Qg2 = Ql + ((size_t)h * S_LEN + qb * 64) * HD;
#pragma unroll
        for (int j = 0; j < 8; j++) {
            int v = tid + j * 128;
            int row = v >> 4, c16 = v & 15;
            *(uint4*)((char*)sKh + row * ATT_ROWB + c16 * 16) = *(const uint4*)(Qg2 + (size_t)row * HD + c16 * 8);
        }
        __syncthreads();
#pragma unroll
        for (int k = 0; k < 8; k++) ldsm4(qlf[k], a_addr + k * 32);
    }

    // B-fragment lane addressing for K (non-trans) and V (trans)
    const uint32_t kb_off = (uint32_t)((((lane >> 4) & 1) * 8 + (lane & 7)) * ATT_ROWB
                                       + ((lane >> 3) & 1) * 16);
    const uint32_t vb_off = (uint32_t)(((((lane >> 3) & 1) * 8) + (lane & 7)) * ATT_ROWB
                                       + (lane >> 4) * 16);

    float o[16][4];
#pragma unroll
    for (int dg = 0; dg < 16; dg++)
#pragma unroll
        for (int q = 0; q < 4; q++) o[dg][q] = 0.f;
    float m0 = -1e30f, m1 = -1e30f, l0 = 0.f, l1 = 0.f;

    for (int kt = 0; kt <= qb; kt++) {
        __syncthreads();
        // cooperative load K hi/lo + V (64 x 128 halves each)
        {
            const __half* Kgh = Kh + ((size_t)kvh * S_LEN + kt * 64) * HD;
            const __half* Kgl = Kl + ((size_t)kvh * S_LEN + kt * 64) * HD;
            const __half* Vg  = V  + ((size_t)kvh * S_LEN + kt * 64) * HD;
#pragma unroll
            for (int j = 0; j < 8; j++) {
                int v = tid + j * 128;
                int row = v >> 4, c16 = v & 15;
                int doff = row * ATT_ROWB + c16 * 16;
                size_t goff = (size_t)row * HD + c16 * 8;
                *(uint4*)((char*)sKh + doff) = *(const uint4*)(Kgh + goff);
                *(uint4*)((char*)sKl + doff) = *(const uint4*)(Kgl + goff);
                *(uint4*)((char*)sV  + doff) = *(const uint4*)(Vg  + goff);
            }
        }
        __syncthreads();

        // ---- S = Q K^T (3-pass) ----
        float sreg[8][4];
#pragma unroll
        for (int nt = 0; nt < 8; nt++)
#pragma unroll
            for (int q = 0; q < 4; q++) sreg[nt][q] = 0.f;

#pragma unroll
        for (int k = 0; k < 8; k++) {
            uint32_t kfh[4][4], kfl[4][4];
#pragma unroll
            for (int g = 0; g < 4; g++) {
                ldsm4(kfh[g], skh + kb_off + (uint32_t)(g * 16 * ATT_ROWB) + (uint32_t)(k * 32));
                ldsm4(kfl[g], skl + kb_off + (uint32_t)(g * 16 * ATT_ROWB) + (uint32_t)(k * 32));
            }
#pragma unroll
            for (int nt = 0; nt < 8; nt++) {
                const uint32_t* bh = &kfh[nt >> 1][(nt & 1) * 2];
                const uint32_t* bl = &kfl[nt >> 1][(nt & 1) * 2];
                mma16816(sreg[nt], qhf[k], bh);
                mma16816(sreg[nt], qlf[k], bh);
                mma16816(sreg[nt], qhf[k], bl);
            }
        }

        // scale + causal mask
#pragma unroll
        for (int nt = 0; nt < 8; nt++)
#pragma unroll
            for (int q = 0; q < 4; q++) sreg[nt][q] *= SCALING;
        if (kt == qb) {
            int r0 = wid * 16 + (lane >> 2);
            int r1 = r0 + 8;
#pragma unroll
            for (int nt = 0; nt < 8; nt++) {
                int cb = nt * 8 + (lane & 3) * 2;
                if (cb     > r0) sreg[nt][0] = -1e30f;
                if (cb + 1 > r0) sreg[nt][1] = -1e30f;
                if (cb     > r1) sreg[nt][2] = -1e30f;
                if (cb + 1 > r1) sreg[nt][3] = -1e30f;
            }
        }

        // ---- online softmax (rows r0, r0+8 per thread, quad-reduced) ----
        float rmax0 = -1e30f, rmax1 = -1e30f;
#pragma unroll
        for (int nt = 0; nt < 8; nt++) {
            rmax0 = fmaxf(rmax0, fmaxf(sreg[nt][0], sreg[nt][1]));
            rmax1 = fmaxf(rmax1, fmaxf(sreg[nt][2], sreg[nt][3]));
        }
        rmax0 = fmaxf(rmax0, __shfl_xor_sync(0xffffffffu, rmax0, 1));
        rmax0 = fmaxf(rmax0, __shfl_xor_sync(0xffffffffu, rmax0, 2));
        rmax1 = fmaxf(rmax1, __shfl_xor_sync(0xffffffffu, rmax1, 1));
        rmax1 = fmaxf(rmax1, __shfl_xor_sync(0xffffffffu, rmax1, 2));
        float mn0 = fmaxf(m0, rmax0), mn1 = fmaxf(m1, rmax1);
        float corr0 = __expf(m0 - mn0), corr1 = __expf(m1 - mn1);
        m0 = mn0; m1 = mn1;

        float rs0 = 0.f, rs1 = 0.f;
        uint32_t pah[4][4], pal[4][4];
#pragma unroll
        for (int nt = 0; nt < 8; nt++) {
            float p0 = __expf(sreg[nt][0] - m0);
            float p1 = __expf(sreg[nt][1] - m0);
            float p2 = __expf(sreg[nt][2] - m1);
            float p3 = __expf(sreg[nt][3] - m1);
            rs0 += p0 + p1; rs1 += p2 + p3;
            __half h0 = __float2half_rn(p0), h1 = __float2half_rn(p1);
            __half h2 = __float2half_rn(p2), h3 = __float2half_rn(p3);
            __half e0 = __float2half_rn(p0 - __half2float(h0));
            __half e1 = __float2half_rn(p1 - __half2float(h1));
            __half e2 = __float2half_rn(p2 - __half2float(h2));
            __half e3 = __float2half_rn(p3 - __half2float(h3));
            int t = nt >> 1, pc = (nt & 1) * 2;
            pah[t][pc + 0] = packh2(h0, h1);
            pah[t][pc + 1] = packh2(h2, h3);
            pal[t][pc + 0] = packh2(e0, e1);
            pal[t][pc + 1] = packh2(e2, e3);
        }
        rs0 += __shfl_xor_sync(0xffffffffu, rs0, 1);
        rs0 += __shfl_xor_sync(0xffffffffu, rs0, 2);
        rs1 += __shfl_xor_sync(0xffffffffu, rs1, 1);
        rs1 += __shfl_xor_sync(0xffffffffu, rs1, 2);
        l0 = l0 * corr0 + rs0;
        l1 = l1 * corr1 + rs1;

#pragma unroll
        for (int dg = 0; dg < 16; dg++) {
            o[dg][0] *= corr0; o[dg][1] *= corr0;
            o[dg][2] *= corr1; o[dg][3] *= corr1;
        }

        // ---- O += P V (2-pass: Phi*V + Plo*V) ----
#pragma unroll
        for (int t = 0; t < 4; t++) {
#pragma unroll
            for (int pp = 0; pp < 8; pp++) {
                uint32_t vf[4];
                ldsm4t(vf, sv + vb_off + (uint32_t)(t * 16 * ATT_ROWB) + (uint32_t)(pp * 32));
                mma16816(o[2 * pp],     pah[t], &vf[0]);
                mma16816(o[2 * pp],     pal[t], &vf[0]);
                mma16816(o[2 * pp + 1], pah[t], &vf[2]);
                mma16816(o[2 * pp + 1], pal[t], &vf[2]);
            }
        }
    }

    // ---- write AO (fp16 hi/lo), layout [s][h*128+d] ----
    float inv0 = 1.f / l0, inv1 = 1.f / l1;
    int r0g = qb * 64 + wid * 16 + (lane >> 2);
    size_t base0 = (size_t)r0g * (NH * HD) + (size_t)h * HD;
    size_t base1 = base0 + (size_t)8 * (NH * HD);
    int coff = (lane & 3) * 2;
#pragma unroll
    for (int dg = 0; dg < 16; dg++) {
        float x0 = o[dg][0] * inv0, x1 = o[dg][1] * inv0;
        float x2 = o[dg][2] * inv1, x3 = o[dg][3] * inv1;
        __half h0 = __float2half_rn(x0), h1 = __float2half_rn(x1);
        __half h2 = __float2half_rn(x2), h3 = __float2half_rn(x3);
        __half e0 = __float2half_rn(x0 - __half2float(h0));
        __half e1 = __float2half_rn(x1 - __half2float(h1));
        __half e2 = __float2half_rn(x2 - __half2float(h2));
        __half e3 = __float2half_rn(x3 - __half2float(h3));
        *(__half2*)(AOh + base0 + dg * 8 + coff) = __halves2half2(h0, h1);
        *(__half2*)(AOl + base0 + dg * 8 + coff) = __halves2half2(e0, e1);
        *(__half2*)(AOh + base1 + dg * 8 + coff) = __halves2half2(h2, h3);
        *(__half2*)(AOl + base1 + dg * 8 + coff) = __halves2half2(e2, e3);
    }
}

// ---------------- launch ----------------
extern "C" void kernel_launch(void* const* d_in, const int* in_sizes, int n_in,
                              void* d_out, int out_size)
{
    const float* hs   = (const float*)d_in[0];
    const float* cosb = (const float*)d_in[1];
    const float* sinb = (const float*)d_in[2];
    const float* Wq   = (const float*)d_in[3];
    const float* bq   = (const float*)d_in[4];
    const float* Wk   = (const float*)d_in[5];
    const float* bk   = (const float*)d_in[6];
    const float* Wv   = (const float*)d_in[7];
    const float* bv   = (const float*)d_in[8];
    const float* Wo   = (const float*)d_in[9];
    float* out = (float*)d_out;

    float *pq, *pk;
    cudaGetSymbolAddress((void**)&pq, g_q);
    cudaGetSymbolAddress((void**)&pk, g_k);

    __half *qh, *ql, *kh, *kl, *v16, *aoh, *aol;
    cudaGetSymbolAddress((void**)&qh,  g_qh);
    cudaGetSymbolAddress((void**)&ql,  g_ql);
    cudaGetSymbolAddress((void**)&kh,  g_kh);
    cudaGetSymbolAddress((void**)&kl,  g_kl);
    cudaGetSymbolAddress((void**)&v16, g_v16);
    cudaGetSymbolAddress((void**)&aoh, g_aoh);
    cudaGetSymbolAddress((void**)&aol, g_aol);

    __half *hs_hi, *hs_lo, *wq_hi, *wq_lo, *wk_hi, *wk_lo, *wv_hi, *wv_lo, *wo_hi, *wo_lo;
    cudaGetSymbolAddress((void**)&hs_hi, g_hs_hi);
    cudaGetSymbolAddress((void**)&hs_lo, g_hs_lo);
    cudaGetSymbolAddress((void**)&wq_hi, g_wq_hi);
    cudaGetSymbolAddress((void**)&wq_lo, g_wq_lo);
    cudaGetSymbolAddress((void**)&wk_hi, g_wk_hi);
    cudaGetSymbolAddress((void**)&wk_lo, g_wk_lo);
    cudaGetSymbolAddress((void**)&wv_hi, g_wv_hi);
    cudaGetSymbolAddress((void**)&wv_lo, g_wv_lo);
    cudaGetSymbolAddress((void**)&wo_hi, g_wo_hi);
    cudaGetSymbolAddress((void**)&wo_lo, g_wo_lo);

    auto split = [&](const float* x, __half* h, __half* l, int n) {
        int n4 = n / 4;
        split_kernel<<<(n4 + 255) / 256, 256>>>(x, h, l, n4);
    };

    split(hs, hs_hi, hs_lo, S_LEN * HIDDEN);
    split(Wq, wq_hi, wq_lo, NH  * HD * HIDDEN);
    split(Wk, wk_hi, wk_lo, NKV * HD * HIDDEN);
    split(Wv, wv_hi, wv_lo, NKV * HD * HIDDEN);
    split(Wo, wo_hi, wo_lo, HIDDEN * NH * HD);

    cudaFuncSetAttribute(gemm_tc, cudaFuncAttributeMaxDynamicSharedMemorySize, GEMM_SMEM);

    // QKV projections (3-pass). Q,K -> fp32 head-major; V -> fp16 head-major.
    gemm_tc<<<dim3(NH,  16), 256, GEMM_SMEM>>>(hs_hi, hs_lo, wq_hi, wq_lo, bq, pq, nullptr,
                                               S_LEN, NH  * HD, HIDDEN, 0);
    gemm_tc<<<dim3(NKV, 16), 256, GEMM_SMEM>>>(hs_hi, hs_lo, wk_hi, wk_lo, bk, pk, nullptr,
                                               S_LEN, NKV * HD, HIDDEN, 0);
    gemm_tc<<<dim3(NKV, 16), 256, GEMM_SMEM>>>(hs_hi, hs_lo, wv_hi, wv_lo, bv, nullptr, v16,
                                               S_LEN, NKV * HD, HIDDEN, 2);

    // RoPE + fp16 split for Q, K
    rope_split<<<(NH  * S_LEN * 64 + 255) / 256, 256>>>(pq, cosb, sinb, qh, ql, NH);
    rope_split<<<(NKV * S_LEN * 64 + 255) / 256, 256>>>(pk, cosb, sinb, kh, kl, NKV);

    // HMMA flash attention
    cudaFuncSetAttribute(attn_hmma, cudaFuncAttributeMaxDynamicSharedMemorySize, ATT_SMEM);
    attn_hmma<<<dim3(S_LEN / 64, NH), 128, ATT_SMEM>>>(qh, ql, kh, kl, v16, aoh, aol);

    // O projection (2-pass: AOhi*Wo + AOlo*Wo), fp32 row-major out
    gemm_tc<<<dim3(NH, 16), 256, GEMM_SMEM>>>(aoh, aol, wo_hi, nullptr, nullptr, out, nullptr,
                                              S_LEN, HIDDEN, NH * HD, 1);
}

// round 9
// speedup vs baseline: 7.5139x; 1.4069x over previous
#include <cuda_runtime.h>
#include <cuda_fp16.h>
#include <math.h>
#include <stdint.h>

#define S_LEN   2048
#define HIDDEN  3584
#define NH      28
#define NKV     4
#define HD      128
#define GROUPS  7
#define SCALING 0.08838834764831845f

// ---------------- scratch (device globals, no allocation) ----------------
__device__ float g_q [NH  * S_LEN * HD];   // fp32 pre-rope Q
__device__ float g_k [NKV * S_LEN * HD];   // fp32 pre-rope K

__device__ __half g_qh[NH  * S_LEN * HD];
__device__ __half g_ql[NH  * S_LEN * HD];
__device__ __half g_kh[NKV * S_LEN * HD];
__device__ __half g_kl[NKV * S_LEN * HD];
__device__ __half g_v16[NKV * S_LEN * HD];
__device__ __half g_aoh[S_LEN * NH * HD];

__device__ __half g_hs_hi[S_LEN * HIDDEN];
__device__ __half g_hs_lo[S_LEN * HIDDEN];
__device__ __half g_wq_hi[NH * HD * HIDDEN];
__device__ __half g_wq_lo[NH * HD * HIDDEN];
__device__ __half g_wk_hi[NKV * HD * HIDDEN];
__device__ __half g_wk_lo[NKV * HD * HIDDEN];
__device__ __half g_wv_hi[NKV * HD * HIDDEN];
__device__ __half g_wo_hi[HIDDEN * NH * HD];

// ---------------- PTX helpers ----------------
__device__ __forceinline__ uint32_t smem_u32(const void* p) {
    uint32_t a;
    asm("{ .reg .u64 t; cvta.to.shared.u64 t, %1; cvt.u32.u64 %0, t; }" : "=r"(a) : "l"(p));
    return a;
}
__device__ __forceinline__ void mma16816(float* c, const uint32_t* a, const uint32_t* b) {
    asm volatile("mma.sync.aligned.m16n8k16.row.col.f32.f16.f16.f32 "
        "{%0,%1,%2,%3}, {%4,%5,%6,%7}, {%8,%9}, {%0,%1,%2,%3};"
        : "+f"(c[0]), "+f"(c[1]), "+f"(c[2]), "+f"(c[3])
        : "r"(a[0]), "r"(a[1]), "r"(a[2]), "r"(a[3]), "r"(b[0]), "r"(b[1]));
}
__device__ __forceinline__ void ldsm4(uint32_t* r, uint32_t addr) {
    asm volatile("ldmatrix.sync.aligned.m8n8.x4.shared.b16 {%0,%1,%2,%3}, [%4];"
        : "=r"(r[0]), "=r"(r[1]), "=r"(r[2]), "=r"(r[3]) : "r"(addr));
}
__device__ __forceinline__ void ldsm4t(uint32_t* r, uint32_t addr) {
    asm volatile("ldmatrix.sync.aligned.m8n8.x4.trans.shared.b16 {%0,%1,%2,%3}, [%4];"
        : "=r"(r[0]), "=r"(r[1]), "=r"(r[2]), "=r"(r[3]) : "r"(addr));
}
__device__ __forceinline__ uint32_t packh2(__half a, __half b) {
    __half2 t = __halves2half2(a, b);
    return *(uint32_t*)&t;
}

#define GEMM_SMEM (64 * 1024)

// ---------------- GEMM body: C = A[M,K] * W[N,K]^T (+bias), fp16 split, fp32 accum ----------------
// pass count = 1 + (Alo?1) + (Blo?1):  AhiBhi [, AloBhi] [, AhiBlo]
// out_mode 0: fp32 head-major Cf[(n/128)][m][n%128]
// out_mode 1: fp32 row-major  Cf[m][n]
// out_mode 2: fp16 head-major Ch[(n/128)][m][n%128]
__device__ __forceinline__ void gemm_body(
    char* smc,
    const __half* __restrict__ Ahi, const __half* __restrict__ Alo,
    const __half* __restrict__ Bhi, const __half* __restrict__ Blo,
    const float* __restrict__ bias, float* __restrict__ Cf, __half* __restrict__ Ch,
    int M, int N, int K, int out_mode, int bm, int bn)
{
    const int tid = threadIdx.x, wid = tid >> 5, lane = tid & 31;
    const uint32_t sbase = smem_u32(smc);
    const int NC = K >> 6;
    const int total = NC * (1 + (Alo ? 1 : 0) + (Blo ? 1 : 0));

    int rowj[4], c8j[4];
    uint32_t soffj[4];
#pragma unroll
    for (int j = 0; j < 4; j++) {
        int idx = tid + j * 256;
        rowj[j] = idx >> 3;
        c8j[j]  = idx & 7;
        uint32_t so = (uint32_t)(rowj[j] * 128 + c8j[j] * 16);
        soffj[j] = so ^ ((so >> 3) & 0x70);
    }

    const int wm = wid & 3;
    const int wn = wid >> 2;

    uint32_t a_base[2], aswz[2], b_base[4], bswz[4];
    const uint32_t acol = (uint32_t)((lane >> 4) << 4);
    const uint32_t bcol = (uint32_t)(((lane >> 3) & 1) << 4);
#pragma unroll
    for (int mi = 0; mi < 2; mi++) {
        int r = wm * 32 + mi * 16 + (lane & 15);
        a_base[mi] = sbase + r * 128;
        aswz[mi]   = (uint32_t)((r & 7) << 4);
    }
#pragma unroll
    for (int p = 0; p < 4; p++) {
        int r = wn * 64 + p * 16 + ((lane >> 4) & 1) * 8 + (lane & 7);
        b_base[p] = sbase + 16384 + r * 128;
        bswz[p]   = (uint32_t)((r & 7) << 4);
    }

    float acc[2][8][4];
#pragma unroll
    for (int mi = 0; mi < 2; mi++)
#pragma unroll
        for (int ni = 0; ni < 8; ni++)
#pragma unroll
            for (int q = 0; q < 4; q++) acc[mi][ni][q] = 0.f;

    // prologue: chunk 0 -> buf0 (pass 0)
#pragma unroll
    for (int j = 0; j < 4; j++) {
        uint4 ra = *(const uint4*)(Ahi + (size_t)(bm + rowj[j]) * K + c8j[j] * 8);
        uint4 rb = *(const uint4*)(Bhi + (size_t)(bn + rowj[j]) * K + c8j[j] * 8);
        *(uint4*)(smc + soffj[j])         = ra;
        *(uint4*)(smc + 16384 + soffj[j]) = rb;
    }
    uint4 pra[4], prb[4];
    if (total > 1) {
        int cn = 1, p = cn / NC, kc = cn - p * NC;
        const __half* pa = (p == 1) ? Alo : Ahi;
        const __half* pb = (p == 2) ? Blo : Bhi;
#pragma unroll
        for (int j = 0; j < 4; j++) {
            pra[j] = *(const uint4*)(pa + (size_t)(bm + rowj[j]) * K + kc * 64 + c8j[j] * 8);
            prb[j] = *(const uint4*)(pb + (size_t)(bn + rowj[j]) * K + kc * 64 + c8j[j] * 8);
        }
    }
    __syncthreads();

    for (int c = 0; c < total; c++) {
        const int buf = c & 1;
        if (c + 1 < total) {
            const uint32_t nboff = (uint32_t)((buf ^ 1) * 32768);
#pragma unroll
            for (int j = 0; j < 4; j++) {
                *(uint4*)(smc + nboff + soffj[j])         = pra[j];
                *(uint4*)(smc + nboff + 16384 + soffj[j]) = prb[j];
            }
        }
        if (c + 2 < total) {
            int cn = c + 2, p = cn / NC, kc = cn - p * NC;
            const __half* pa = (p == 1) ? Alo : Ahi;
            const __half* pb = (p == 2) ? Blo : Bhi;
#pragma unroll
            for (int j = 0; j < 4; j++) {
                pra[j] = *(const uint4*)(pa + (size_t)(bm + rowj[j]) * K + kc * 64 + c8j[j] * 8);
                prb[j] = *(const uint4*)(pb + (size_t)(bn + rowj[j]) * K + kc * 64 + c8j[j] * 8);
            }
        }
        const uint32_t bufoff = (uint32_t)(buf * 32768);
#pragma unroll
        for (int s = 0; s < 4; s++) {
            uint32_t af[2][4], bfr[4][4];
#pragma unroll
            for (int mi = 0; mi < 2; mi++)
                ldsm4(af[mi], a_base[mi] + bufoff + (uint32_t)(((uint32_t)(s * 32) + acol) ^ aswz[mi]));
#pragma unroll
            for (int p = 0; p < 4; p++)
                ldsm4(bfr[p], b_base[p] + bufoff + (uint32_t)(((uint32_t)(s * 32) + bcol) ^ bswz[p]));
#pragma unroll
            for (int mi = 0; mi < 2; mi++)
#pragma unroll
                for (int ni = 0; ni < 8; ni++)
                    mma16816(acc[mi][ni], af[mi], &bfr[ni >> 1][(ni & 1) * 2]);
        }
        __syncthreads();
    }

    // epilogue
#pragma unroll
    for (int mi = 0; mi < 2; mi++) {
        int r0 = wm * 32 + mi * 16 + (lane >> 2);
#pragma unroll
        for (int ni = 0; ni < 8; ni++) {
            int ncol = wn * 64 + ni * 8 + (lane & 3) * 2;
            float b0 = bias ? bias[bn + ncol]     : 0.f;
            float b1 = bias ? bias[bn + ncol + 1] : 0.f;
            float v00 = acc[mi][ni][0] + b0, v01 = acc[mi][ni][1] + b1;
            float v10 = acc[mi][ni][2] + b0, v11 = acc[mi][ni][3] + b1;
            if (out_mode == 0) {
                float* base = Cf + (size_t)(bn >> 7) * M * HD;
                *(float2*)(base + (size_t)(bm + r0) * HD + (ncol & 127))     = make_float2(v00, v01);
                *(float2*)(base + (size_t)(bm + r0 + 8) * HD + (ncol & 127)) = make_float2(v10, v11);
            } else if (out_mode == 1) {
                *(float2*)(Cf + (size_t)(bm + r0) * N + bn + ncol)     = make_float2(v00, v01);
                *(float2*)(Cf + (size_t)(bm + r0 + 8) * N + bn + ncol) = make_float2(v10, v11);
            } else {
                __half* base = Ch + (size_t)(bn >> 7) * M * HD;
                *(__half2*)(base + (size_t)(bm + r0) * HD + (ncol & 127)) =
                    __halves2half2(__float2half_rn(v00), __float2half_rn(v01));
                *(__half2*)(base + (size_t)(bm + r0 + 8) * HD + (ncol & 127)) =
                    __halves2half2(__float2half_rn(v10), __float2half_rn(v11));
            }
        }
    }
}

// generic single-GEMM launcher (used for O projection)
__global__ void __launch_bounds__(256, 1)
gemm_tc(const __half* __restrict__ Ahi, const __half* __restrict__ Alo,
        const __half* __restrict__ Bhi, const __half* __restrict__ Blo,
        const float* __restrict__ bias, float* __restrict__ Cf, __half* __restrict__ Ch,
        int M, int N, int K, int out_mode)
{
    extern __shared__ __align__(1024) char smc[];
    gemm_body(smc, Ahi, Alo, Bhi, Blo, bias, Cf, Ch, M, N, K, out_mode,
              (int)(blockIdx.y << 7), (int)(blockIdx.x << 7));
}

// fused QKV: grid (36, 16). bx<28 -> Q (3-pass), 28..31 -> K (3-pass), 32..35 -> V (2-pass, fp16 out)
__global__ void __launch_bounds__(256, 1)
qkv_fused(const __half* __restrict__ hs_hi, const __half* __restrict__ hs_lo,
          const __half* __restrict__ wq_hi, const __half* __restrict__ wq_lo,
          const float* __restrict__ bq, float* __restrict__ pq,
          const __half* __restrict__ wk_hi, const __half* __restrict__ wk_lo,
          const float* __restrict__ bk, float* __restrict__ pk,
          const __half* __restrict__ wv_hi, const float* __restrict__ bv,
          __half* __restrict__ v16)
{
    extern __shared__ __align__(1024) char smc[];
    const int bx = blockIdx.x;
    const int bm = (int)(blockIdx.y << 7);
    if (bx < 28) {
        gemm_body(smc, hs_hi, hs_lo, wq_hi, wq_lo, bq, pq, nullptr,
                  S_LEN, NH * HD, HIDDEN, 0, bm, bx << 7);
    } else if (bx < 32) {
        gemm_body(smc, hs_hi, hs_lo, wk_hi, wk_lo, bk, pk, nullptr,
                  S_LEN, NKV * HD, HIDDEN, 0, bm, (bx - 28) << 7);
    } else {
        gemm_body(smc, hs_hi, hs_lo, wv_hi, nullptr, bv, nullptr, v16,
                  S_LEN, NKV * HD, HIDDEN, 2, bm, (bx - 32) << 7);
    }
}

// ---------------- fp32 -> fp16 hi/lo split ----------------
__global__ void split_kernel(const float* __restrict__ x,
                             __half* __restrict__ hi,
                             __half* __restrict__ lo, int n4)
{
    int i = blockIdx.x * blockDim.x + threadIdx.x;
    if (i >= n4) return;
    float4 v = ((const float4*)x)[i];
    __half h0 = __float2half_rn(v.x), h1 = __float2half_rn(v.y);
    __half h2 = __float2half_rn(v.z), h3 = __float2half_rn(v.w);
    __half l0 = __float2half_rn(v.x - __half2float(h0));
    __half l1 = __float2half_rn(v.y - __half2float(h1));
    __half l2 = __float2half_rn(v.z - __half2float(h2));
    __half l3 = __float2half_rn(v.w - __half2float(h3));
    __half2* hp = (__half2*)hi;
    __half2* lp = (__half2*)lo;
    hp[i*2]   = __halves2half2(h0, h1);
    hp[i*2+1] = __halves2half2(h2, h3);
    lp[i*2]   = __halves2half2(l0, l1);
    lp[i*2+1] = __halves2half2(l2, l3);
}

// hi-only variant (for weights whose lo pass is dropped)
__global__ void split_hi_kernel(const float* __restrict__ x,
                                __half* __restrict__ hi, int n4)
{
    int i = blockIdx.x * blockDim.x + threadIdx.x;
    if (i >= n4) return;
    float4 v = ((const float4*)x)[i];
    __half2* hp = (__half2*)hi;
    hp[i*2]   = __halves2half2(__float2half_rn(v.x), __float2half_rn(v.y));
    hp[i*2+1] = __halves2half2(__float2half_rn(v.z), __float2half_rn(v.w));
}

// ---------------- RoPE + split: fp32 [h][s][128] -> fp16 hi/lo ----------------
__global__ void rope_split(const float* __restrict__ buf,
                           const float* __restrict__ cosb,
                           const float* __restrict__ sinb,
                           __half* __restrict__ hi, __half* __restrict__ lo,
                           int nheads)
{
    int i = blockIdx.x * blockDim.x + threadIdx.x;
    int total = nheads * S_LEN * 64;
    if (i >= total) return;
    int d = i & 63;
    int s = (i >> 6) & (S_LEN - 1);
    int h = i >> 17;
    const float* row = buf + ((size_t)h * S_LEN + s) * HD;
    float c1 = cosb[s * HD + d];
    float c2 = cosb[s * HD + d + 64];
    float s1 = sinb[s * HD + d];
    float s2 = sinb[s * HD + d + 64];
    float x1 = row[d];
    float x2 = row[d + 64];
    float y1 = x1 * c1 - x2 * s1;
    float y2 = x2 * c2 + x1 * s2;
    size_t o = ((size_t)h * S_LEN + s) * HD;
    __half a1 = __float2half_rn(y1);
    __half a2 = __float2half_rn(y2);
    hi[o + d]      = a1;
    hi[o + d + 64] = a2;
    lo[o + d]      = __float2half_rn(y1 - __half2float(a1));
    lo[o + d + 64] = __float2half_rn(y2 - __half2float(a2));
}

// ---------------- HMMA flash attention (causal, GQA) ----------------
// 128 threads = 4 warps; warp w owns q rows [w*16, w*16+16). BM=BN=64, D=128.
// QK^T: 3-pass fp16 split. PV: 2-pass (P split, V single fp16). Output: fp16 hi only.
#define ATT_STRIDE  136
#define ATT_ROWB    (ATT_STRIDE * 2)
#define ATT_BUF     (64 * ATT_STRIDE)
#define ATT_SMEM    (3 * ATT_BUF * 2)

__global__ void __launch_bounds__(128, 1)
attn_hmma(const __half* __restrict__ Qh, const __half* __restrict__ Ql,
          const __half* __restrict__ Kh, const __half* __restrict__ Kl,
          const __half* __restrict__ V,
          __half* __restrict__ AOh)
{
    extern __shared__ __align__(1024) __half sa[];
    __half* sKh = sa;
    __half* sKl = sa + ATT_BUF;
    __half* sV  = sa + 2 * ATT_BUF;

    const int qb  = (int)gridDim.x - 1 - (int)blockIdx.x;
    const int h   = blockIdx.y;
    const int kvh = h / GROUPS;
    const int tid = threadIdx.x, wid = tid >> 5, lane = tid & 31;

    const uint32_t skh = smem_u32(sKh);
    const uint32_t skl = smem_u32(sKl);
    const uint32_t sv  = smem_u32(sV);

    // ---- stage Q (hi then lo) through sKh, extract A-fragments ----
    uint32_t qhf[8][4], qlf[8][4];
    const uint32_t a_addr = skh + (uint32_t)((wid * 16 + (lane & 15)) * ATT_ROWB + ((lane >> 4) * 8) * 2);
    {
        const __half* Qg = Qh + ((size_t)h * S_LEN + qb * 64) * HD;
#pragma unroll
        for (int j = 0; j < 8; j++) {
            int v = tid + j * 128;
            int row = v >> 4, c16 = v & 15;
            *(uint4*)((char*)sKh + row * ATT_ROWB + c16 * 16) = *(const uint4*)(Qg + (size_t)row * HD + c16 * 8);
        }
        __syncthreads();
#pragma unroll
        for (int k = 0; k < 8; k++) ldsm4(qhf[k], a_addr + k * 32);
        __syncthreads();
        const __half* Qg2 = Ql + ((size_t)h * S_LEN + qb * 64) * HD;
#pragma unroll
        for (int j = 0; j < 8; j++) {
            int v = tid + j * 128;
            int row = v >> 4, c16 = v & 15;
            *(uint4*)((char*)sKh + row * ATT_ROWB + c16 * 16) = *(const uint4*)(Qg2 + (size_t)row * HD + c16 * 8);
        }
        __syncthreads();
#pragma unroll
        for (int k = 0; k < 8; k++) ldsm4(qlf[k], a_addr + k * 32);
    }

    const uint32_t kb_off = (uint32_t)((((lane >> 4) & 1) * 8 + (lane & 7)) * ATT_ROWB
                                       + ((lane >> 3) & 1) * 16);
    const uint32_t vb_off = (uint32_t)(((((lane >> 3) & 1) * 8) + (lane & 7)) * ATT_ROWB
                                       + (lane >> 4) * 16);

    float o[16][4];
#pragma unroll
    for (int dg = 0; dg < 16; dg++)
#pragma unroll
        for (int q = 0; q < 4; q++) o[dg][q] = 0.f;
    float m0 = -1e30f, m1 = -1e30f, l0 = 0.f, l1 = 0.f;

    for (int kt = 0; kt <= qb; kt++) {
        __syncthreads();
        {
            const __half* Kgh = Kh + ((size_t)kvh * S_LEN + kt * 64) * HD;
            const __half* Kgl = Kl + ((size_t)kvh * S_LEN + kt * 64) * HD;
            const __half* Vg  = V  + ((size_t)kvh * S_LEN + kt * 64) * HD;
#pragma unroll
            for (int j = 0; j < 8; j++) {
                int v = tid + j * 128;
                int row = v >> 4, c16 = v & 15;
                int doff = row * ATT_ROWB + c16 * 16;
                size_t goff = (size_t)row * HD + c16 * 8;
                *(uint4*)((char*)sKh + doff) = *(const uint4*)(Kgh + goff);
                *(uint4*)((char*)sKl + doff) = *(const uint4*)(Kgl + goff);
                *(uint4*)((char*)sV  + doff) = *(const uint4*)(Vg  + goff);
            }
        }
        __syncthreads();

        float sreg[8][4];
#pragma unroll
        for (int nt = 0; nt < 8; nt++)
#pragma unroll
            for (int q = 0; q < 4; q++) sreg[nt][q] = 0.f;

#pragma unroll
        for (int k = 0; k < 8; k++) {
            uint32_t kfh[4][4], kfl[4][4];
#pragma unroll
            for (int g = 0; g < 4; g++) {
                ldsm4(kfh[g], skh + kb_off + (uint32_t)(g * 16 * ATT_ROWB) + (uint32_t)(k * 32));
                ldsm4(kfl[g], skl + kb_off + (uint32_t)(g * 16 * ATT_ROWB) + (uint32_t)(k * 32));
            }
#pragma unroll
            for (int nt = 0; nt < 8; nt++) {
                const uint32_t* bh = &kfh[nt >> 1][(nt & 1) * 2];
                const uint32_t* bl = &kfl[nt >> 1][(nt & 1) * 2];
                mma16816(sreg[nt], qhf[k], bh);
                mma16816(sreg[nt], qlf[k], bh);
                mma16816(sreg[nt], qhf[k], bl);
            }
        }

#pragma unroll
        for (int nt = 0; nt < 8; nt++)
#pragma unroll
            for (int q = 0; q < 4; q++) sreg[nt][q] *= SCALING;
        if (kt == qb) {
            int r0 = wid * 16 + (lane >> 2);
            int r1 = r0 + 8;
#pragma unroll
            for (int nt = 0; nt < 8; nt++) {
                int cb = nt * 8 + (lane & 3) * 2;
                if (cb     > r0) sreg[nt][0] = -1e30f;
                if (cb + 1 > r0) sreg[nt][1] = -1e30f;
                if (cb     > r1) sreg[nt][2] = -1e30f;
                if (cb + 1 > r1) sreg[nt][3] = -1e30f;
            }
        }

        float rmax0 = -1e30f, rmax1 = -1e30f;
#pragma unroll
        for (int nt = 0; nt < 8; nt++) {
            rmax0 = fmaxf(rmax0, fmaxf(sreg[nt][0], sreg[nt][1]));
            rmax1 = fmaxf(rmax1, fmaxf(sreg[nt][2], sreg[nt][3]));
        }
        rmax0 = fmaxf(rmax0, __shfl_xor_sync(0xffffffffu, rmax0, 1));
        rmax0 = fmaxf(rmax0, __shfl_xor_sync(0xffffffffu, rmax0, 2));
        rmax1 = fmaxf(rmax1, __shfl_xor_sync(0xffffffffu, rmax1, 1));
        rmax1 = fmaxf(rmax1, __shfl_xor_sync(0xffffffffu, rmax1, 2));
        float mn0 = fmaxf(m0, rmax0), mn1 = fmaxf(m1, rmax1);
        float corr0 = __expf(m0 - mn0), corr1 = __expf(m1 - mn1);
        m0 = mn0; m1 = mn1;

        float rs0 = 0.f, rs1 = 0.f;
        uint32_t pah[4][4], pal[4][4];
#pragma unroll
        for (int nt = 0; nt < 8; nt++) {
            float p0 = __expf(sreg[nt][0] - m0);
            float p1 = __expf(sreg[nt][1] - m0);
            float p2 = __expf(sreg[nt][2] - m1);
            float p3 = __expf(sreg[nt][3] - m1);
            rs0 += p0 + p1; rs1 += p2 + p3;
            __half h0 = __float2half_rn(p0), h1 = __float2half_rn(p1);
            __half h2 = __float2half_rn(p2), h3 = __float2half_rn(p3);
            __half e0 = __float2half_rn(p0 - __half2float(h0));
            __half e1 = __float2half_rn(p1 - __half2float(h1));
            __half e2 = __float2half_rn(p2 - __half2float(h2));
            __half e3 = __float2half_rn(p3 - __half2float(h3));
            int t = nt >> 1, pc = (nt & 1) * 2;
            pah[t][pc + 0] = packh2(h0, h1);
            pah[t][pc + 1] = packh2(h2, h3);
            pal[t][pc + 0] = packh2(e0, e1);
            pal[t][pc + 1] = packh2(e2, e3);
        }
        rs0 += __shfl_xor_sync(0xffffffffu, rs0, 1);
        rs0 += __shfl_xor_sync(0xffffffffu, rs0, 2);
        rs1 += __shfl_xor_sync(0xffffffffu, rs1, 1);
        rs1 += __shfl_xor_sync(0xffffffffu, rs1, 2);
        l0 = l0 * corr0 + rs0;
        l1 = l1 * corr1 + rs1;

#pragma unroll
        for (int dg = 0; dg < 16; dg++) {
            o[dg][0] *= corr0; o[dg][1] *= corr0;
            o[dg][2] *= corr1; o[dg][3] *= corr1;
        }

#pragma unroll
        for (int t = 0; t < 4; t++) {
#pragma unroll
            for (int pp = 0; pp < 8; pp++) {
                uint32_t vf[4];
                ldsm4t(vf, sv + vb_off + (uint32_t)(t * 16 * ATT_ROWB) + (uint32_t)(pp * 32));
                mma16816(o[2 * pp],     pah[t], &vf[0]);
                mma16816(o[2 * pp],     pal[t], &vf[0]);
                mma16816(o[2 * pp + 1], pah[t], &vf[2]);
                mma16816(o[2 * pp + 1], pal[t], &vf[2]);
            }
        }
    }

    // ---- write AO (fp16 hi only), layout [s][h*128+d] ----
    float inv0 = 1.f / l0, inv1 = 1.f / l1;
    int r0g = qb * 64 + wid * 16 + (lane >> 2);
    size_t base0 = (size_t)r0g * (NH * HD) + (size_t)h * HD;
    size_t base1 = base0 + (size_t)8 * (NH * HD);
    int coff = (lane & 3) * 2;
#pragma unroll
    for (int dg = 0; dg < 16; dg++) {
        float x0 = o[dg][0] * inv0, x1 = o[dg][1] * inv0;
        float x2 = o[dg][2] * inv1, x3 = o[dg][3] * inv1;
        *(__half2*)(AOh + base0 + dg * 8 + coff) =
            __halves2half2(__float2half_rn(x0), __float2half_rn(x1));
        *(__half2*)(AOh + base1 + dg * 8 + coff) =
            __halves2half2(__float2half_rn(x2), __float2half_rn(x3));
    }
}

// ---------------- launch ----------------
extern "C" void kernel_launch(void* const* d_in, const int* in_sizes, int n_in,
                              void* d_out, int out_size)
{
    const float* hs   = (const float*)d_in[0];
    const float* cosb = (const float*)d_in[1];
    const float* sinb = (const float*)d_in[2];
    const float* Wq   = (const float*)d_in[3];
    const float* bq   = (const float*)d_in[4];
    const float* Wk   = (const float*)d_in[5];
    const float* bk   = (const float*)d_in[6];
    const float* Wv   = (const float*)d_in[7];
    const float* bv   = (const float*)d_in[8];
    const float* Wo   = (const float*)d_in[9];
    float* out = (float*)d_out;

    float *pq, *pk;
    cudaGetSymbolAddress((void**)&pq, g_q);
    cudaGetSymbolAddress((void**)&pk, g_k);

    __half *qh, *ql, *kh, *kl, *v16, *aoh;
    cudaGetSymbolAddress((void**)&qh,  g_qh);
    cudaGetSymbolAddress((void**)&ql,  g_ql);
    cudaGetSymbolAddress((void**)&kh,  g_kh);
    cudaGetSymbolAddress((void**)&kl,  g_kl);
    cudaGetSymbolAddress((void**)&v16, g_v16);
    cudaGetSymbolAddress((void**)&aoh, g_aoh);

    __half *hs_hi, *hs_lo, *wq_hi, *wq_lo, *wk_hi, *wk_lo, *wv_hi, *wo_hi;
    cudaGetSymbolAddress((void**)&hs_hi, g_hs_hi);
    cudaGetSymbolAddress((void**)&hs_lo, g_hs_lo);
    cudaGetSymbolAddress((void**)&wq_hi, g_wq_hi);
    cudaGetSymbolAddress((void**)&wq_lo, g_wq_lo);
    cudaGetSymbolAddress((void**)&wk_hi, g_wk_hi);
    cudaGetSymbolAddress((void**)&wk_lo, g_wk_lo);
    cudaGetSymbolAddress((void**)&wv_hi, g_wv_hi);
    cudaGetSymbolAddress((void**)&wo_hi, g_wo_hi);

    // splits: hs, Wq, Wk need hi+lo; Wv, Wo need hi only
    {
        int n4;
        n4 = (S_LEN * HIDDEN) / 4;
        split_kernel<<<(n4 + 255) / 256, 256>>>(hs, hs_hi, hs_lo, n4);
        n4 = (NH * HD * HIDDEN) / 4;
        split_kernel<<<(n4 + 255) / 256, 256>>>(Wq, wq_hi, wq_lo, n4);
        n4 = (NKV * HD * HIDDEN) / 4;
        split_kernel<<<(n4 + 255) / 256, 256>>>(Wk, wk_hi, wk_lo, n4);
        split_hi_kernel<<<(n4 + 255) / 256, 256>>>(Wv, wv_hi, n4);
        n4 = (HIDDEN * NH * HD) / 4;
        split_hi_kernel<<<(n4 + 255) / 256, 256>>>(Wo, wo_hi, n4);
    }

    cudaFuncSetAttribute(qkv_fused, cudaFuncAttributeMaxDynamicSharedMemorySize, GEMM_SMEM);
    cudaFuncSetAttribute(gemm_tc,   cudaFuncAttributeMaxDynamicSharedMemorySize, GEMM_SMEM);

    // fused QKV projections (Q,K 3-pass fp32 head-major; V 2-pass fp16 head-major)
    qkv_fused<<<dim3(36, 16), 256, GEMM_SMEM>>>(hs_hi, hs_lo,
                                                wq_hi, wq_lo, bq, pq,
                                                wk_hi, wk_lo, bk, pk,
                                                wv_hi, bv, v16);

    // RoPE + fp16 split for Q, K
    rope_split<<<(NH  * S_LEN * 64 + 255) / 256, 256>>>(pq, cosb, sinb, qh, ql, NH);
    rope_split<<<(NKV * S_LEN * 64 + 255) / 256, 256>>>(pk, cosb, sinb, kh, kl, NKV);

    // HMMA flash attention
    cudaFuncSetAttribute(attn_hmma, cudaFuncAttributeMaxDynamicSharedMemorySize, ATT_SMEM);
    attn_hmma<<<dim3(S_LEN / 64, NH), 128, ATT_SMEM>>>(qh, ql, kh, kl, v16, aoh);

    // O projection (1-pass: AOh * Wo_hi), fp32 row-major out
    gemm_tc<<<dim3(NH, 16), 256, GEMM_SMEM>>>(aoh, nullptr, wo_hi, nullptr, nullptr, out, nullptr,
                                              S_LEN, HIDDEN, NH * HD, 1);
}

// round 11
// speedup vs baseline: 8.5724x; 1.1409x over previous
#include <cuda_runtime.h>
#include <cuda_fp16.h>
#include <math.h>
#include <stdint.h>

#define S_LEN   2048
#define HIDDEN  3584
#define NH      28
#define NKV     4
#define HD      128
#define GROUPS  7
#define SCALING 0.08838834764831845f

// ---------------- scratch (device globals, no allocation) ----------------
__device__ float g_q [NH  * S_LEN * HD];   // fp32 pre-rope Q
__device__ float g_k [NKV * S_LEN * HD];   // fp32 pre-rope K

__device__ __half g_qh[NH  * S_LEN * HD];
__device__ __half g_kh[NKV * S_LEN * HD];
__device__ __half g_kl[NKV * S_LEN * HD];
__device__ __half g_v16[NKV * S_LEN * HD];
__device__ __half g_aoh[S_LEN * NH * HD];

__device__ __half g_hs_hi[S_LEN * HIDDEN];
__device__ __half g_hs_lo[S_LEN * HIDDEN];
__device__ __half g_wq_hi[NH * HD * HIDDEN];
__device__ __half g_wk_hi[NKV * HD * HIDDEN];
__device__ __half g_wk_lo[NKV * HD * HIDDEN];
__device__ __half g_wv_hi[NKV * HD * HIDDEN];
__device__ __half g_wo_hi[HIDDEN * NH * HD];

// ---------------- PTX helpers ----------------
__device__ __forceinline__ uint32_t smem_u32(const void* p) {
    uint32_t a;
    asm("{ .reg .u64 t; cvta.to.shared.u64 t, %1; cvt.u32.u64 %0, t; }" : "=r"(a) : "l"(p));
    return a;
}
__device__ __forceinline__ void mma16816(float* c, const uint32_t* a, const uint32_t* b) {
    asm volatile("mma.sync.aligned.m16n8k16.row.col.f32.f16.f16.f32 "
        "{%0,%1,%2,%3}, {%4,%5,%6,%7}, {%8,%9}, {%0,%1,%2,%3};"
        : "+f"(c[0]), "+f"(c[1]), "+f"(c[2]), "+f"(c[3])
        : "r"(a[0]), "r"(a[1]), "r"(a[2]), "r"(a[3]), "r"(b[0]), "r"(b[1]));
}
__device__ __forceinline__ void ldsm4(uint32_t* r, uint32_t addr) {
    asm volatile("ldmatrix.sync.aligned.m8n8.x4.shared.b16 {%0,%1,%2,%3}, [%4];"
        : "=r"(r[0]), "=r"(r[1]), "=r"(r[2]), "=r"(r[3]) : "r"(addr));
}
__device__ __forceinline__ void ldsm4t(uint32_t* r, uint32_t addr) {
    asm volatile("ldmatrix.sync.aligned.m8n8.x4.trans.shared.b16 {%0,%1,%2,%3}, [%4];"
        : "=r"(r[0]), "=r"(r[1]), "=r"(r[2]), "=r"(r[3]) : "r"(addr));
}
__device__ __forceinline__ uint32_t packh2(__half a, __half b) {
    __half2 t = __halves2half2(a, b);
    return *(uint32_t*)&t;
}

#define GEMM_SMEM (64 * 1024)

// ---------------- GEMM body: C = A[M,K] * W[N,K]^T (+bias), fp16 split, fp32 accum ----------------
// pass count = 1 + (Alo?1) + (Blo?1):  AhiBhi [, AloBhi] [, AhiBlo]
// out_mode 0: fp32 head-major Cf[(n/128)][m][n%128]
// out_mode 1: fp32 row-major  Cf[m][n]
// out_mode 2: fp16 head-major Ch[(n/128)][m][n%128]
__device__ __forceinline__ void gemm_body(
    char* smc,
    const __half* __restrict__ Ahi, const __half* __restrict__ Alo,
    const __half* __restrict__ Bhi, const __half* __restrict__ Blo,
    const float* __restrict__ bias, float* __restrict__ Cf, __half* __restrict__ Ch,
    int M, int N, int K, int out_mode, int bm, int bn)
{
    const int tid = threadIdx.x, wid = tid >> 5, lane = tid & 31;
    const uint32_t sbase = smem_u32(smc);
    const int NC = K >> 6;
    const int total = NC * (1 + (Alo ? 1 : 0) + (Blo ? 1 : 0));

    int rowj[4], c8j[4];
    uint32_t soffj[4];
#pragma unroll
    for (int j = 0; j < 4; j++) {
        int idx = tid + j * 256;
        rowj[j] = idx >> 3;
        c8j[j]  = idx & 7;
        uint32_t so = (uint32_t)(rowj[j] * 128 + c8j[j] * 16);
        soffj[j] = so ^ ((so >> 3) & 0x70);
    }

    const int wm = wid & 3;
    const int wn = wid >> 2;

    uint32_t a_base[2], aswz[2], b_base[4], bswz[4];
    const uint32_t acol = (uint32_t)((lane >> 4) << 4);
    const uint32_t bcol = (uint32_t)(((lane >> 3) & 1) << 4);
#pragma unroll
    for (int mi = 0; mi < 2; mi++) {
        int r = wm * 32 + mi * 16 + (lane & 15);
        a_base[mi] = sbase + r * 128;
        aswz[mi]   = (uint32_t)((r & 7) << 4);
    }
#pragma unroll
    for (int p = 0; p < 4; p++) {
        int r = wn * 64 + p * 16 + ((lane >> 4) & 1) * 8 + (lane & 7);
        b_base[p] = sbase + 16384 + r * 128;
        bswz[p]   = (uint32_t)((r & 7) << 4);
    }

    float acc[2][8][4];
#pragma unroll
    for (int mi = 0; mi < 2; mi++)
#pragma unroll
        for (int ni = 0; ni < 8; ni++)
#pragma unroll
            for (int q = 0; q < 4; q++) acc[mi][ni][q] = 0.f;

    // prologue: chunk 0 -> buf0 (pass 0)
#pragma unroll
    for (int j = 0; j < 4; j++) {
        uint4 ra = *(const uint4*)(Ahi + (size_t)(bm + rowj[j]) * K + c8j[j] * 8);
        uint4 rb = *(const uint4*)(Bhi + (size_t)(bn + rowj[j]) * K + c8j[j] * 8);
        *(uint4*)(smc + soffj[j])         = ra;
        *(uint4*)(smc + 16384 + soffj[j]) = rb;
    }
    uint4 pra[4], prb[4];
    if (total > 1) {
        int cn = 1, p = cn / NC, kc = cn - p * NC;
        const __half* pa = (p == 1) ? Alo : Ahi;
        const __half* pb = (p == 2) ? Blo : Bhi;
#pragma unroll
        for (int j = 0; j < 4; j++) {
            pra[j] = *(const uint4*)(pa + (size_t)(bm + rowj[j]) * K + kc * 64 + c8j[j] * 8);
            prb[j] = *(const uint4*)(pb + (size_t)(bn + rowj[j]) * K + kc * 64 + c8j[j] * 8);
        }
    }
    __syncthreads();

    for (int c = 0; c < total; c++) {
        const int buf = c & 1;
        if (c + 1 < total) {
            const uint32_t nboff = (uint32_t)((buf ^ 1) * 32768);
#pragma unroll
            for (int j = 0; j < 4; j++) {
                *(uint4*)(smc + nboff + soffj[j])         = pra[j];
                *(uint4*)(smc + nboff + 16384 + soffj[j]) = prb[j];
            }
        }
        if (c + 2 < total) {
            int cn = c + 2, p = cn / NC, kc = cn - p * NC;
            const __half* pa = (p == 1) ? Alo : Ahi;
            const __half* pb = (p == 2) ? Blo : Bhi;
#pragma unroll
            for (int j = 0; j < 4; j++) {
                pra[j] = *(const uint4*)(pa + (size_t)(bm + rowj[j]) * K + kc * 64 + c8j[j] * 8);
                prb[j] = *(const uint4*)(pb + (size_t)(bn + rowj[j]) * K + kc * 64 + c8j[j] * 8);
            }
        }
        const uint32_t bufoff = (uint32_t)(buf * 32768);
#pragma unroll
        for (int s = 0; s < 4; s++) {
            uint32_t af[2][4], bfr[4][4];
#pragma unroll
            for (int mi = 0; mi < 2; mi++)
                ldsm4(af[mi], a_base[mi] + bufoff + (uint32_t)(((uint32_t)(s * 32) + acol) ^ aswz[mi]));
#pragma unroll
            for (int p = 0; p < 4; p++)
                ldsm4(bfr[p], b_base[p] + bufoff + (uint32_t)(((uint32_t)(s * 32) + bcol) ^ bswz[p]));
#pragma unroll
            for (int mi = 0; mi < 2; mi++)
#pragma unroll
                for (int ni = 0; ni < 8; ni++)
                    mma16816(acc[mi][ni], af[mi], &bfr[ni >> 1][(ni & 1) * 2]);
        }
        __syncthreads();
    }

    // epilogue
#pragma unroll
    for (int mi = 0; mi < 2; mi++) {
        int r0 = wm * 32 + mi * 16 + (lane >> 2);
#pragma unroll
        for (int ni = 0; ni < 8; ni++) {
            int ncol = wn * 64 + ni * 8 + (lane & 3) * 2;
            float b0 = bias ? bias[bn + ncol]     : 0.f;
            float b1 = bias ? bias[bn + ncol + 1] : 0.f;
            float v00 = acc[mi][ni][0] + b0, v01 = acc[mi][ni][1] + b1;
            float v10 = acc[mi][ni][2] + b0, v11 = acc[mi][ni][3] + b1;
            if (out_mode == 0) {
                float* base = Cf + (size_t)(bn >> 7) * M * HD;
                *(float2*)(base + (size_t)(bm + r0) * HD + (ncol & 127))     = make_float2(v00, v01);
                *(float2*)(base + (size_t)(bm + r0 + 8) * HD + (ncol & 127)) = make_float2(v10, v11);
            } else if (out_mode == 1) {
                *(float2*)(Cf + (size_t)(bm + r0) * N + bn + ncol)     = make_float2(v00, v01);
                *(float2*)(Cf + (size_t)(bm + r0 + 8) * N + bn + ncol) = make_float2(v10, v11);
            } else {
                __half* base = Ch + (size_t)(bn >> 7) * M * HD;
                *(__half2*)(base + (size_t)(bm + r0) * HD + (ncol & 127)) =
                    __halves2half2(__float2half_rn(v00), __float2half_rn(v01));
                *(__half2*)(base + (size_t)(bm + r0 + 8) * HD + (ncol & 127)) =
                    __halves2half2(__float2half_rn(v10), __float2half_rn(v11));
            }
        }
    }
}

// generic single-GEMM launcher (used for O projection)
__global__ void __launch_bounds__(256, 1)
gemm_tc(const __half* __restrict__ Ahi, const __half* __restrict__ Alo,
        const __half* __restrict__ Bhi, const __half* __restrict__ Blo,
        const float* __restrict__ bias, float* __restrict__ Cf, __half* __restrict__ Ch,
        int M, int N, int K, int out_mode)
{
    extern __shared__ __align__(1024) char smc[];
    gemm_body(smc, Ahi, Alo, Bhi, Blo, bias, Cf, Ch, M, N, K, out_mode,
              (int)(blockIdx.y << 7), (int)(blockIdx.x << 7));
}

// fused QKV: grid (36, 16). bx<28 -> Q (2-pass), 28..31 -> K (3-pass), 32..35 -> V (2-pass, fp16 out)
__global__ void __launch_bounds__(256, 1)
qkv_fused(const __half* __restrict__ hs_hi, const __half* __restrict__ hs_lo,
          const __half* __restrict__ wq_hi,
          const float* __restrict__ bq, float* __restrict__ pq,
          const __half* __restrict__ wk_hi, const __half* __restrict__ wk_lo,
          const float* __restrict__ bk, float* __restrict__ pk,
          const __half* __restrict__ wv_hi, const float* __restrict__ bv,
          __half* __restrict__ v16)
{
    extern __shared__ __align__(1024) char smc[];
    const int bx = blockIdx.x;
    const int bm = (int)(blockIdx.y << 7);
    if (bx < 28) {
        gemm_body(smc, hs_hi, hs_lo, wq_hi, nullptr, bq, pq, nullptr,
                  S_LEN, NH * HD, HIDDEN, 0, bm, bx << 7);
    } else if (bx < 32) {
        gemm_body(smc, hs_hi, hs_lo, wk_hi, wk_lo, bk, pk, nullptr,
                  S_LEN, NKV * HD, HIDDEN, 0, bm, (bx - 28) << 7);
    } else {
        gemm_body(smc, hs_hi, hs_lo, wv_hi, nullptr, bv, nullptr, v16,
                  S_LEN, NKV * HD, HIDDEN, 2, bm, (bx - 32) << 7);
    }
}

// ---------------- fp32 -> fp16 hi/lo split ----------------
__global__ void split_kernel(const float* __restrict__ x,
                             __half* __restrict__ hi,
                             __half* __restrict__ lo, int n4)
{
    int i = blockIdx.x * blockDim.x + threadIdx.x;
    if (i >= n4) return;
    float4 v = ((const float4*)x)[i];
    __half h0 = __float2half_rn(v.x), h1 = __float2half_rn(v.y);
    __half h2 = __float2half_rn(v.z), h3 = __float2half_rn(v.w);
    __half l0 = __float2half_rn(v.x - __half2float(h0));
    __half l1 = __float2half_rn(v.y - __half2float(h1));
    __half l2 = __float2half_rn(v.z - __half2float(h2));
    __half l3 = __float2half_rn(v.w - __half2float(h3));
    __half2* hp = (__half2*)hi;
    __half2* lp = (__half2*)lo;
    hp[i*2]   = __halves2half2(h0, h1);
    hp[i*2+1] = __halves2half2(h2, h3);
    lp[i*2]   = __halves2half2(l0, l1);
    lp[i*2+1] = __halves2half2(l2, l3);
}

// hi-only variant (for weights whose lo pass is dropped)
__global__ void split_hi_kernel(const float* __restrict__ x,
                                __half* __restrict__ hi, int n4)
{
    int i = blockIdx.x * blockDim.x + threadIdx.x;
    if (i >= n4) return;
    float4 v = ((const float4*)x)[i];
    __half2* hp = (__half2*)hi;
    hp[i*2]   = __halves2half2(__float2half_rn(v.x), __float2half_rn(v.y));
    hp[i*2+1] = __halves2half2(__float2half_rn(v.z), __float2half_rn(v.w));
}

// ---------------- RoPE + split: fp32 [h][s][128] -> fp16 hi/lo (for K) ----------------
__global__ void rope_split(const float* __restrict__ buf,
                           const float* __restrict__ cosb,
                           const float* __restrict__ sinb,
                           __half* __restrict__ hi, __half* __restrict__ lo,
                           int nheads)
{
    int i = blockIdx.x * blockDim.x + threadIdx.x;
    int total = nheads * S_LEN * 64;
    if (i >= total) return;
    int d = i & 63;
    int s = (i >> 6) & (S_LEN - 1);
    int h = i >> 17;
    const float* row = buf + ((size_t)h * S_LEN + s) * HD;
    float c1 = cosb[s * HD + d];
    float c2 = cosb[s * HD + d + 64];
    float s1 = sinb[s * HD + d];
    float s2 = sinb[s * HD + d + 64];
    float x1 = row[d];
    float x2 = row[d + 64];
    float y1 = x1 * c1 - x2 * s1;
    float y2 = x2 * c2 + x1 * s2;
    size_t o = ((size_t)h * S_LEN + s) * HD;
    __half a1 = __float2half_rn(y1);
    __half a2 = __float2half_rn(y2);
    hi[o + d]      = a1;
    hi[o + d + 64] = a2;
    lo[o + d]      = __float2half_rn(y1 - __half2float(a1));
    lo[o + d + 64] = __float2half_rn(y2 - __half2float(a2));
}

// RoPE, hi-only output (for Q)
__global__ void rope_hi(const float* __restrict__ buf,
                        const float* __restrict__ cosb,
                        const float* __restrict__ sinb,
                        __half* __restrict__ hi, int nheads)
{
    int i = blockIdx.x * blockDim.x + threadIdx.x;
    int total = nheads * S_LEN * 64;
    if (i >= total) return;
    int d = i & 63;
    int s = (i >> 6) & (S_LEN - 1);
    int h = i >> 17;
    const float* row = buf + ((size_t)h * S_LEN + s) * HD;
    float c1 = cosb[s * HD + d];
    float c2 = cosb[s * HD + d + 64];
    float s1 = sinb[s * HD + d];
    float s2 = sinb[s * HD + d + 64];
    float x1 = row[d];
    float x2 = row[d + 64];
    size_t o = ((size_t)h * S_LEN + s) * HD;
    hi[o + d]      = __float2half_rn(x1 * c1 - x2 * s1);
    hi[o + d + 64] = __float2half_rn(x2 * c2 + x1 * s2);
}

// ---------------- HMMA flash attention (causal, GQA) ----------------
// 128 threads = 4 warps; warp w owns q rows [w*16, w*16+16). BM=BN=64, D=128.
// QK^T: 2-pass (Q single fp16, K hi/lo). PV: 2-pass (P split, V single fp16).
#define ATT_STRIDE  136
#define ATT_ROWB    (ATT_STRIDE * 2)
#define ATT_BUF     (64 * ATT_STRIDE)
#define ATT_SMEM    (3 * ATT_BUF * 2)

__global__ void __launch_bounds__(128, 2)
attn_hmma(const __half* __restrict__ Qh,
          const __half* __restrict__ Kh, const __half* __restrict__ Kl,
          const __half* __restrict__ V,
          __half* __restrict__ AOh)
{
    extern __shared__ __align__(1024) __half sa[];
    __half* sKh = sa;
    __half* sKl = sa + ATT_BUF;
    __half* sV  = sa + 2 * ATT_BUF;

    const int qb  = (int)gridDim.x - 1 - (int)blockIdx.x;
    const int h   = blockIdx.y;
    const int kvh = h / GROUPS;
    const int tid = threadIdx.x, wid = tid >> 5, lane = tid & 31;

    const uint32_t skh = smem_u32(sKh);
    const uint32_t skl = smem_u32(sKl);
    const uint32_t sv  = smem_u32(sV);

    // ---- stage Q (hi) through sKh, extract A-fragments ----
    uint32_t qhf[8][4];
    const uint32_t a_addr = skh + (uint32_t)((wid * 16 + (lane & 15)) * ATT_ROWB + ((lane >> 4) * 8) * 2);
    {
        const __half* Qg = Qh + ((size_t)h * S_LEN + qb * 64) * HD;
#pragma unroll
        for (int j = 0; j < 8; j++) {
            int v = tid + j * 128;
            int row = v >> 4, c16 = v & 15;
            *(uint4*)((char*)sKh + row * ATT_ROWB + c16 * 16) = *(const uint4*)(Qg + (size_t)row * HD + c16 * 8);
        }
        __syncthreads();
#pragma unroll
        for (int k = 0; k < 8; k++) ldsm4(qhf[k], a_addr + k * 32);
    }

    const uint32_t kb_off = (uint32_t)((((lane >> 4) & 1) * 8 + (lane & 7)) * ATT_ROWB
                                       + ((lane >> 3) & 1) * 16);
    const uint32_t vb_off = (uint32_t)(((((lane >> 3) & 1) * 8) + (lane & 7)) * ATT_ROWB
                                       + (lane >> 4) * 16);

    float o[16][4];
#pragma unroll
    for (int dg = 0; dg < 16; dg++)
#pragma unroll
        for (int q = 0; q < 4; q++) o[dg][q] = 0.f;
    float m0 = -1e30f, m1 = -1e30f, l0 = 0.f, l1 = 0.f;

    for (int kt = 0; kt <= qb; kt++) {
        __syncthreads();
        {
            const __half* Kgh = Kh + ((size_t)kvh * S_LEN + kt * 64) * HD;
            const __half* Kgl = Kl + ((size_t)kvh * S_LEN + kt * 64) * HD;
            const __half* Vg  = V  + ((size_t)kvh * S_LEN + kt * 64) * HD;
#pragma unroll
            for (int j = 0; j < 8; j++) {
                int v = tid + j * 128;
                int row = v >> 4, c16 = v & 15;
                int doff = row * ATT_ROWB + c16 * 16;
                size_t goff = (size_t)row * HD + c16 * 8;
                *(uint4*)((char*)sKh + doff) = *(const uint4*)(Kgh + goff);
                *(uint4*)((char*)sKl + doff) = *(const uint4*)(Kgl + goff);
                *(uint4*)((char*)sV  + doff) = *(const uint4*)(Vg  + goff);
            }
        }
        __syncthreads();

        // ---- S = Q K^T (2-pass: qh*kh + qh*kl) ----
        float sreg[8][4];
#pragma unroll
        for (int nt = 0; nt < 8; nt++)
#pragma unroll
            for (int q = 0; q < 4; q++) sreg[nt][q] = 0.f;

#pragma unroll
        for (int k = 0; k < 8; k++) {
            uint32_t kfh[4][4], kfl[4][4];
#pragma unroll
            for (int g = 0; g < 4; g++) {
                ldsm4(kfh[g], skh + kb_off + (uint32_t)(g * 16 * ATT_ROWB) + (uint32_t)(k * 32));
                ldsm4(kfl[g], skl + kb_off + (uint32_t)(g * 16 * ATT_ROWB) + (uint32_t)(k * 32));
            }
#pragma unroll
            for (int nt = 0; nt < 8; nt++) {
                const uint32_t* bh = &kfh[nt >> 1][(nt & 1) * 2];
                const uint32_t* bl = &kfl[nt >> 1][(nt & 1) * 2];
                mma16816(sreg[nt], qhf[k], bh);
                mma16816(sreg[nt], qhf[k], bl);
            }
        }

#pragma unroll
        for (int nt = 0; nt < 8; nt++)
#pragma unroll
            for (int q = 0; q < 4; q++) sreg[nt][q] *= SCALING;
        if (kt == qb) {
            int r0 = wid * 16 + (lane >> 2);
            int r1 = r0 + 8;
#pragma unroll
            for (int nt = 0; nt < 8; nt++) {
                int cb = nt * 8 + (lane & 3) * 2;
                if (cb     > r0) sreg[nt][0] = -1e30f;
                if (cb + 1 > r0) sreg[nt][1] = -1e30f;
                if (cb     > r1) sreg[nt][2] = -1e30f;
                if (cb + 1 > r1) sreg[nt][3] = -1e30f;
            }
        }

        float rmax0 = -1e30f, rmax1 = -1e30f;
#pragma unroll
        for (int nt = 0; nt < 8; nt++) {
            rmax0 = fmaxf(rmax0, fmaxf(sreg[nt][0], sreg[nt][1]));
            rmax1 = fmaxf(rmax1, fmaxf(sreg[nt][2], sreg[nt][3]));
        }
        rmax0 = fmaxf(rmax0, __shfl_xor_sync(0xffffffffu, rmax0, 1));
        rmax0 = fmaxf(rmax0, __shfl_xor_sync(0xffffffffu, rmax0, 2));
        rmax1 = fmaxf(rmax1, __shfl_xor_sync(0xffffffffu, rmax1, 1));
        rmax1 = fmaxf(rmax1, __shfl_xor_sync(0xffffffffu, rmax1, 2));
        float mn0 = fmaxf(m0, rmax0), mn1 = fmaxf(m1, rmax1);
        float corr0 = __expf(m0 - mn0), corr1 = __expf(m1 - mn1);
        m0 = mn0; m1 = mn1;

        float rs0 = 0.f, rs1 = 0.f;
        uint32_t pah[4][4], pal[4][4];
#pragma unroll
        for (int nt = 0; nt < 8; nt++) {
            float p0 = __expf(sreg[nt][0] - m0);
            float p1 = __expf(sreg[nt][1] - m0);
            float p2 = __expf(sreg[nt][2] - m1);
            float p3 = __expf(sreg[nt][3] - m1);
            rs0 += p0 + p1; rs1 += p2 + p3;
            __half h0 = __float2half_rn(p0), h1 = __float2half_rn(p1);
            __half h2 = __float2half_rn(p2), h3 = __float2half_rn(p3);
            __half e0 = __float2half_rn(p0 - __half2float(h0));
            __half e1 = __float2half_rn(p1 - __half2float(h1));
            __half e2 = __float2half_rn(p2 - __half2float(h2));
            __half e3 = __float2half_rn(p3 - __half2float(h3));
            int t = nt >> 1, pc = (nt & 1) * 2;
            pah[t][pc + 0] = packh2(h0, h1);
            pah[t][pc + 1] = packh2(h2, h3);
            pal[t][pc + 0] = packh2(e0, e1);
            pal[t][pc + 1] = packh2(e2, e3);
        }
        rs0 += __shfl_xor_sync(0xffffffffu, rs0, 1);
        rs0 += __shfl_xor_sync(0xffffffffu, rs0, 2);
        rs1 += __shfl_xor_sync(0xffffffffu, rs1, 1);
        rs1 += __shfl_xor_sync(0xffffffffu, rs1, 2);
        l0 = l0 * corr0 + rs0;
        l1 = l1 * corr1 + rs1;

#pragma unroll
        for (int dg = 0; dg < 16; dg++) {
            o[dg][0] *= corr0; o[dg][1] *= corr0;
            o[dg][2] *= corr1; o[dg][3] *= corr1;
        }

#pragma unroll
        for (int t = 0; t < 4; t++) {
#pragma unroll
            for (int pp = 0; pp < 8; pp++) {
                uint32_t vf[4];
                ldsm4t(vf, sv + vb_off + (uint32_t)(t * 16 * ATT_ROWB) + (uint32_t)(pp * 32));
                mma16816(o[2 * pp],     pah[t], &vf[0]);
                mma16816(o[2 * pp],     pal[t], &vf[0]);
                mma16816(o[2 * pp + 1], pah[t], &vf[2]);
                mma16816(o[2 * pp + 1], pal[t], &vf[2]);
            }
        }
    }

    // ---- write AO (fp16 hi only), layout [s][h*128+d] ----
    float inv0 = 1.f / l0, inv1 = 1.f / l1;
    int r0g = qb * 64 + wid * 16 + (lane >> 2);
    size_t base0 = (size_t)r0g * (NH * HD) + (size_t)h * HD;
    size_t base1 = base0 + (size_t)8 * (NH * HD);
    int coff = (lane & 3) * 2;
#pragma unroll
    for (int dg = 0; dg < 16; dg++) {
        float x0 = o[dg][0] * inv0, x1 = o[dg][1] * inv0;
        float x2 = o[dg][2] * inv1, x3 = o[dg][3] * inv1;
        *(__half2*)(AOh + base0 + dg * 8 + coff) =
            __halves2half2(__float2half_rn(x0), __float2half_rn(x1));
        *(__half2*)(AOh + base1 + dg * 8 + coff) =
            __halves2half2(__float2half_rn(x2), __float2half_rn(x3));
    }
}

// ---------------- launch ----------------
extern "C" void kernel_launch(void* const* d_in, const int* in_sizes, int n_in,
                              void* d_out, int out_size)
{
    const float* hs   = (const float*)d_in[0];
    const float* cosb = (const float*)d_in[1];
    const float* sinb = (const float*)d_in[2];
    const float* Wq   = (const float*)d_in[3];
    const float* bq   = (const float*)d_in[4];
    const float* Wk   = (const float*)d_in[5];
    const float* bk   = (const float*)d_in[6];
    const float* Wv   = (const float*)d_in[7];
    const float* bv   = (const float*)d_in[8];
    const float* Wo   = (const float*)d_in[9];
    float* out = (float*)d_out;

    float *pq, *pk;
    cudaGetSymbolAddress((void**)&pq, g_q);
    cudaGetSymbolAddress((void**)&pk, g_k);

    __half *qh, *kh, *kl, *v16, *aoh;
    cudaGetSymbolAddress((void**)&qh,  g_qh);
    cudaGetSymbolAddress((void**)&kh,  g_kh);
    cudaGetSymbolAddress((void**)&kl,  g_kl);
    cudaGetSymbolAddress((void**)&v16, g_v16);
    cudaGetSymbolAddress((void**)&aoh, g_aoh);

    __half *hs_hi, *hs_lo, *wq_hi, *wk_hi, *wk_lo, *wv_hi, *wo_hi;
    cudaGetSymbolAddress((void**)&hs_hi, g_hs_hi);
    cudaGetSymbolAddress((void**)&hs_lo, g_hs_lo);
    cudaGetSymbolAddress((void**)&wq_hi, g_wq_hi);
    cudaGetSymbolAddress((void**)&wk_hi, g_wk_hi);
    cudaGetSymbolAddress((void**)&wk_lo, g_wk_lo);
    cudaGetSymbolAddress((void**)&wv_hi, g_wv_hi);
    cudaGetSymbolAddress((void**)&wo_hi, g_wo_hi);

    // splits: hs, Wk need hi+lo; Wq, Wv, Wo hi only
    {
        int n4;
        n4 = (S_LEN * HIDDEN) / 4;
        split_kernel<<<(n4 + 255) / 256, 256>>>(hs, hs_hi, hs_lo, n4);
        n4 = (NH * HD * HIDDEN) / 4;
        split_hi_kernel<<<(n4 + 255) / 256, 256>>>(Wq, wq_hi, n4);
        n4 = (NKV * HD * HIDDEN) / 4;
        split_kernel<<<(n4 + 255) / 256, 256>>>(Wk, wk_hi, wk_lo, n4);
        split_hi_kernel<<<(n4 + 255) / 256, 256>>>(Wv, wv_hi, n4);
        n4 = (HIDDEN * NH * HD) / 4;
        split_hi_kernel<<<(n4 + 255) / 256, 256>>>(Wo, wo_hi, n4);
    }

    cudaFuncSetAttribute(qkv_fused, cudaFuncAttributeMaxDynamicSharedMemorySize, GEMM_SMEM);
    cudaFuncSetAttribute(gemm_tc,   cudaFuncAttributeMaxDynamicSharedMemorySize, GEMM_SMEM);

    // fused QKV projections (Q 2-pass fp32; K 3-pass fp32; V 2-pass fp16)
    qkv_fused<<<dim3(36, 16), 256, GEMM_SMEM>>>(hs_hi, hs_lo,
                                                wq_hi, bq, pq,
                                                wk_hi, wk_lo, bk, pk,
                                                wv_hi, bv, v16);

    // RoPE: Q -> fp16 hi only; K -> fp16 hi/lo
    rope_hi   <<<(NH  * S_LEN * 64 + 255) / 256, 256>>>(pq, cosb, sinb, qh, NH);
    rope_split<<<(NKV * S_LEN * 64 + 255) / 256, 256>>>(pk, cosb, sinb, kh, kl, NKV);

    // HMMA flash attention
    cudaFuncSetAttribute(attn_hmma, cudaFuncAttributeMaxDynamicSharedMemorySize, ATT_SMEM);
    attn_hmma<<<dim3(S_LEN / 64, NH), 128, ATT_SMEM>>>(qh, kh, kl, v16, aoh);

    // O projection (1-pass: AOh * Wo_hi), fp32 row-major out
    gemm_tc<<<dim3(NH, 16), 256, GEMM_SMEM>>>(aoh, nullptr, wo_hi, nullptr, nullptr, out, nullptr,
                                              S_LEN, HIDDEN, NH * HD, 1);
}

// round 12
// speedup vs baseline: 10.2544x; 1.1962x over previous
#include <cuda_runtime.h>
#include <cuda_fp16.h>
#include <math.h>
#include <stdint.h>

#define S_LEN   2048
#define HIDDEN  3584
#define NH      28
#define NKV     4
#define HD      128
#define GROUPS  7
#define SCALING 0.08838834764831845f

// ---------------- scratch (device globals, no allocation) ----------------
__device__ float g_q [NH  * S_LEN * HD];   // fp32 pre-rope Q
__device__ float g_k [NKV * S_LEN * HD];   // fp32 pre-rope K

__device__ __half g_qh[NH  * S_LEN * HD];
__device__ __half g_kh[NKV * S_LEN * HD];
__device__ __half g_kl[NKV * S_LEN * HD];
__device__ __half g_v16[NKV * S_LEN * HD];
__device__ __half g_aoh[S_LEN * NH * HD];

__device__ __half g_hs_hi[S_LEN * HIDDEN];
__device__ __half g_hs_lo[S_LEN * HIDDEN];
__device__ __half g_wq_hi[NH * HD * HIDDEN];
__device__ __half g_wk_hi[NKV * HD * HIDDEN];
__device__ __half g_wk_lo[NKV * HD * HIDDEN];
__device__ __half g_wv_hi[NKV * HD * HIDDEN];
__device__ __half g_wo_hi[HIDDEN * NH * HD];

// ---------------- PTX helpers ----------------
__device__ __forceinline__ uint32_t smem_u32(const void* p) {
    uint32_t a;
    asm("{ .reg .u64 t; cvta.to.shared.u64 t, %1; cvt.u32.u64 %0, t; }" : "=r"(a) : "l"(p));
    return a;
}
__device__ __forceinline__ void mma16816(float* c, const uint32_t* a, const uint32_t* b) {
    asm volatile("mma.sync.aligned.m16n8k16.row.col.f32.f16.f16.f32 "
        "{%0,%1,%2,%3}, {%4,%5,%6,%7}, {%8,%9}, {%0,%1,%2,%3};"
        : "+f"(c[0]), "+f"(c[1]), "+f"(c[2]), "+f"(c[3])
        : "r"(a[0]), "r"(a[1]), "r"(a[2]), "r"(a[3]), "r"(b[0]), "r"(b[1]));
}
__device__ __forceinline__ void ldsm4(uint32_t* r, uint32_t addr) {
    asm volatile("ldmatrix.sync.aligned.m8n8.x4.shared.b16 {%0,%1,%2,%3}, [%4];"
        : "=r"(r[0]), "=r"(r[1]), "=r"(r[2]), "=r"(r[3]) : "r"(addr));
}
__device__ __forceinline__ void ldsm4t(uint32_t* r, uint32_t addr) {
    asm volatile("ldmatrix.sync.aligned.m8n8.x4.trans.shared.b16 {%0,%1,%2,%3}, [%4];"
        : "=r"(r[0]), "=r"(r[1]), "=r"(r[2]), "=r"(r[3]) : "r"(addr));
}
__device__ __forceinline__ uint32_t packh2(__half a, __half b) {
    __half2 t = __halves2half2(a, b);
    return *(uint32_t*)&t;
}
__device__ __forceinline__ void cp16(uint32_t saddr, const void* gaddr) {
    asm volatile("cp.async.cg.shared.global [%0], [%1], 16;" :: "r"(saddr), "l"(gaddr));
}
__device__ __forceinline__ void cp_commit() {
    asm volatile("cp.async.commit_group;" ::: "memory");
}
__device__ __forceinline__ void cp_wait0() {
    asm volatile("cp.async.wait_group 0;" ::: "memory");
}

#define GEMM_SMEM (64 * 1024)

// ---------------- GEMM body: C = A[M,K] * W[N,K]^T (+bias), fp16 split, fp32 accum ----------------
// cp.async double-buffered; designed for 2 CTAs/SM.
// pass count = 1 + (Alo?1) + (Blo?1):  AhiBhi [, AloBhi] [, AhiBlo]
// out_mode 0: fp32 head-major Cf[(n/128)][m][n%128]
// out_mode 1: fp32 row-major  Cf[m][n]
// out_mode 2: fp16 head-major Ch[(n/128)][m][n%128]
__device__ __forceinline__ void gemm_body(
    char* smc,
    const __half* __restrict__ Ahi, const __half* __restrict__ Alo,
    const __half* __restrict__ Bhi, const __half* __restrict__ Blo,
    const float* __restrict__ bias, float* __restrict__ Cf, __half* __restrict__ Ch,
    int M, int N, int K, int out_mode, int bm, int bn)
{
    const int tid = threadIdx.x, wid = tid >> 5, lane = tid & 31;
    const uint32_t sbase = smem_u32(smc);
    const int NC = K >> 6;
    const int total = NC * (1 + (Alo ? 1 : 0) + (Blo ? 1 : 0));

    int rowj[4], c8j[4];
    uint32_t soffj[4];
#pragma unroll
    for (int j = 0; j < 4; j++) {
        int idx = tid + j * 256;
        rowj[j] = idx >> 3;
        c8j[j]  = idx & 7;
        uint32_t so = (uint32_t)(rowj[j] * 128 + c8j[j] * 16);
        soffj[j] = so ^ ((so >> 3) & 0x70);
    }

    const int wm = wid & 3;
    const int wn = wid >> 2;

    uint32_t a_base[2], aswz[2], b_base[4], bswz[4];
    const uint32_t acol = (uint32_t)((lane >> 4) << 4);
    const uint32_t bcol = (uint32_t)(((lane >> 3) & 1) << 4);
#pragma unroll
    for (int mi = 0; mi < 2; mi++) {
        int r = wm * 32 + mi * 16 + (lane & 15);
        a_base[mi] = sbase + r * 128;
        aswz[mi]   = (uint32_t)((r & 7) << 4);
    }
#pragma unroll
    for (int p = 0; p < 4; p++) {
        int r = wn * 64 + p * 16 + ((lane >> 4) & 1) * 8 + (lane & 7);
        b_base[p] = sbase + 16384 + r * 128;
        bswz[p]   = (uint32_t)((r & 7) << 4);
    }

    float acc[2][8][4];
#pragma unroll
    for (int mi = 0; mi < 2; mi++)
#pragma unroll
        for (int ni = 0; ni < 8; ni++)
#pragma unroll
            for (int q = 0; q < 4; q++) acc[mi][ni][q] = 0.f;

    // prologue: cp.async chunk 0 -> buf0 (pass 0)
#pragma unroll
    for (int j = 0; j < 4; j++) {
        cp16(sbase + soffj[j],         Ahi + (size_t)(bm + rowj[j]) * K + c8j[j] * 8);
        cp16(sbase + 16384 + soffj[j], Bhi + (size_t)(bn + rowj[j]) * K + c8j[j] * 8);
    }
    cp_commit();
    cp_wait0();
    __syncthreads();

    for (int c = 0; c < total; c++) {
        const int buf = c & 1;
        // issue next chunk into the other buffer
        if (c + 1 < total) {
            int cn = c + 1, p = cn / NC, kc = cn - p * NC;
            const __half* pa = (p == 1) ? Alo : Ahi;
            const __half* pb = (p == 2) ? Blo : Bhi;
            const uint32_t nboff = (uint32_t)((buf ^ 1) * 32768);
#pragma unroll
            for (int j = 0; j < 4; j++) {
                cp16(sbase + nboff + soffj[j],
                     pa + (size_t)(bm + rowj[j]) * K + kc * 64 + c8j[j] * 8);
                cp16(sbase + nboff + 16384 + soffj[j],
                     pb + (size_t)(bn + rowj[j]) * K + kc * 64 + c8j[j] * 8);
            }
            cp_commit();
        }
        // compute on current buffer
        const uint32_t bufoff = (uint32_t)(buf * 32768);
#pragma unroll
        for (int s = 0; s < 4; s++) {
            uint32_t af[2][4], bfr[4][4];
#pragma unroll
            for (int mi = 0; mi < 2; mi++)
                ldsm4(af[mi], a_base[mi] + bufoff + (uint32_t)(((uint32_t)(s * 32) + acol) ^ aswz[mi]));
#pragma unroll
            for (int p = 0; p < 4; p++)
                ldsm4(bfr[p], b_base[p] + bufoff + (uint32_t)(((uint32_t)(s * 32) + bcol) ^ bswz[p]));
#pragma unroll
            for (int mi = 0; mi < 2; mi++)
#pragma unroll
                for (int ni = 0; ni < 8; ni++)
                    mma16816(acc[mi][ni], af[mi], &bfr[ni >> 1][(ni & 1) * 2]);
        }
        if (c + 1 < total) cp_wait0();
        __syncthreads();
    }

    // epilogue
#pragma unroll
    for (int mi = 0; mi < 2; mi++) {
        int r0 = wm * 32 + mi * 16 + (lane >> 2);
#pragma unroll
        for (int ni = 0; ni < 8; ni++) {
            int ncol = wn * 64 + ni * 8 + (lane & 3) * 2;
            float b0 = bias ? bias[bn + ncol]     : 0.f;
            float b1 = bias ? bias[bn + ncol + 1] : 0.f;
            float v00 = acc[mi][ni][0] + b0, v01 = acc[mi][ni][1] + b1;
            float v10 = acc[mi][ni][2] + b0, v11 = acc[mi][ni][3] + b1;
            if (out_mode == 0) {
                float* base = Cf + (size_t)(bn >> 7) * M * HD;
                *(float2*)(base + (size_t)(bm + r0) * HD + (ncol & 127))     = make_float2(v00, v01);
                *(float2*)(base + (size_t)(bm + r0 + 8) * HD + (ncol & 127)) = make_float2(v10, v11);
            } else if (out_mode == 1) {
                *(float2*)(Cf + (size_t)(bm + r0) * N + bn + ncol)     = make_float2(v00, v01);
                *(float2*)(Cf + (size_t)(bm + r0 + 8) * N + bn + ncol) = make_float2(v10, v11);
            } else {
                __half* base = Ch + (size_t)(bn >> 7) * M * HD;
                *(__half2*)(base + (size_t)(bm + r0) * HD + (ncol & 127)) =
                    __halves2half2(__float2half_rn(v00), __float2half_rn(v01));
                *(__half2*)(base + (size_t)(bm + r0 + 8) * HD + (ncol & 127)) =
                    __halves2half2(__float2half_rn(v10), __float2half_rn(v11));
            }
        }
    }
}

// generic single-GEMM launcher (used for O projection)
__global__ void __launch_bounds__(256, 2)
gemm_tc(const __half* __restrict__ Ahi, const __half* __restrict__ Alo,
        const __half* __restrict__ Bhi, const __half* __restrict__ Blo,
        const float* __restrict__ bias, float* __restrict__ Cf, __half* __restrict__ Ch,
        int M, int N, int K, int out_mode)
{
    extern __shared__ __align__(1024) char smc[];
    gemm_body(smc, Ahi, Alo, Bhi, Blo, bias, Cf, Ch, M, N, K, out_mode,
              (int)(blockIdx.y << 7), (int)(blockIdx.x << 7));
}

// fused QKV: grid (36, 16). bx<28 -> Q (2-pass), 28..31 -> K (3-pass), 32..35 -> V (2-pass, fp16 out)
__global__ void __launch_bounds__(256, 2)
qkv_fused(const __half* __restrict__ hs_hi, const __half* __restrict__ hs_lo,
          const __half* __restrict__ wq_hi,
          const float* __restrict__ bq, float* __restrict__ pq,
          const __half* __restrict__ wk_hi, const __half* __restrict__ wk_lo,
          const float* __restrict__ bk, float* __restrict__ pk,
          const __half* __restrict__ wv_hi, const float* __restrict__ bv,
          __half* __restrict__ v16)
{
    extern __shared__ __align__(1024) char smc[];
    const int bx = blockIdx.x;
    const int bm = (int)(blockIdx.y << 7);
    if (bx < 28) {
        gemm_body(smc, hs_hi, hs_lo, wq_hi, nullptr, bq, pq, nullptr,
                  S_LEN, NH * HD, HIDDEN, 0, bm, bx << 7);
    } else if (bx < 32) {
        gemm_body(smc, hs_hi, hs_lo, wk_hi, wk_lo, bk, pk, nullptr,
                  S_LEN, NKV * HD, HIDDEN, 0, bm, (bx - 28) << 7);
    } else {
        gemm_body(smc, hs_hi, hs_lo, wv_hi, nullptr, bv, nullptr, v16,
                  S_LEN, NKV * HD, HIDDEN, 2, bm, (bx - 32) << 7);
    }
}

// ---------------- fp32 -> fp16 hi/lo split ----------------
__global__ void split_kernel(const float* __restrict__ x,
                             __half* __restrict__ hi,
                             __half* __restrict__ lo, int n4)
{
    int i = blockIdx.x * blockDim.x + threadIdx.x;
    if (i >= n4) return;
    float4 v = ((const float4*)x)[i];
    __half h0 = __float2half_rn(v.x), h1 = __float2half_rn(v.y);
    __half h2 = __float2half_rn(v.z), h3 = __float2half_rn(v.w);
    __half l0 = __float2half_rn(v.x - __half2float(h0));
    __half l1 = __float2half_rn(v.y - __half2float(h1));
    __half l2 = __float2half_rn(v.z - __half2float(h2));
    __half l3 = __float2half_rn(v.w - __half2float(h3));
    __half2* hp = (__half2*)hi;
    __half2* lp = (__half2*)lo;
    hp[i*2]   = __halves2half2(h0, h1);
    hp[i*2+1] = __halves2half2(h2, h3);
    lp[i*2]   = __halves2half2(l0, l1);
    lp[i*2+1] = __halves2half2(l2, l3);
}

// hi-only variant (for weights whose lo pass is dropped)
__global__ void split_hi_kernel(const float* __restrict__ x,
                                __half* __restrict__ hi, int n4)
{
    int i = blockIdx.x * blockDim.x + threadIdx.x;
    if (i >= n4) return;
    float4 v = ((const float4*)x)[i];
    __half2* hp = (__half2*)hi;
    hp[i*2]   = __halves2half2(__float2half_rn(v.x), __float2half_rn(v.y));
    hp[i*2+1] = __halves2half2(__float2half_rn(v.z), __float2half_rn(v.w));
}

// ---------------- RoPE + split: fp32 [h][s][128] -> fp16 hi/lo (for K) ----------------
__global__ void rope_split(const float* __restrict__ buf,
                           const float* __restrict__ cosb,
                           const float* __restrict__ sinb,
                           __half* __restrict__ hi, __half* __restrict__ lo,
                           int nheads)
{
    int i = blockIdx.x * blockDim.x + threadIdx.x;
    int total = nheads * S_LEN * 64;
    if (i >= total) return;
    int d = i & 63;
    int s = (i >> 6) & (S_LEN - 1);
    int h = i >> 17;
    const float* row = buf + ((size_t)h * S_LEN + s) * HD;
    float c1 = cosb[s * HD + d];
    float c2 = cosb[s * HD + d + 64];
    float s1 = sinb[s * HD + d];
    float s2 = sinb[s * HD + d + 64];
    float x1 = row[d];
    float x2 = row[d + 64];
    float y1 = x1 * c1 - x2 * s1;
    float y2 = x2 * c2 + x1 * s2;
    size_t o = ((size_t)h * S_LEN + s) * HD;
    __half a1 = __float2half_rn(y1);
    __half a2 = __float2half_rn(y2);
    hi[o + d]      = a1;
    hi[o + d + 64] = a2;
    lo[o + d]      = __float2half_rn(y1 - __half2float(a1));
    lo[o + d + 64] = __float2half_rn(y2 - __half2float(a2));
}

// RoPE, hi-only output (for Q)
__global__ void rope_hi(const float* __restrict__ buf,
                        const float* __restrict__ cosb,
                        const float* __restrict__ sinb,
                        __half* __restrict__ hi, int nheads)
{
    int i = blockIdx.x * blockDim.x + threadIdx.x;
    int total = nheads * S_LEN * 64;
    if (i >= total) return;
    int d = i & 63;
    int s = (i >> 6) & (S_LEN - 1);
    int h = i >> 17;
    const float* row = buf + ((size_t)h * S_LEN + s) * HD;
    float c1 = cosb[s * HD + d];
    float c2 = cosb[s * HD + d + 64];
    float s1 = sinb[s * HD + d];
    float s2 = sinb[s * HD + d + 64];
    float x1 = row[d];
    float x2 = row[d + 64];
    size_t o = ((size_t)h * S_LEN + s) * HD;
    hi[o + d]      = __float2half_rn(x1 * c1 - x2 * s1);
    hi[o + d + 64] = __float2half_rn(x2 * c2 + x1 * s2);
}

// ---------------- HMMA flash attention (causal, GQA) ----------------
// 128 threads = 4 warps; warp w owns q rows [w*16, w*16+16). BM=BN=64, D=128.
// QK^T: 2-pass (Q single fp16, K hi/lo). PV: 2-pass (P split, V single fp16).
#define ATT_STRIDE  136
#define ATT_ROWB    (ATT_STRIDE * 2)
#define ATT_BUF     (64 * ATT_STRIDE)
#define ATT_SMEM    (3 * ATT_BUF * 2)

__global__ void __launch_bounds__(128, 2)
attn_hmma(const __half* __restrict__ Qh,
          const __half* __restrict__ Kh, const __half* __restrict__ Kl,
          const __half* __restrict__ V,
          __half* __restrict__ AOh)
{
    extern __shared__ __align__(1024) __half sa[];
    __half* sKh = sa;
    __half* sKl = sa + ATT_BUF;
    __half* sV  = sa + 2 * ATT_BUF;

    const int qb  = (int)gridDim.x - 1 - (int)blockIdx.x;
    const int h   = blockIdx.y;
    const int kvh = h / GROUPS;
    const int tid = threadIdx.x, wid = tid >> 5, lane = tid & 31;

    const uint32_t skh = smem_u32(sKh);
    const uint32_t skl = smem_u32(sKl);
    const uint32_t sv  = smem_u32(sV);

    // ---- stage Q (hi) through sKh, extract A-fragments ----
    uint32_t qhf[8][4];
    const uint32_t a_addr = skh + (uint32_t)((wid * 16 + (lane & 15)) * ATT_ROWB + ((lane >> 4) * 8) * 2);
    {
        const __half* Qg = Qh + ((size_t)h * S_LEN + qb * 64) * HD;
#pragma unroll
        for (int j = 0; j < 8; j++) {
            int v = tid + j * 128;
            int row = v >> 4, c16 = v & 15;
            *(uint4*)((char*)sKh + row * ATT_ROWB + c16 * 16) = *(const uint4*)(Qg + (size_t)row * HD + c16 * 8);
        }
        __syncthreads();
#pragma unroll
        for (int k = 0; k < 8; k++) ldsm4(qhf[k], a_addr + k * 32);
    }

    const uint32_t kb_off = (uint32_t)((((lane >> 4) & 1) * 8 + (lane & 7)) * ATT_ROWB
                                       + ((lane >> 3) & 1) * 16);
    const uint32_t vb_off = (uint32_t)(((((lane >> 3) & 1) * 8) + (lane & 7)) * ATT_ROWB
                                       + (lane >> 4) * 16);

    float o[16][4];
#pragma unroll
    for (int dg = 0; dg < 16; dg++)
#pragma unroll
        for (int q = 0; q < 4; q++) o[dg][q] = 0.f;
    float m0 = -1e30f, m1 = -1e30f, l0 = 0.f, l1 = 0.f;

    for (int kt = 0; kt <= qb; kt++) {
        __syncthreads();
        {
            const __half* Kgh = Kh + ((size_t)kvh * S_LEN + kt * 64) * HD;
            const __half* Kgl = Kl + ((size_t)kvh * S_LEN + kt * 64) * HD;
            const __half* Vg  = V  + ((size_t)kvh * S_LEN + kt * 64) * HD;
#pragma unroll
            for (int j = 0; j < 8; j++) {
                int v = tid + j * 128;
                int row = v >> 4, c16 = v & 15;
                int doff = row * ATT_ROWB + c16 * 16;
                size_t goff = (size_t)row * HD + c16 * 8;
                *(uint4*)((char*)sKh + doff) = *(const uint4*)(Kgh + goff);
                *(uint4*)((char*)sKl + doff) = *(const uint4*)(Kgl + goff);
                *(uint4*)((char*)sV  + doff) = *(const uint4*)(Vg  + goff);
            }
        }
        __syncthreads();

        // ---- S = Q K^T (2-pass: qh*kh + qh*kl) ----
        float sreg[8][4];
#pragma unroll
        for (int nt = 0; nt < 8; nt++)
#pragma unroll
            for (int q = 0; q < 4; q++) sreg[nt][q] = 0.f;

#pragma unroll
        for (int k = 0; k < 8; k++) {
            uint32_t kfh[4][4], kfl[4][4];
#pragma unroll
            for (int g = 0; g < 4; g++) {
                ldsm4(kfh[g], skh + kb_off + (uint32_t)(g * 16 * ATT_ROWB) + (uint32_t)(k * 32));
                ldsm4(kfl[g], skl + kb_off + (uint32_t)(g * 16 * ATT_ROWB) + (uint32_t)(k * 32));
            }
#pragma unroll
            for (int nt = 0; nt < 8; nt++) {
                const uint32_t* bh = &kfh[nt >> 1][(nt & 1) * 2];
                const uint32_t* bl = &kfl[nt >> 1][(nt & 1) * 2];
                mma16816(sreg[nt], qhf[k], bh);
                mma16816(sreg[nt], qhf[k], bl);
            }
        }

#pragma unroll
        for (int nt = 0; nt < 8; nt++)
#pragma unroll
            for (int q = 0; q < 4; q++) sreg[nt][q] *= SCALING;
        if (kt == qb) {
            int r0 = wid * 16 + (lane >> 2);
            int r1 = r0 + 8;
#pragma unroll
            for (int nt = 0; nt < 8; nt++) {
                int cb = nt * 8 + (lane & 3) * 2;
                if (cb     > r0) sreg[nt][0] = -1e30f;
                if (cb + 1 > r0) sreg[nt][1] = -1e30f;
                if (cb     > r1) sreg[nt][2] = -1e30f;
                if (cb + 1 > r1) sreg[nt][3] = -1e30f;
            }
        }

        float rmax0 = -1e30f, rmax1 = -1e30f;
#pragma unroll
        for (int nt = 0; nt < 8; nt++) {
            rmax0 = fmaxf(rmax0, fmaxf(sreg[nt][0], sreg[nt][1]));
            rmax1 = fmaxf(rmax1, fmaxf(sreg[nt][2], sreg[nt][3]));
        }
        rmax0 = fmaxf(rmax0, __shfl_xor_sync(0xffffffffu, rmax0, 1));
        rmax0 = fmaxf(rmax0, __shfl_xor_sync(0xffffffffu, rmax0, 2));
        rmax1 = fmaxf(rmax1, __shfl_xor_sync(0xffffffffu, rmax1, 1));
        rmax1 = fmaxf(rmax1, __shfl_xor_sync(0xffffffffu, rmax1, 2));
        float mn0 = fmaxf(m0, rmax0), mn1 = fmaxf(m1, rmax1);
        float corr0 = __expf(m0 - mn0), corr1 = __expf(m1 - mn1);
        m0 = mn0; m1 = mn1;

        float rs0 = 0.f, rs1 = 0.f;
        uint32_t pah[4][4], pal[4][4];
#pragma unroll
        for (int nt = 0; nt < 8; nt++) {
            float p0 = __expf(sreg[nt][0] - m0);
            float p1 = __expf(sreg[nt][1] - m0);
            float p2 = __expf(sreg[nt][2] - m1);
            float p3 = __expf(sreg[nt][3] - m1);
            rs0 += p0 + p1; rs1 += p2 + p3;
            __half h0 = __float2half_rn(p0), h1 = __float2half_rn(p1);
            __half h2 = __float2half_rn(p2), h3 = __float2half_rn(p3);
            __half e0 = __float2half_rn(p0 - __half2float(h0));
            __half e1 = __float2half_rn(p1 - __half2float(h1));
            __half e2 = __float2half_rn(p2 - __half2float(h2));
            __half e3 = __float2half_rn(p3 - __half2float(h3));
            int t = nt >> 1, pc = (nt & 1) * 2;
            pah[t][pc + 0] = packh2(h0, h1);
            pah[t][pc + 1] = packh2(h2, h3);
            pal[t][pc + 0] = packh2(e0, e1);
            pal[t][pc + 1] = packh2(e2, e3);
        }
        rs0 += __shfl_xor_sync(0xffffffffu, rs0, 1);
        rs0 += __shfl_xor_sync(0xffffffffu, rs0, 2);
        rs1 += __shfl_xor_sync(0xffffffffu, rs1, 1);
        rs1 += __shfl_xor_sync(0xffffffffu, rs1, 2);
        l0 = l0 * corr0 + rs0;
        l1 = l1 * corr1 + rs1;

#pragma unroll
        for (int dg = 0; dg < 16; dg++) {
            o[dg][0] *= corr0; o[dg][1] *= corr0;
            o[dg][2] *= corr1; o[dg][3] *= corr1;
        }

#pragma unroll
        for (int t = 0; t < 4; t++) {
#pragma unroll
            for (int pp = 0; pp < 8; pp++) {
                uint32_t vf[4];
                ldsm4t(vf, sv + vb_off + (uint32_t)(t * 16 * ATT_ROWB) + (uint32_t)(pp * 32));
                mma16816(o[2 * pp],     pah[t], &vf[0]);
                mma16816(o[2 * pp],     pal[t], &vf[0]);
                mma16816(o[2 * pp + 1], pah[t], &vf[2]);
                mma16816(o[2 * pp + 1], pal[t], &vf[2]);
            }
        }
    }

    // ---- write AO (fp16 hi only), layout [s][h*128+d] ----
    float inv0 = 1.f / l0, inv1 = 1.f / l1;
    int r0g = qb * 64 + wid * 16 + (lane >> 2);
    size_t base0 = (size_t)r0g * (NH * HD) + (size_t)h * HD;
    size_t base1 = base0 + (size_t)8 * (NH * HD);
    int coff = (lane & 3) * 2;
#pragma unroll
    for (int dg = 0; dg < 16; dg++) {
        float x0 = o[dg][0] * inv0, x1 = o[dg][1] * inv0;
        float x2 = o[dg][2] * inv1, x3 = o[dg][3] * inv1;
        *(__half2*)(AOh + base0 + dg * 8 + coff) =
            __halves2half2(__float2half_rn(x0), __float2half_rn(x1));
        *(__half2*)(AOh + base1 + dg * 8 + coff) =
            __halves2half2(__float2half_rn(x2), __float2half_rn(x3));
    }
}

// ---------------- launch ----------------
extern "C" void kernel_launch(void* const* d_in, const int* in_sizes, int n_in,
                              void* d_out, int out_size)
{
    const float* hs   = (const float*)d_in[0];
    const float* cosb = (const float*)d_in[1];
    const float* sinb = (const float*)d_in[2];
    const float* Wq   = (const float*)d_in[3];
    const float* bq   = (const float*)d_in[4];
    const float* Wk   = (const float*)d_in[5];
    const float* bk   = (const float*)d_in[6];
    const float* Wv   = (const float*)d_in[7];
    const float* bv   = (const float*)d_in[8];
    const float* Wo   = (const float*)d_in[9];
    float* out = (float*)d_out;

    float *pq, *pk;
    cudaGetSymbolAddress((void**)&pq, g_q);
    cudaGetSymbolAddress((void**)&pk, g_k);

    __half *qh, *kh, *kl, *v16, *aoh;
    cudaGetSymbolAddress((void**)&qh,  g_qh);
    cudaGetSymbolAddress((void**)&kh,  g_kh);
    cudaGetSymbolAddress((void**)&kl,  g_kl);
    cudaGetSymbolAddress((void**)&v16, g_v16);
    cudaGetSymbolAddress((void**)&aoh, g_aoh);

    __half *hs_hi, *hs_lo, *wq_hi, *wk_hi, *wk_lo, *wv_hi, *wo_hi;
    cudaGetSymbolAddress((void**)&hs_hi, g_hs_hi);
    cudaGetSymbolAddress((void**)&hs_lo, g_hs_lo);
    cudaGetSymbolAddress((void**)&wq_hi, g_wq_hi);
    cudaGetSymbolAddress((void**)&wk_hi, g_wk_hi);
    cudaGetSymbolAddress((void**)&wk_lo, g_wk_lo);
    cudaGetSymbolAddress((void**)&wv_hi, g_wv_hi);
    cudaGetSymbolAddress((void**)&wo_hi, g_wo_hi);

    // splits: hs, Wk need hi+lo; Wq, Wv, Wo hi only
    {
        int n4;
        n4 = (S_LEN * HIDDEN) / 4;
        split_kernel<<<(n4 + 255) / 256, 256>>>(hs, hs_hi, hs_lo, n4);
        n4 = (NH * HD * HIDDEN) / 4;
        split_hi_kernel<<<(n4 + 255) / 256, 256>>>(Wq, wq_hi, n4);
        n4 = (NKV * HD * HIDDEN) / 4;
        split_kernel<<<(n4 + 255) / 256, 256>>>(Wk, wk_hi, wk_lo, n4);
        split_hi_kernel<<<(n4 + 255) / 256, 256>>>(Wv, wv_hi, n4);
        n4 = (HIDDEN * NH * HD) / 4;
        split_hi_kernel<<<(n4 + 255) / 256, 256>>>(Wo, wo_hi, n4);
    }

    cudaFuncSetAttribute(qkv_fused, cudaFuncAttributeMaxDynamicSharedMemorySize, GEMM_SMEM);
    cudaFuncSetAttribute(gemm_tc,   cudaFuncAttributeMaxDynamicSharedMemorySize, GEMM_SMEM);

    // fused QKV projections (Q 2-pass fp32; K 3-pass fp32; V 2-pass fp16)
    qkv_fused<<<dim3(36, 16), 256, GEMM_SMEM>>>(hs_hi, hs_lo,
                                                wq_hi, bq, pq,
                                                wk_hi, wk_lo, bk, pk,
                                                wv_hi, bv, v16);

    // RoPE: Q -> fp16 hi only; K -> fp16 hi/lo
    rope_hi   <<<(NH  * S_LEN * 64 + 255) / 256, 256>>>(pq, cosb, sinb, qh, NH);
    rope_split<<<(NKV * S_LEN * 64 + 255) / 256, 256>>>(pk, cosb, sinb, kh, kl, NKV);

    // HMMA flash attention
    cudaFuncSetAttribute(attn_hmma, cudaFuncAttributeMaxDynamicSharedMemorySize, ATT_SMEM);
    attn_hmma<<<dim3(S_LEN / 64, NH), 128, ATT_SMEM>>>(qh, kh, kl, v16, aoh);

    // O projection (1-pass: AOh * Wo_hi), fp32 row-major out
    gemm_tc<<<dim3(NH, 16), 256, GEMM_SMEM>>>(aoh, nullptr, wo_hi, nullptr, nullptr, out, nullptr,
                                              S_LEN, HIDDEN, NH * HD, 1);
}

// round 13
// speedup vs baseline: 11.5995x; 1.1312x over previous
#include <cuda_runtime.h>
#include <cuda_fp16.h>
#include <math.h>
#include <stdint.h>

#define S_LEN   2048
#define HIDDEN  3584
#define NH      28
#define NKV     4
#define HD      128
#define GROUPS  7
#define SCALING 0.08838834764831845f

// ---------------- scratch (device globals, no allocation) ----------------
__device__ float g_q [NH  * S_LEN * HD];   // fp32 pre-rope Q
__device__ float g_k [NKV * S_LEN * HD];   // fp32 pre-rope K

__device__ __half g_qh[NH  * S_LEN * HD];
__device__ __half g_kh[NKV * S_LEN * HD];
__device__ __half g_v16[NKV * S_LEN * HD];
__device__ __half g_aoh[S_LEN * NH * HD];

__device__ __half g_hs_hi[S_LEN * HIDDEN];
__device__ __half g_hs_lo[S_LEN * HIDDEN];
__device__ __half g_wq_hi[NH * HD * HIDDEN];
__device__ __half g_wk_hi[NKV * HD * HIDDEN];
__device__ __half g_wk_lo[NKV * HD * HIDDEN];
__device__ __half g_wv_hi[NKV * HD * HIDDEN];
__device__ __half g_wo_hi[HIDDEN * NH * HD];

// ---------------- PTX helpers ----------------
__device__ __forceinline__ uint32_t smem_u32(const void* p) {
    uint32_t a;
    asm("{ .reg .u64 t; cvta.to.shared.u64 t, %1; cvt.u32.u64 %0, t; }" : "=r"(a) : "l"(p));
    return a;
}
__device__ __forceinline__ void mma16816(float* c, const uint32_t* a, const uint32_t* b) {
    asm volatile("mma.sync.aligned.m16n8k16.row.col.f32.f16.f16.f32 "
        "{%0,%1,%2,%3}, {%4,%5,%6,%7}, {%8,%9}, {%0,%1,%2,%3};"
        : "+f"(c[0]), "+f"(c[1]), "+f"(c[2]), "+f"(c[3])
        : "r"(a[0]), "r"(a[1]), "r"(a[2]), "r"(a[3]), "r"(b[0]), "r"(b[1]));
}
__device__ __forceinline__ void ldsm4(uint32_t* r, uint32_t addr) {
    asm volatile("ldmatrix.sync.aligned.m8n8.x4.shared.b16 {%0,%1,%2,%3}, [%4];"
        : "=r"(r[0]), "=r"(r[1]), "=r"(r[2]), "=r"(r[3]) : "r"(addr));
}
__device__ __forceinline__ void ldsm4t(uint32_t* r, uint32_t addr) {
    asm volatile("ldmatrix.sync.aligned.m8n8.x4.trans.shared.b16 {%0,%1,%2,%3}, [%4];"
        : "=r"(r[0]), "=r"(r[1]), "=r"(r[2]), "=r"(r[3]) : "r"(addr));
}
__device__ __forceinline__ uint32_t packh2(__half a, __half b) {
    __half2 t = __halves2half2(a, b);
    return *(uint32_t*)&t;
}
__device__ __forceinline__ void cp16(uint32_t saddr, const void* gaddr) {
    asm volatile("cp.async.cg.shared.global [%0], [%1], 16;" :: "r"(saddr), "l"(gaddr));
}
__device__ __forceinline__ void cp_commit() {
    asm volatile("cp.async.commit_group;" ::: "memory");
}
__device__ __forceinline__ void cp_wait0() {
    asm volatile("cp.async.wait_group 0;" ::: "memory");
}

#define GEMM_SMEM (64 * 1024)

// ---------------- GEMM body: C = A[M,K] * W[N,K]^T (+bias), fp16 split, fp32 accum ----------------
// cp.async double-buffered; 2 CTAs/SM.
__device__ __forceinline__ void gemm_body(
    char* smc,
    const __half* __restrict__ Ahi, const __half* __restrict__ Alo,
    const __half* __restrict__ Bhi, const __half* __restrict__ Blo,
    const float* __restrict__ bias, float* __restrict__ Cf, __half* __restrict__ Ch,
    int M, int N, int K, int out_mode, int bm, int bn)
{
    const int tid = threadIdx.x, wid = tid >> 5, lane = tid & 31;
    const uint32_t sbase = smem_u32(smc);
    const int NC = K >> 6;
    const int total = NC * (1 + (Alo ? 1 : 0) + (Blo ? 1 : 0));

    int rowj[4], c8j[4];
    uint32_t soffj[4];
#pragma unroll
    for (int j = 0; j < 4; j++) {
        int idx = tid + j * 256;
        rowj[j] = idx >> 3;
        c8j[j]  = idx & 7;
        uint32_t so = (uint32_t)(rowj[j] * 128 + c8j[j] * 16);
        soffj[j] = so ^ ((so >> 3) & 0x70);
    }

    const int wm = wid & 3;
    const int wn = wid >> 2;

    uint32_t a_base[2], aswz[2], b_base[4], bswz[4];
    const uint32_t acol = (uint32_t)((lane >> 4) << 4);
    const uint32_t bcol = (uint32_t)(((lane >> 3) & 1) << 4);
#pragma unroll
    for (int mi = 0; mi < 2; mi++) {
        int r = wm * 32 + mi * 16 + (lane & 15);
        a_base[mi] = sbase + r * 128;
        aswz[mi]   = (uint32_t)((r & 7) << 4);
    }
#pragma unroll
    for (int p = 0; p < 4; p++) {
        int r = wn * 64 + p * 16 + ((lane >> 4) & 1) * 8 + (lane & 7);
        b_base[p] = sbase + 16384 + r * 128;
        bswz[p]   = (uint32_t)((r & 7) << 4);
    }

    float acc[2][8][4];
#pragma unroll
    for (int mi = 0; mi < 2; mi++)
#pragma unroll
        for (int ni = 0; ni < 8; ni++)
#pragma unroll
            for (int q = 0; q < 4; q++) acc[mi][ni][q] = 0.f;

    // prologue
#pragma unroll
    for (int j = 0; j < 4; j++) {
        cp16(sbase + soffj[j],         Ahi + (size_t)(bm + rowj[j]) * K + c8j[j] * 8);
        cp16(sbase + 16384 + soffj[j], Bhi + (size_t)(bn + rowj[j]) * K + c8j[j] * 8);
    }
    cp_commit();
    cp_wait0();
    __syncthreads();

    for (int c = 0; c < total; c++) {
        const int buf = c & 1;
        if (c + 1 < total) {
            int cn = c + 1, p = cn / NC, kc = cn - p * NC;
            const __half* pa = (p == 1) ? Alo : Ahi;
            const __half* pb = (p == 2) ? Blo : Bhi;
            const uint32_t nboff = (uint32_t)((buf ^ 1) * 32768);
#pragma unroll
            for (int j = 0; j < 4; j++) {
                cp16(sbase + nboff + soffj[j],
                     pa + (size_t)(bm + rowj[j]) * K + kc * 64 + c8j[j] * 8);
                cp16(sbase + nboff + 16384 + soffj[j],
                     pb + (size_t)(bn + rowj[j]) * K + kc * 64 + c8j[j] * 8);
            }
            cp_commit();
        }
        const uint32_t bufoff = (uint32_t)(buf * 32768);
#pragma unroll
        for (int s = 0; s < 4; s++) {
            uint32_t af[2][4], bfr[4][4];
#pragma unroll
            for (int mi = 0; mi < 2; mi++)
                ldsm4(af[mi], a_base[mi] + bufoff + (uint32_t)(((uint32_t)(s * 32) + acol) ^ aswz[mi]));
#pragma unroll
            for (int p = 0; p < 4; p++)
                ldsm4(bfr[p], b_base[p] + bufoff + (uint32_t)(((uint32_t)(s * 32) + bcol) ^ bswz[p]));
#pragma unroll
            for (int mi = 0; mi < 2; mi++)
#pragma unroll
                for (int ni = 0; ni < 8; ni++)
                    mma16816(acc[mi][ni], af[mi], &bfr[ni >> 1][(ni & 1) * 2]);
        }
        if (c + 1 < total) cp_wait0();
        __syncthreads();
    }

    // epilogue
#pragma unroll
    for (int mi = 0; mi < 2; mi++) {
        int r0 = wm * 32 + mi * 16 + (lane >> 2);
#pragma unroll
        for (int ni = 0; ni < 8; ni++) {
            int ncol = wn * 64 + ni * 8 + (lane & 3) * 2;
            float b0 = bias ? bias[bn + ncol]     : 0.f;
            float b1 = bias ? bias[bn + ncol + 1] : 0.f;
            float v00 = acc[mi][ni][0] + b0, v01 = acc[mi][ni][1] + b1;
            float v10 = acc[mi][ni][2] + b0, v11 = acc[mi][ni][3] + b1;
            if (out_mode == 0) {
                float* base = Cf + (size_t)(bn >> 7) * M * HD;
                *(float2*)(base + (size_t)(bm + r0) * HD + (ncol & 127))     = make_float2(v00, v01);
                *(float2*)(base + (size_t)(bm + r0 + 8) * HD + (ncol & 127)) = make_float2(v10, v11);
            } else if (out_mode == 1) {
                *(float2*)(Cf + (size_t)(bm + r0) * N + bn + ncol)     = make_float2(v00, v01);
                *(float2*)(Cf + (size_t)(bm + r0 + 8) * N + bn + ncol) = make_float2(v10, v11);
            } else {
                __half* base = Ch + (size_t)(bn >> 7) * M * HD;
                *(__half2*)(base + (size_t)(bm + r0) * HD + (ncol & 127)) =
                    __halves2half2(__float2half_rn(v00), __float2half_rn(v01));
                *(__half2*)(base + (size_t)(bm + r0 + 8) * HD + (ncol & 127)) =
                    __halves2half2(__float2half_rn(v10), __float2half_rn(v11));
            }
        }
    }
}

// generic single-GEMM launcher (used for O projection)
__global__ void __launch_bounds__(256, 2)
gemm_tc(const __half* __restrict__ Ahi, const __half* __restrict__ Alo,
        const __half* __restrict__ Bhi, const __half* __restrict__ Blo,
        const float* __restrict__ bias, float* __restrict__ Cf, __half* __restrict__ Ch,
        int M, int N, int K, int out_mode)
{
    extern __shared__ __align__(1024) char smc[];
    gemm_body(smc, Ahi, Alo, Bhi, Blo, bias, Cf, Ch, M, N, K, out_mode,
              (int)(blockIdx.y << 7), (int)(blockIdx.x << 7));
}

// fused QKV: grid (36, 16). bx<28 -> Q (2-pass), 28..31 -> K (3-pass), 32..35 -> V (2-pass, fp16 out)
__global__ void __launch_bounds__(256, 2)
qkv_fused(const __half* __restrict__ hs_hi, const __half* __restrict__ hs_lo,
          const __half* __restrict__ wq_hi,
          const float* __restrict__ bq, float* __restrict__ pq,
          const __half* __restrict__ wk_hi, const __half* __restrict__ wk_lo,
          const float* __restrict__ bk, float* __restrict__ pk,
          const __half* __restrict__ wv_hi, const float* __restrict__ bv,
          __half* __restrict__ v16)
{
    extern __shared__ __align__(1024) char smc[];
    const int bx = blockIdx.x;
    const int bm = (int)(blockIdx.y << 7);
    if (bx < 28) {
        gemm_body(smc, hs_hi, hs_lo, wq_hi, nullptr, bq, pq, nullptr,
                  S_LEN, NH * HD, HIDDEN, 0, bm, bx << 7);
    } else if (bx < 32) {
        gemm_body(smc, hs_hi, hs_lo, wk_hi, wk_lo, bk, pk, nullptr,
                  S_LEN, NKV * HD, HIDDEN, 0, bm, (bx - 28) << 7);
    } else {
        gemm_body(smc, hs_hi, hs_lo, wv_hi, nullptr, bv, nullptr, v16,
                  S_LEN, NKV * HD, HIDDEN, 2, bm, (bx - 32) << 7);
    }
}

// ---------------- fp32 -> fp16 hi/lo split ----------------
__global__ void split_kernel(const float* __restrict__ x,
                             __half* __restrict__ hi,
                             __half* __restrict__ lo, int n4)
{
    int i = blockIdx.x * blockDim.x + threadIdx.x;
    if (i >= n4) return;
    float4 v = ((const float4*)x)[i];
    __half h0 = __float2half_rn(v.x), h1 = __float2half_rn(v.y);
    __half h2 = __float2half_rn(v.z), h3 = __float2half_rn(v.w);
    __half l0 = __float2half_rn(v.x - __half2float(h0));
    __half l1 = __float2half_rn(v.y - __half2float(h1));
    __half l2 = __float2half_rn(v.z - __half2float(h2));
    __half l3 = __float2half_rn(v.w - __half2float(h3));
    __half2* hp = (__half2*)hi;
    __half2* lp = (__half2*)lo;
    hp[i*2]   = __halves2half2(h0, h1);
    hp[i*2+1] = __halves2half2(h2, h3);
    lp[i*2]   = __halves2half2(l0, l1);
    lp[i*2+1] = __halves2half2(l2, l3);
}

// hi-only variant
__global__ void split_hi_kernel(const float* __restrict__ x,
                                __half* __restrict__ hi, int n4)
{
    int i = blockIdx.x * blockDim.x + threadIdx.x;
    if (i >= n4) return;
    float4 v = ((const float4*)x)[i];
    __half2* hp = (__half2*)hi;
    hp[i*2]   = __halves2half2(__float2half_rn(v.x), __float2half_rn(v.y));
    hp[i*2+1] = __halves2half2(__float2half_rn(v.z), __float2half_rn(v.w));
}

// RoPE, hi-only output (for Q and K)
__global__ void rope_hi(const float* __restrict__ buf,
                        const float* __restrict__ cosb,
                        const float* __restrict__ sinb,
                        __half* __restrict__ hi, int nheads)
{
    int i = blockIdx.x * blockDim.x + threadIdx.x;
    int total = nheads * S_LEN * 64;
    if (i >= total) return;
    int d = i & 63;
    int s = (i >> 6) & (S_LEN - 1);
    int h = i >> 17;
    const float* row = buf + ((size_t)h * S_LEN + s) * HD;
    float c1 = cosb[s * HD + d];
    float c2 = cosb[s * HD + d + 64];
    float s1 = sinb[s * HD + d];
    float s2 = sinb[s * HD + d + 64];
    float x1 = row[d];
    float x2 = row[d + 64];
    size_t o = ((size_t)h * S_LEN + s) * HD;
    hi[o + d]      = __float2half_rn(x1 * c1 - x2 * s1);
    hi[o + d + 64] = __float2half_rn(x2 * c2 + x1 * s2);
}

// ---------------- HMMA flash attention (causal, GQA) ----------------
// 128 threads = 4 warps; warp w owns q rows [w*16, w*16+16). BM=BN=64, D=128.
// QK^T: single pass (Q, K fp16). PV: single pass (P, V fp16). fp32 accum throughout.
// K/V tiles double-buffered via cp.async.
#define ATT_STRIDE  136
#define ATT_ROWB    (ATT_STRIDE * 2)
#define ATT_BUFB    (64 * ATT_ROWB)          // bytes per tile (17408)
#define ATT_SMEM    (4 * ATT_BUFB)           // 2 stages x (K + V)

__global__ void __launch_bounds__(128, 2)
attn_hmma(const __half* __restrict__ Qh,
          const __half* __restrict__ Kh,
          const __half* __restrict__ V,
          __half* __restrict__ AOh)
{
    extern __shared__ __align__(1024) char sa[];
    const uint32_t sbase = smem_u32(sa);

    const int qb  = (int)gridDim.x - 1 - (int)blockIdx.x;
    const int h   = blockIdx.y;
    const int kvh = h / GROUPS;
    const int tid = threadIdx.x, wid = tid >> 5, lane = tid & 31;

    // per-thread tile-copy mapping (64 rows x 256B)
    int crow[8], cc16[8];
#pragma unroll
    for (int j = 0; j < 8; j++) {
        int v = tid + j * 128;
        crow[j] = v >> 4;
        cc16[j] = v & 15;
    }

    // ---- stage Q through buffer 0, extract A-fragments ----
    uint32_t qhf[8][4];
    const uint32_t a_addr = sbase + (uint32_t)((wid * 16 + (lane & 15)) * ATT_ROWB + (lane >> 4) * 16);
    {
        const __half* Qg = Qh + ((size_t)h * S_LEN + qb * 64) * HD;
#pragma unroll
        for (int j = 0; j < 8; j++)
            *(uint4*)(sa + crow[j] * ATT_ROWB + cc16[j] * 16) =
                *(const uint4*)(Qg + (size_t)crow[j] * HD + cc16[j] * 8);
        __syncthreads();
#pragma unroll
        for (int k = 0; k < 8; k++) ldsm4(qhf[k], a_addr + k * 32);
        __syncthreads();   // everyone done reading Q before cp.async overwrites buf0
    }

    const uint32_t kb_off = (uint32_t)((((lane >> 4) & 1) * 8 + (lane & 7)) * ATT_ROWB
                                       + ((lane >> 3) & 1) * 16);
    const uint32_t vb_off = (uint32_t)(((((lane >> 3) & 1) * 8) + (lane & 7)) * ATT_ROWB
                                       + (lane >> 4) * 16);

    float o[16][4];
#pragma unroll
    for (int dg = 0; dg < 16; dg++)
#pragma unroll
        for (int q = 0; q < 4; q++) o[dg][q] = 0.f;
    float m0 = -1e30f, m1 = -1e30f, l0 = 0.f, l1 = 0.f;

    // prologue: tile 0 -> buffer 0
    {
        const __half* Kg = Kh + ((size_t)kvh * S_LEN) * HD;
        const __half* Vg = V  + ((size_t)kvh * S_LEN) * HD;
#pragma unroll
        for (int j = 0; j < 8; j++) {
            uint32_t doff = (uint32_t)(crow[j] * ATT_ROWB + cc16[j] * 16);
            size_t goff = (size_t)crow[j] * HD + cc16[j] * 8;
            cp16(sbase + doff,            Kg + goff);
            cp16(sbase + ATT_BUFB + doff, Vg + goff);
        }
        cp_commit();
        cp_wait0();
    }
    __syncthreads();

    for (int kt = 0; kt <= qb; kt++) {
        const int buf = kt & 1;
        // issue next tile into other buffer
        if (kt < qb) {
            const __half* Kg = Kh + ((size_t)kvh * S_LEN + (kt + 1) * 64) * HD;
            const __half* Vg = V  + ((size_t)kvh * S_LEN + (kt + 1) * 64) * HD;
            const uint32_t nboff = (uint32_t)((buf ^ 1) * 2 * ATT_BUFB);
#pragma unroll
            for (int j = 0; j < 8; j++) {
                uint32_t doff = (uint32_t)(crow[j] * ATT_ROWB + cc16[j] * 16);
                size_t goff = (size_t)crow[j] * HD + cc16[j] * 8;
                cp16(sbase + nboff + doff,            Kg + goff);
                cp16(sbase + nboff + ATT_BUFB + doff, Vg + goff);
            }
            cp_commit();
        }

        const uint32_t kbase = sbase + (uint32_t)(buf * 2 * ATT_BUFB);
        const uint32_t vbase = kbase + ATT_BUFB;

        // ---- S = Q K^T (single pass) ----
        float sreg[8][4];
#pragma unroll
        for (int nt = 0; nt < 8; nt++)
#pragma unroll
            for (int q = 0; q < 4; q++) sreg[nt][q] = 0.f;

#pragma unroll
        for (int k = 0; k < 8; k++) {
            uint32_t kfh[4][4];
#pragma unroll
            for (int g = 0; g < 4; g++)
                ldsm4(kfh[g], kbase + kb_off + (uint32_t)(g * 16 * ATT_ROWB) + (uint32_t)(k * 32));
#pragma unroll
            for (int nt = 0; nt < 8; nt++)
                mma16816(sreg[nt], qhf[k], &kfh[nt >> 1][(nt & 1) * 2]);
        }

#pragma unroll
        for (int nt = 0; nt < 8; nt++)
#pragma unroll
            for (int q = 0; q < 4; q++) sreg[nt][q] *= SCALING;
        if (kt == qb) {
            int r0 = wid * 16 + (lane >> 2);
            int r1 = r0 + 8;
#pragma unroll
            for (int nt = 0; nt < 8; nt++) {
                int cb = nt * 8 + (lane & 3) * 2;
                if (cb     > r0) sreg[nt][0] = -1e30f;
                if (cb + 1 > r0) sreg[nt][1] = -1e30f;
                if (cb     > r1) sreg[nt][2] = -1e30f;
                if (cb + 1 > r1) sreg[nt][3] = -1e30f;
            }
        }

        // ---- online softmax ----
        float rmax0 = -1e30f, rmax1 = -1e30f;
#pragma unroll
        for (int nt = 0; nt < 8; nt++) {
            rmax0 = fmaxf(rmax0, fmaxf(sreg[nt][0], sreg[nt][1]));
            rmax1 = fmaxf(rmax1, fmaxf(sreg[nt][2], sreg[nt][3]));
        }
        rmax0 = fmaxf(rmax0, __shfl_xor_sync(0xffffffffu, rmax0, 1));
        rmax0 = fmaxf(rmax0, __shfl_xor_sync(0xffffffffu, rmax0, 2));
        rmax1 = fmaxf(rmax1, __shfl_xor_sync(0xffffffffu, rmax1, 1));
        rmax1 = fmaxf(rmax1, __shfl_xor_sync(0xffffffffu, rmax1, 2));
        float mn0 = fmaxf(m0, rmax0), mn1 = fmaxf(m1, rmax1);
        float corr0 = __expf(m0 - mn0), corr1 = __expf(m1 - mn1);
        m0 = mn0; m1 = mn1;

        float rs0 = 0.f, rs1 = 0.f;
        uint32_t pah[4][4];
#pragma unroll
        for (int nt = 0; nt < 8; nt++) {
            float p0 = __expf(sreg[nt][0] - m0);
            float p1 = __expf(sreg[nt][1] - m0);
            float p2 = __expf(sreg[nt][2] - m1);
            float p3 = __expf(sreg[nt][3] - m1);
            rs0 += p0 + p1; rs1 += p2 + p3;
            int t = nt >> 1, pc = (nt & 1) * 2;
            pah[t][pc + 0] = packh2(__float2half_rn(p0), __float2half_rn(p1));
            pah[t][pc + 1] = packh2(__float2half_rn(p2), __float2half_rn(p3));
        }
        rs0 += __shfl_xor_sync(0xffffffffu, rs0, 1);
        rs0 += __shfl_xor_sync(0xffffffffu, rs0, 2);
        rs1 += __shfl_xor_sync(0xffffffffu, rs1, 1);
        rs1 += __shfl_xor_sync(0xffffffffu, rs1, 2);
        l0 = l0 * corr0 + rs0;
        l1 = l1 * corr1 + rs1;

#pragma unroll
        for (int dg = 0; dg < 16; dg++) {
            o[dg][0] *= corr0; o[dg][1] *= corr0;
            o[dg][2] *= corr1; o[dg][3] *= corr1;
        }

        // ---- O += P V (single pass) ----
#pragma unroll
        for (int t = 0; t < 4; t++) {
#pragma unroll
            for (int pp = 0; pp < 8; pp++) {
                uint32_t vf[4];
                ldsm4t(vf, vbase + vb_off + (uint32_t)(t * 16 * ATT_ROWB) + (uint32_t)(pp * 32));
                mma16816(o[2 * pp],     pah[t], &vf[0]);
                mma16816(o[2 * pp + 1], pah[t], &vf[2]);
            }
        }

        if (kt < qb) cp_wait0();
        __syncthreads();
    }

    // ---- write AO (fp16), layout [s][h*128+d] ----
    float inv0 = 1.f / l0, inv1 = 1.f / l1;
    int r0g = qb * 64 + wid * 16 + (lane >> 2);
    size_t base0 = (size_t)r0g * (NH * HD) + (size_t)h * HD;
    size_t base1 = base0 + (size_t)8 * (NH * HD);
    int coff = (lane & 3) * 2;
#pragma unroll
    for (int dg = 0; dg < 16; dg++) {
        float x0 = o[dg][0] * inv0, x1 = o[dg][1] * inv0;
        float x2 = o[dg][2] * inv1, x3 = o[dg][3] * inv1;
        *(__half2*)(AOh + base0 + dg * 8 + coff) =
            __halves2half2(__float2half_rn(x0), __float2half_rn(x1));
        *(__half2*)(AOh + base1 + dg * 8 + coff) =
            __halves2half2(__float2half_rn(x2), __float2half_rn(x3));
    }
}

// ---------------- launch ----------------
extern "C" void kernel_launch(void* const* d_in, const int* in_sizes, int n_in,
                              void* d_out, int out_size)
{
    const float* hs   = (const float*)d_in[0];
    const float* cosb = (const float*)d_in[1];
    const float* sinb = (const float*)d_in[2];
    const float* Wq   = (const float*)d_in[3];
    const float* bq   = (const float*)d_in[4];
    const float* Wk   = (const float*)d_in[5];
    const float* bk   = (const float*)d_in[6];
    const float* Wv   = (const float*)d_in[7];
    const float* bv   = (const float*)d_in[8];
    const float* Wo   = (const float*)d_in[9];
    float* out = (float*)d_out;

    float *pq, *pk;
    cudaGetSymbolAddress((void**)&pq, g_q);
    cudaGetSymbolAddress((void**)&pk, g_k);

    __half *qh, *kh, *v16, *aoh;
    cudaGetSymbolAddress((void**)&qh,  g_qh);
    cudaGetSymbolAddress((void**)&kh,  g_kh);
    cudaGetSymbolAddress((void**)&v16, g_v16);
    cudaGetSymbolAddress((void**)&aoh, g_aoh);

    __half *hs_hi, *hs_lo, *wq_hi, *wk_hi, *wk_lo, *wv_hi, *wo_hi;
    cudaGetSymbolAddress((void**)&hs_hi, g_hs_hi);
    cudaGetSymbolAddress((void**)&hs_lo, g_hs_lo);
    cudaGetSymbolAddress((void**)&wq_hi, g_wq_hi);
    cudaGetSymbolAddress((void**)&wk_hi, g_wk_hi);
    cudaGetSymbolAddress((void**)&wk_lo, g_wk_lo);
    cudaGetSymbolAddress((void**)&wv_hi, g_wv_hi);
    cudaGetSymbolAddress((void**)&wo_hi, g_wo_hi);

    // splits: hs, Wk hi+lo; Wq, Wv, Wo hi only
    {
        int n4;
        n4 = (S_LEN * HIDDEN) / 4;
        split_kernel<<<(n4 + 255) / 256, 256>>>(hs, hs_hi, hs_lo, n4);
        n4 = (NH * HD * HIDDEN) / 4;
        split_hi_kernel<<<(n4 + 255) / 256, 256>>>(Wq, wq_hi, n4);
        n4 = (NKV * HD * HIDDEN) / 4;
        split_kernel<<<(n4 + 255) / 256, 256>>>(Wk, wk_hi, wk_lo, n4);
        split_hi_kernel<<<(n4 + 255) / 256, 256>>>(Wv, wv_hi, n4);
        n4 = (HIDDEN * NH * HD) / 4;
        split_hi_kernel<<<(n4 + 255) / 256, 256>>>(Wo, wo_hi, n4);
    }

    cudaFuncSetAttribute(qkv_fused, cudaFuncAttributeMaxDynamicSharedMemorySize, GEMM_SMEM);
    cudaFuncSetAttribute(gemm_tc,   cudaFuncAttributeMaxDynamicSharedMemorySize, GEMM_SMEM);

    // fused QKV projections (Q 2-pass fp32; K 3-pass fp32; V 2-pass fp16)
    qkv_fused<<<dim3(36, 16), 256, GEMM_SMEM>>>(hs_hi, hs_lo,
                                                wq_hi, bq, pq,
                                                wk_hi, wk_lo, bk, pk,
                                                wv_hi, bv, v16);

    // RoPE: Q, K -> fp16 hi only
    rope_hi<<<(NH  * S_LEN * 64 + 255) / 256, 256>>>(pq, cosb, sinb, qh, NH);
    rope_hi<<<(NKV * S_LEN * 64 + 255) / 256, 256>>>(pk, cosb, sinb, kh, NKV);

    // HMMA flash attention (single-pass QK and PV, double-buffered K/V)
    cudaFuncSetAttribute(attn_hmma, cudaFuncAttributeMaxDynamicSharedMemorySize, ATT_SMEM);
    attn_hmma<<<dim3(S_LEN / 64, NH), 128, ATT_SMEM>>>(qh, kh, v16, aoh);

    // O projection (1-pass: AOh * Wo_hi), fp32 row-major out
    gemm_tc<<<dim3(NH, 16), 256, GEMM_SMEM>>>(aoh, nullptr, wo_hi, nullptr, nullptr, out, nullptr,
                                              S_LEN, HIDDEN, NH * HD, 1);
}

// round 16
// speedup vs baseline: 12.8563x; 1.1083x over previous
#include <cuda_runtime.h>
#include <cuda_fp16.h>
#include <math.h>
#include <stdint.h>

#define S_LEN   2048
#define HIDDEN  3584
#define NH      28
#define NKV     4
#define HD      128
#define GROUPS  7
#define SCALING 0.08838834764831845f

// ---------------- scratch (device globals, no allocation) ----------------
__device__ float g_q [NH  * S_LEN * HD];   // fp32 pre-rope Q
__device__ float g_k [NKV * S_LEN * HD];   // fp32 pre-rope K

__device__ __half g_qh[NH  * S_LEN * HD];
__device__ __half g_kh[NKV * S_LEN * HD];
__device__ __half g_v16[NKV * S_LEN * HD];
__device__ __half g_aoh[S_LEN * NH * HD];

__device__ __half g_hs_hi[S_LEN * HIDDEN];
__device__ __half g_hs_lo[S_LEN * HIDDEN];
__device__ __half g_wq_hi[NH * HD * HIDDEN];
__device__ __half g_wk_hi[NKV * HD * HIDDEN];
__device__ __half g_wk_lo[NKV * HD * HIDDEN];
__device__ __half g_wv_hi[NKV * HD * HIDDEN];
__device__ __half g_wo_hi[HIDDEN * NH * HD];

// ---------------- PTX helpers ----------------
__device__ __forceinline__ uint32_t smem_u32(const void* p) {
    uint32_t a;
    asm("{ .reg .u64 t; cvta.to.shared.u64 t, %1; cvt.u32.u64 %0, t; }" : "=r"(a) : "l"(p));
    return a;
}
__device__ __forceinline__ void mma16816(float* c, const uint32_t* a, const uint32_t* b) {
    asm volatile("mma.sync.aligned.m16n8k16.row.col.f32.f16.f16.f32 "
        "{%0,%1,%2,%3}, {%4,%5,%6,%7}, {%8,%9}, {%0,%1,%2,%3};"
        : "+f"(c[0]), "+f"(c[1]), "+f"(c[2]), "+f"(c[3])
        : "r"(a[0]), "r"(a[1]), "r"(a[2]), "r"(a[3]), "r"(b[0]), "r"(b[1]));
}
__device__ __forceinline__ void ldsm4(uint32_t* r, uint32_t addr) {
    asm volatile("ldmatrix.sync.aligned.m8n8.x4.shared.b16 {%0,%1,%2,%3}, [%4];"
        : "=r"(r[0]), "=r"(r[1]), "=r"(r[2]), "=r"(r[3]) : "r"(addr));
}
__device__ __forceinline__ void ldsm4t(uint32_t* r, uint32_t addr) {
    asm volatile("ldmatrix.sync.aligned.m8n8.x4.trans.shared.b16 {%0,%1,%2,%3}, [%4];"
        : "=r"(r[0]), "=r"(r[1]), "=r"(r[2]), "=r"(r[3]) : "r"(addr));
}
__device__ __forceinline__ uint32_t packh2(__half a, __half b) {
    __half2 t = __halves2half2(a, b);
    return *(uint32_t*)&t;
}
__device__ __forceinline__ void cp16(uint32_t saddr, const void* gaddr) {
    asm volatile("cp.async.cg.shared.global [%0], [%1], 16;" :: "r"(saddr), "l"(gaddr));
}
__device__ __forceinline__ void cp_commit() {
    asm volatile("cp.async.commit_group;" ::: "memory");
}
__device__ __forceinline__ void cp_wait0() {
    asm volatile("cp.async.wait_group 0;" ::: "memory");
}

#define GEMM_SMEM (64 * 1024)

// ---------------- GEMM body: C = A[M,K] * W[N,K]^T (+bias), fp16 split, fp32 accum ----------------
// cp.async double-buffered; 2 CTAs/SM.
__device__ __forceinline__ void gemm_body(
    char* smc,
    const __half* __restrict__ Ahi, const __half* __restrict__ Alo,
    const __half* __restrict__ Bhi, const __half* __restrict__ Blo,
    const float* __restrict__ bias, float* __restrict__ Cf, __half* __restrict__ Ch,
    int M, int N, int K, int out_mode, int bm, int bn)
{
    const int tid = threadIdx.x, wid = tid >> 5, lane = tid & 31;
    const uint32_t sbase = smem_u32(smc);
    const int NC = K >> 6;
    const int total = NC * (1 + (Alo ? 1 : 0) + (Blo ? 1 : 0));

    int rowj[4], c8j[4];
    uint32_t soffj[4];
#pragma unroll
    for (int j = 0; j < 4; j++) {
        int idx = tid + j * 256;
        rowj[j] = idx >> 3;
        c8j[j]  = idx & 7;
        uint32_t so = (uint32_t)(rowj[j] * 128 + c8j[j] * 16);
        soffj[j] = so ^ ((so >> 3) & 0x70);
    }

    const int wm = wid & 3;
    const int wn = wid >> 2;

    uint32_t a_base[2], aswz[2], b_base[4], bswz[4];
    const uint32_t acol = (uint32_t)((lane >> 4) << 4);
    const uint32_t bcol = (uint32_t)(((lane >> 3) & 1) << 4);
#pragma unroll
    for (int mi = 0; mi < 2; mi++) {
        int r = wm * 32 + mi * 16 + (lane & 15);
        a_base[mi] = sbase + r * 128;
        aswz[mi]   = (uint32_t)((r & 7) << 4);
    }
#pragma unroll
    for (int p = 0; p < 4; p++) {
        int r = wn * 64 + p * 16 + ((lane >> 4) & 1) * 8 + (lane & 7);
        b_base[p] = sbase + 16384 + r * 128;
        bswz[p]   = (uint32_t)((r & 7) << 4);
    }

    float acc[2][8][4];
#pragma unroll
    for (int mi = 0; mi < 2; mi++)
#pragma unroll
        for (int ni = 0; ni < 8; ni++)
#pragma unroll
            for (int q = 0; q < 4; q++) acc[mi][ni][q] = 0.f;

    // prologue
#pragma unroll
    for (int j = 0; j < 4; j++) {
        cp16(sbase + soffj[j],         Ahi + (size_t)(bm + rowj[j]) * K + c8j[j] * 8);
        cp16(sbase + 16384 + soffj[j], Bhi + (size_t)(bn + rowj[j]) * K + c8j[j] * 8);
    }
    cp_commit();
    cp_wait0();
    __syncthreads();

    for (int c = 0; c < total; c++) {
        const int buf = c & 1;
        if (c + 1 < total) {
            int cn = c + 1, p = cn / NC, kc = cn - p * NC;
            const __half* pa = (p == 1) ? Alo : Ahi;
            const __half* pb = (p == 2) ? Blo : Bhi;
            const uint32_t nboff = (uint32_t)((buf ^ 1) * 32768);
#pragma unroll
            for (int j = 0; j < 4; j++) {
                cp16(sbase + nboff + soffj[j],
                     pa + (size_t)(bm + rowj[j]) * K + kc * 64 + c8j[j] * 8);
                cp16(sbase + nboff + 16384 + soffj[j],
                     pb + (size_t)(bn + rowj[j]) * K + kc * 64 + c8j[j] * 8);
            }
            cp_commit();
        }
        const uint32_t bufoff = (uint32_t)(buf * 32768);
#pragma unroll
        for (int s = 0; s < 4; s++) {
            uint32_t af[2][4], bfr[4][4];
#pragma unroll
            for (int mi = 0; mi < 2; mi++)
                ldsm4(af[mi], a_base[mi] + bufoff + (uint32_t)(((uint32_t)(s * 32) + acol) ^ aswz[mi]));
#pragma unroll
            for (int p = 0; p < 4; p++)
                ldsm4(bfr[p], b_base[p] + bufoff + (uint32_t)(((uint32_t)(s * 32) + bcol) ^ bswz[p]));
#pragma unroll
            for (int mi = 0; mi < 2; mi++)
#pragma unroll
                for (int ni = 0; ni < 8; ni++)
                    mma16816(acc[mi][ni], af[mi], &bfr[ni >> 1][(ni & 1) * 2]);
        }
        if (c + 1 < total) cp_wait0();
        __syncthreads();
    }

    // epilogue
#pragma unroll
    for (int mi = 0; mi < 2; mi++) {
        int r0 = wm * 32 + mi * 16 + (lane >> 2);
#pragma unroll
        for (int ni = 0; ni < 8; ni++) {
            int ncol = wn * 64 + ni * 8 + (lane & 3) * 2;
            float b0 = bias ? bias[bn + ncol]     : 0.f;
            float b1 = bias ? bias[bn + ncol + 1] : 0.f;
            float v00 = acc[mi][ni][0] + b0, v01 = acc[mi][ni][1] + b1;
            float v10 = acc[mi][ni][2] + b0, v11 = acc[mi][ni][3] + b1;
            if (out_mode == 0) {
                float* base = Cf + (size_t)(bn >> 7) * M * HD;
                *(float2*)(base + (size_t)(bm + r0) * HD + (ncol & 127))     = make_float2(v00, v01);
                *(float2*)(base + (size_t)(bm + r0 + 8) * HD + (ncol & 127)) = make_float2(v10, v11);
            } else if (out_mode == 1) {
                *(float2*)(Cf + (size_t)(bm + r0) * N + bn + ncol)     = make_float2(v00, v01);
                *(float2*)(Cf + (size_t)(bm + r0 + 8) * N + bn + ncol) = make_float2(v10, v11);
            } else {
                __half* base = Ch + (size_t)(bn >> 7) * M * HD;
                *(__half2*)(base + (size_t)(bm + r0) * HD + (ncol & 127)) =
                    __halves2half2(__float2half_rn(v00), __float2half_rn(v01));
                *(__half2*)(base + (size_t)(bm + r0 + 8) * HD + (ncol & 127)) =
                    __halves2half2(__float2half_rn(v10), __float2half_rn(v11));
            }
        }
    }
}

// generic single-GEMM launcher (used for O projection)
__global__ void __launch_bounds__(256, 2)
gemm_tc(const __half* __restrict__ Ahi, const __half* __restrict__ Alo,
        const __half* __restrict__ Bhi, const __half* __restrict__ Blo,
        const float* __restrict__ bias, float* __restrict__ Cf, __half* __restrict__ Ch,
        int M, int N, int K, int out_mode)
{
    extern __shared__ __align__(1024) char smc[];
    gemm_body(smc, Ahi, Alo, Bhi, Blo, bias, Cf, Ch, M, N, K, out_mode,
              (int)(blockIdx.y << 7), (int)(blockIdx.x << 7));
}

// fused QKV: grid (36, 16). bx<28 -> Q (1-pass), 28..31 -> K (3-pass), 32..35 -> V (2-pass, fp16 out)
__global__ void __launch_bounds__(256, 2)
qkv_fused(const __half* __restrict__ hs_hi, const __half* __restrict__ hs_lo,
          const __half* __restrict__ wq_hi,
          const float* __restrict__ bq, float* __restrict__ pq,
          const __half* __restrict__ wk_hi, const __half* __restrict__ wk_lo,
          const float* __restrict__ bk, float* __restrict__ pk,
          const __half* __restrict__ wv_hi, const float* __restrict__ bv,
          __half* __restrict__ v16)
{
    extern __shared__ __align__(1024) char smc[];
    const int bx = blockIdx.x;
    const int bm = (int)(blockIdx.y << 7);
    if (bx < 28) {
        gemm_body(smc, hs_hi, nullptr, wq_hi, nullptr, bq, pq, nullptr,
                  S_LEN, NH * HD, HIDDEN, 0, bm, bx << 7);
    } else if (bx < 32) {
        gemm_body(smc, hs_hi, hs_lo, wk_hi, wk_lo, bk, pk, nullptr,
                  S_LEN, NKV * HD, HIDDEN, 0, bm, (bx - 28) << 7);
    } else {
        gemm_body(smc, hs_hi, hs_lo, wv_hi, nullptr, bv, nullptr, v16,
                  S_LEN, NKV * HD, HIDDEN, 2, bm, (bx - 32) << 7);
    }
}

// ---------------- fp32 -> fp16 hi/lo split ----------------
__global__ void split_kernel(const float* __restrict__ x,
                             __half* __restrict__ hi,
                             __half* __restrict__ lo, int n4)
{
    int i = blockIdx.x * blockDim.x + threadIdx.x;
    if (i >= n4) return;
    float4 v = ((const float4*)x)[i];
    __half h0 = __float2half_rn(v.x), h1 = __float2half_rn(v.y);
    __half h2 = __float2half_rn(v.z), h3 = __float2half_rn(v.w);
    __half l0 = __float2half_rn(v.x - __half2float(h0));
    __half l1 = __float2half_rn(v.y - __half2float(h1));
    __half l2 = __float2half_rn(v.z - __half2float(h2));
    __half l3 = __float2half_rn(v.w - __half2float(h3));
    __half2* hp = (__half2*)hi;
    __half2* lp = (__half2*)lo;
    hp[i*2]   = __halves2half2(h0, h1);
    hp[i*2+1] = __halves2half2(h2, h3);
    lp[i*2]   = __halves2half2(l0, l1);
    lp[i*2+1] = __halves2half2(l2, l3);
}

// hi-only variant
__global__ void split_hi_kernel(const float* __restrict__ x,
                                __half* __restrict__ hi, int n4)
{
    int i = blockIdx.x * blockDim.x + threadIdx.x;
    if (i >= n4) return;
    float4 v = ((const float4*)x)[i];
    __half2* hp = (__half2*)hi;
    hp[i*2]   = __halves2half2(__float2half_rn(v.x), __float2half_rn(v.y));
    hp[i*2+1] = __halves2half2(__float2half_rn(v.z), __float2half_rn(v.w));
}

// RoPE, hi-only output (for Q and K)
__global__ void rope_hi(const float* __restrict__ buf,
                        const float* __restrict__ cosb,
                        const float* __restrict__ sinb,
                        __half* __restrict__ hi, int nheads)
{
    int i = blockIdx.x * blockDim.x + threadIdx.x;
    int total = nheads * S_LEN * 64;
    if (i >= total) return;
    int d = i & 63;
    int s = (i >> 6) & (S_LEN - 1);
    int h = i >> 17;
    const float* row = buf + ((size_t)h * S_LEN + s) * HD;
    float c1 = cosb[s * HD + d];
    float c2 = cosb[s * HD + d + 64];
    float s1 = sinb[s * HD + d];
    float s2 = sinb[s * HD + d + 64];
    float x1 = row[d];
    float x2 = row[d + 64];
    size_t o = ((size_t)h * S_LEN + s) * HD;
    hi[o + d]      = __float2half_rn(x1 * c1 - x2 * s1);
    hi[o + d + 64] = __float2half_rn(x2 * c2 + x1 * s2);
}

// ---------------- HMMA flash attention (causal, GQA) ----------------
// 128 threads = 4 warps; warp w owns q rows [w*16, w*16+16). BM=BN=64, D=128.
// QK^T: single pass (Q, K fp16). PV: single pass (P, V fp16). fp32 accum throughout.
// K/V tiles double-buffered via cp.async.
#define ATT_STRIDE  136
#define ATT_ROWB    (ATT_STRIDE * 2)
#define ATT_BUFB    (64 * ATT_ROWB)          // bytes per tile (17408)
#define ATT_SMEM    (4 * ATT_BUFB)           // 2 stages x (K + V)

__global__ void __launch_bounds__(128, 2)
attn_hmma(const __half* __restrict__ Qh,
          const __half* __restrict__ Kh,
          const __half* __restrict__ V,
          __half* __restrict__ AOh)
{
    extern __shared__ __align__(1024) char sa[];
    const uint32_t sbase = smem_u32(sa);

    const int qb  = (int)gridDim.x - 1 - (int)blockIdx.x;
    const int h   = blockIdx.y;
    const int kvh = h / GROUPS;
    const int tid = threadIdx.x, wid = tid >> 5, lane = tid & 31;

    // per-thread tile-copy mapping (64 rows x 256B)
    int crow[8], cc16[8];
#pragma unroll
    for (int j = 0; j < 8; j++) {
        int v = tid + j * 128;
        crow[j] = v >> 4;
        cc16[j] = v & 15;
    }

    // ---- stage Q through buffer 0, extract A-fragments ----
    uint32_t qhf[8][4];
    const uint32_t a_addr = sbase + (uint32_t)((wid * 16 + (lane & 15)) * ATT_ROWB + (lane >> 4) * 16);
    {
        const __half* Qg = Qh + ((size_t)h * S_LEN + qb * 64) * HD;
#pragma unroll
        for (int j = 0; j < 8; j++)
            *(uint4*)(sa + crow[j] * ATT_ROWB + cc16[j] * 16) =
                *(const uint4*)(Qg + (size_t)crow[j] * HD + cc16[j] * 8);
        __syncthreads();
#pragma unroll
        for (int k = 0; k < 8; k++) ldsm4(qhf[k], a_addr + k * 32);
        __syncthreads();   // everyone done reading Q before cp.async overwrites buf0
    }

    const uint32_t kb_off = (uint32_t)((((lane >> 4) & 1) * 8 + (lane & 7)) * ATT_ROWB
                                       + ((lane >> 3) & 1) * 16);
    const uint32_t vb_off = (uint32_t)(((((lane >> 3) & 1) * 8) + (lane & 7)) * ATT_ROWB
                                       + (lane >> 4) * 16);

    float o[16][4];
#pragma unroll
    for (int dg = 0; dg < 16; dg++)
#pragma unroll
        for (int q = 0; q < 4; q++) o[dg][q] = 0.f;
    float m0 = -1e30f, m1 = -1e30f, l0 = 0.f, l1 = 0.f;

    // prologue: tile 0 -> buffer 0
    {
        const __half* Kg = Kh + ((size_t)kvh * S_LEN) * HD;
        const __half* Vg = V  + ((size_t)kvh * S_LEN) * HD;
#pragma unroll
        for (int j = 0; j < 8; j++) {
            uint32_t doff = (uint32_t)(crow[j] * ATT_ROWB + cc16[j] * 16);
            size_t goff = (size_t)crow[j] * HD + cc16[j] * 8;
            cp16(sbase + doff,            Kg + goff);
            cp16(sbase + ATT_BUFB + doff, Vg + goff);
        }
        cp_commit();
        cp_wait0();
    }
    __syncthreads();

    for (int kt = 0; kt <= qb; kt++) {
        const int buf = kt & 1;
        // issue next tile into other buffer
        if (kt < qb) {
            const __half* Kg = Kh + ((size_t)kvh * S_LEN + (kt + 1) * 64) * HD;
            const __half* Vg = V  + ((size_t)kvh * S_LEN + (kt + 1) * 64) * HD;
            const uint32_t nboff = (uint32_t)((buf ^ 1) * 2 * ATT_BUFB);
#pragma unroll
            for (int j = 0; j < 8; j++) {
                uint32_t doff = (uint32_t)(crow[j] * ATT_ROWB + cc16[j] * 16);
                size_t goff = (size_t)crow[j] * HD + cc16[j] * 8;
                cp16(sbase + nboff + doff,            Kg + goff);
                cp16(sbase + nboff + ATT_BUFB + doff, Vg + goff);
            }
            cp_commit();
        }

        const uint32_t kbase = sbase + (uint32_t)(buf * 2 * ATT_BUFB);
        const uint32_t vbase = kbase + ATT_BUFB;

        // ---- S = Q K^T (single pass) ----
        float sreg[8][4];
#pragma unroll
        for (int nt = 0; nt < 8; nt++)
#pragma unroll
            for (int q = 0; q < 4; q++) sreg[nt][q] = 0.f;

#pragma unroll
        for (int k = 0; k < 8; k++) {
            uint32_t kfh[4][4];
#pragma unroll
            for (int g = 0; g < 4; g++)
                ldsm4(kfh[g], kbase + kb_off + (uint32_t)(g * 16 * ATT_ROWB) + (uint32_t)(k * 32));
#pragma unroll
            for (int nt = 0; nt < 8; nt++)
                mma16816(sreg[nt], qhf[k], &kfh[nt >> 1][(nt & 1) * 2]);
        }

#pragma unroll
        for (int nt = 0; nt < 8; nt++)
#pragma unroll
            for (int q = 0; q < 4; q++) sreg[nt][q] *= SCALING;
        if (kt == qb) {
            int r0 = wid * 16 + (lane >> 2);
            int r1 = r0 + 8;
#pragma unroll
            for (int nt = 0; nt < 8; nt++) {
                int cb = nt * 8 + (lane & 3) * 2;
                if (cb     > r0) sreg[nt][0] = -1e30f;
                if (cb + 1 > r0) sreg[nt][1] = -1e30f;
                if (cb     > r1) sreg[nt][2] = -1e30f;
                if (cb + 1 > r1) sreg[nt][3] = -1e30f;
            }
        }

        // ---- online softmax ----
        float rmax0 = -1e30f, rmax1 = -1e30f;
#pragma unroll
        for (int nt = 0; nt < 8; nt++) {
            rmax0 = fmaxf(rmax0, fmaxf(sreg[nt][0], sreg[nt][1]));
            rmax1 = fmaxf(rmax1, fmaxf(sreg[nt][2], sreg[nt][3]));
        }
        rmax0 = fmaxf(rmax0, __shfl_xor_sync(0xffffffffu, rmax0, 1));
        rmax0 = fmaxf(rmax0, __shfl_xor_sync(0xffffffffu, rmax0, 2));
        rmax1 = fmaxf(rmax1, __shfl_xor_sync(0xffffffffu, rmax1, 1));
        rmax1 = fmaxf(rmax1, __shfl_xor_sync(0xffffffffu, rmax1, 2));
        float mn0 = fmaxf(m0, rmax0), mn1 = fmaxf(m1, rmax1);
        float corr0 = __expf(m0 - mn0), corr1 = __expf(m1 - mn1);
        m0 = mn0; m1 = mn1;

        float rs0 = 0.f, rs1 = 0.f;
        uint32_t pah[4][4];
#pragma unroll
        for (int nt = 0; nt < 8; nt++) {
            float p0 = __expf(sreg[nt][0] - m0);
            float p1 = __expf(sreg[nt][1] - m0);
            float p2 = __expf(sreg[nt][2] - m1);
            float p3 = __expf(sreg[nt][3] - m1);
            rs0 += p0 + p1; rs1 += p2 + p3;
            int t = nt >> 1, pc = (nt & 1) * 2;
            pah[t][pc + 0] = packh2(__float2half_rn(p0), __float2half_rn(p1));
            pah[t][pc + 1] = packh2(__float2half_rn(p2), __float2half_rn(p3));
        }
        rs0 += __shfl_xor_sync(0xffffffffu, rs0, 1);
        rs0 += __shfl_xor_sync(0xffffffffu, rs0, 2);
        rs1 += __shfl_xor_sync(0xffffffffu, rs1, 1);
        rs1 += __shfl_xor_sync(0xffffffffu, rs1, 2);
        l0 = l0 * corr0 + rs0;
        l1 = l1 * corr1 + rs1;

#pragma unroll
        for (int dg = 0; dg < 16; dg++) {
            o[dg][0] *= corr0; o[dg][1] *= corr0;
            o[dg][2] *= corr1; o[dg][3] *= corr1;
        }

        // ---- O += P V (single pass) ----
#pragma unroll
        for (int t = 0; t < 4; t++) {
#pragma unroll
            for (int pp = 0; pp < 8; pp++) {
                uint32_t vf[4];
                ldsm4t(vf, vbase + vb_off + (uint32_t)(t * 16 * ATT_ROWB) + (uint32_t)(pp * 32));
                mma16816(o[2 * pp],     pah[t], &vf[0]);
                mma16816(o[2 * pp + 1], pah[t], &vf[2]);
            }
        }

        if (kt < qb) cp_wait0();
        __syncthreads();
    }

    // ---- write AO (fp16), layout [s][h*128+d] ----
    float inv0 = 1.f / l0, inv1 = 1.f / l1;
    int r0g = qb * 64 + wid * 16 + (lane >> 2);
    size_t base0 = (size_t)r0g * (NH * HD) + (size_t)h * HD;
    size_t base1 = base0 + (size_t)8 * (NH * HD);
    int coff = (lane & 3) * 2;
#pragma unroll
    for (int dg = 0; dg < 16; dg++) {
        float x0 = o[dg][0] * inv0, x1 = o[dg][1] * inv0;
        float x2 = o[dg][2] * inv1, x3 = o[dg][3] * inv1;
        *(__half2*)(AOh + base0 + dg * 8 + coff) =
            __halves2half2(__float2half_rn(x0), __float2half_rn(x1));
        *(__half2*)(AOh + base1 + dg * 8 + coff) =
            __halves2half2(__float2half_rn(x2), __float2half_rn(x3));
    }
}

// ---------------- launch ----------------
extern "C" void kernel_launch(void* const* d_in, const int* in_sizes, int n_in,
                              void* d_out, int out_size)
{
    const float* hs   = (const float*)d_in[0];
    const float* cosb = (const float*)d_in[1];
    const float* sinb = (const float*)d_in[2];
    const float* Wq   = (const float*)d_in[3];
    const float* bq   = (const float*)d_in[4];
    const float* Wk   = (const float*)d_in[5];
    const float* bk   = (const float*)d_in[6];
    const float* Wv   = (const float*)d_in[7];
    const float* bv   = (const float*)d_in[8];
    const float* Wo   = (const float*)d_in[9];
    float* out = (float*)d_out;

    float *pq, *pk;
    cudaGetSymbolAddress((void**)&pq, g_q);
    cudaGetSymbolAddress((void**)&pk, g_k);

    __half *qh, *kh, *v16, *aoh;
    cudaGetSymbolAddress((void**)&qh,  g_qh);
    cudaGetSymbolAddress((void**)&kh,  g_kh);
    cudaGetSymbolAddress((void**)&v16, g_v16);
    cudaGetSymbolAddress((void**)&aoh, g_aoh);

    __half *hs_hi, *hs_lo, *wq_hi, *wk_hi, *wk_lo, *wv_hi, *wo_hi;
    cudaGetSymbolAddress((void**)&hs_hi, g_hs_hi);
    cudaGetSymbolAddress((void**)&hs_lo, g_hs_lo);
    cudaGetSymbolAddress((void**)&wq_hi, g_wq_hi);
    cudaGetSymbolAddress((void**)&wk_hi, g_wk_hi);
    cudaGetSymbolAddress((void**)&wk_lo, g_wk_lo);
    cudaGetSymbolAddress((void**)&wv_hi, g_wv_hi);
    cudaGetSymbolAddress((void**)&wo_hi, g_wo_hi);

    // splits: hs, Wk hi+lo; Wq, Wv, Wo hi only
    {
        int n4;
        n4 = (S_LEN * HIDDEN) / 4;
        split_kernel<<<(n4 + 255) / 256, 256>>>(hs, hs_hi, hs_lo, n4);
        n4 = (NH * HD * HIDDEN) / 4;
        split_hi_kernel<<<(n4 + 255) / 256, 256>>>(Wq, wq_hi, n4);
        n4 = (NKV * HD * HIDDEN) / 4;
        split_kernel<<<(n4 + 255) / 256, 256>>>(Wk, wk_hi, wk_lo, n4);
        split_hi_kernel<<<(n4 + 255) / 256, 256>>>(Wv, wv_hi, n4);
        n4 = (HIDDEN * NH * HD) / 4;
        split_hi_kernel<<<(n4 + 255) / 256, 256>>>(Wo, wo_hi, n4);
    }

    cudaFuncSetAttribute(qkv_fused, cudaFuncAttributeMaxDynamicSharedMemorySize, GEMM_SMEM);
    cudaFuncSetAttribute(gemm_tc,   cudaFuncAttributeMaxDynamicSharedMemorySize, GEMM_SMEM);

    // fused QKV projections (Q 1-pass fp32; K 3-pass fp32; V 2-pass fp16)
    qkv_fused<<<dim3(36, 16), 256, GEMM_SMEM>>>(hs_hi, hs_lo,
                                                wq_hi, bq, pq,
                                                wk_hi, wk_lo, bk, pk,
                                                wv_hi, bv, v16);

    // RoPE: Q, K -> fp16 hi only
    rope_hi<<<(NH  * S_LEN * 64 + 255) / 256, 256>>>(pq, cosb, sinb, qh, NH);
    rope_hi<<<(NKV * S_LEN * 64 + 255) / 256, 256>>>(pk, cosb, sinb, kh, NKV);

    // HMMA flash attention (single-pass QK and PV, double-buffered K/V)
    cudaFuncSetAttribute(attn_hmma, cudaFuncAttributeMaxDynamicSharedMemorySize, ATT_SMEM);
    attn_hmma<<<dim3(S_LEN / 64, NH), 128, ATT_SMEM>>>(qh, kh, v16, aoh);

    // O projection (1-pass: AOh * Wo_hi), fp32 row-major out
    gemm_tc<<<dim3(NH, 16), 256, GEMM_SMEM>>>(aoh, nullptr, wo_hi, nullptr, nullptr, out, nullptr,
                                              S_LEN, HIDDEN, NH * HD, 1);
}

// round 17
// speedup vs baseline: 12.9774x; 1.0094x over previous
#include <cuda_runtime.h>
#include <cuda_fp16.h>
#include <math.h>
#include <stdint.h>

#define S_LEN   2048
#define HIDDEN  3584
#define NH      28
#define NKV     4
#define HD      128
#define GROUPS  7
#define SCALING 0.08838834764831845f
#define C2EXP   0.1275174313f        // SCALING * log2(e)

// ---------------- scratch (device globals, no allocation) ----------------
__device__ float g_q [NH  * S_LEN * HD];
__device__ float g_k [NKV * S_LEN * HD];

__device__ __half g_qh[NH  * S_LEN * HD];
__device__ __half g_kh[NKV * S_LEN * HD];
__device__ __half g_v16[NKV * S_LEN * HD];
__device__ __half g_aoh[S_LEN * NH * HD];

__device__ __half g_hs_hi[S_LEN * HIDDEN];
__device__ __half g_hs_lo[S_LEN * HIDDEN];
__device__ __half g_wq_hi[NH * HD * HIDDEN];
__device__ __half g_wk_hi[NKV * HD * HIDDEN];
__device__ __half g_wk_lo[NKV * HD * HIDDEN];
__device__ __half g_wv_hi[NKV * HD * HIDDEN];
__device__ __half g_wo_hi[HIDDEN * NH * HD];

// ---------------- PTX helpers ----------------
__device__ __forceinline__ uint32_t smem_u32(const void* p) {
    uint32_t a;
    asm("{ .reg .u64 t; cvta.to.shared.u64 t, %1; cvt.u32.u64 %0, t; }" : "=r"(a) : "l"(p));
    return a;
}
__device__ __forceinline__ void mma16816(float* c, const uint32_t* a, const uint32_t* b) {
    asm volatile("mma.sync.aligned.m16n8k16.row.col.f32.f16.f16.f32 "
        "{%0,%1,%2,%3}, {%4,%5,%6,%7}, {%8,%9}, {%0,%1,%2,%3};"
        : "+f"(c[0]), "+f"(c[1]), "+f"(c[2]), "+f"(c[3])
        : "r"(a[0]), "r"(a[1]), "r"(a[2]), "r"(a[3]), "r"(b[0]), "r"(b[1]));
}
__device__ __forceinline__ void ldsm4(uint32_t* r, uint32_t addr) {
    asm volatile("ldmatrix.sync.aligned.m8n8.x4.shared.b16 {%0,%1,%2,%3}, [%4];"
        : "=r"(r[0]), "=r"(r[1]), "=r"(r[2]), "=r"(r[3]) : "r"(addr));
}
__device__ __forceinline__ void ldsm4t(uint32_t* r, uint32_t addr) {
    asm volatile("ldmatrix.sync.aligned.m8n8.x4.trans.shared.b16 {%0,%1,%2,%3}, [%4];"
        : "=r"(r[0]), "=r"(r[1]), "=r"(r[2]), "=r"(r[3]) : "r"(addr));
}
__device__ __forceinline__ uint32_t packh2(__half a, __half b) {
    __half2 t = __halves2half2(a, b);
    return *(uint32_t*)&t;
}
__device__ __forceinline__ void cp16(uint32_t saddr, const void* gaddr) {
    asm volatile("cp.async.cg.shared.global [%0], [%1], 16;" :: "r"(saddr), "l"(gaddr));
}
__device__ __forceinline__ void cp_commit() {
    asm volatile("cp.async.commit_group;" ::: "memory");
}
__device__ __forceinline__ void cp_wait0() {
    asm volatile("cp.async.wait_group 0;" ::: "memory");
}
__device__ __forceinline__ float fexp2(float x) {
    float y;
    asm("ex2.approx.f32 %0, %1;" : "=f"(y) : "f"(x));
    return y;
}

#define GEMM_SMEM (64 * 1024)

// ---------------- GEMM body: C = A[M,K] * W[N,K]^T (+bias), fp16 split, fp32 accum ----------------
__device__ __forceinline__ void gemm_body(
    char* smc,
    const __half* __restrict__ Ahi, const __half* __restrict__ Alo,
    const __half* __restrict__ Bhi, const __half* __restrict__ Blo,
    const float* __restrict__ bias, float* __restrict__ Cf, __half* __restrict__ Ch,
    int M, int N, int K, int out_mode, int bm, int bn)
{
    const int tid = threadIdx.x, wid = tid >> 5, lane = tid & 31;
    const uint32_t sbase = smem_u32(smc);
    const int NC = K >> 6;
    const int total = NC * (1 + (Alo ? 1 : 0) + (Blo ? 1 : 0));

    int rowj[4], c8j[4];
    uint32_t soffj[4];
#pragma unroll
    for (int j = 0; j < 4; j++) {
        int idx = tid + j * 256;
        rowj[j] = idx >> 3;
        c8j[j]  = idx & 7;
        uint32_t so = (uint32_t)(rowj[j] * 128 + c8j[j] * 16);
        soffj[j] = so ^ ((so >> 3) & 0x70);
    }

    const int wm = wid & 3;
    const int wn = wid >> 2;

    uint32_t a_base[2], aswz[2], b_base[4], bswz[4];
    const uint32_t acol = (uint32_t)((lane >> 4) << 4);
    const uint32_t bcol = (uint32_t)(((lane >> 3) & 1) << 4);
#pragma unroll
    for (int mi = 0; mi < 2; mi++) {
        int r = wm * 32 + mi * 16 + (lane & 15);
        a_base[mi] = sbase + r * 128;
        aswz[mi]   = (uint32_t)((r & 7) << 4);
    }
#pragma unroll
    for (int p = 0; p < 4; p++) {
        int r = wn * 64 + p * 16 + ((lane >> 4) & 1) * 8 + (lane & 7);
        b_base[p] = sbase + 16384 + r * 128;
        bswz[p]   = (uint32_t)((r & 7) << 4);
    }

    float acc[2][8][4];
#pragma unroll
    for (int mi = 0; mi < 2; mi++)
#pragma unroll
        for (int ni = 0; ni < 8; ni++)
#pragma unroll
            for (int q = 0; q < 4; q++) acc[mi][ni][q] = 0.f;

#pragma unroll
    for (int j = 0; j < 4; j++) {
        cp16(sbase + soffj[j],         Ahi + (size_t)(bm + rowj[j]) * K + c8j[j] * 8);
        cp16(sbase + 16384 + soffj[j], Bhi + (size_t)(bn + rowj[j]) * K + c8j[j] * 8);
    }
    cp_commit();
    cp_wait0();
    __syncthreads();

    for (int c = 0; c < total; c++) {
        const int buf = c & 1;
        if (c + 1 < total) {
            int cn = c + 1, p = cn / NC, kc = cn - p * NC;
            const __half* pa = (p == 1) ? Alo : Ahi;
            const __half* pb = (p == 2) ? Blo : Bhi;
            const uint32_t nboff = (uint32_t)((buf ^ 1) * 32768);
#pragma unroll
            for (int j = 0; j < 4; j++) {
                cp16(sbase + nboff + soffj[j],
                     pa + (size_t)(bm + rowj[j]) * K + kc * 64 + c8j[j] * 8);
                cp16(sbase + nboff + 16384 + soffj[j],
                     pb + (size_t)(bn + rowj[j]) * K + kc * 64 + c8j[j] * 8);
            }
            cp_commit();
        }
        const uint32_t bufoff = (uint32_t)(buf * 32768);
#pragma unroll
        for (int s = 0; s < 4; s++) {
            uint32_t af[2][4], bfr[4][4];
#pragma unroll
            for (int mi = 0; mi < 2; mi++)
                ldsm4(af[mi], a_base[mi] + bufoff + (uint32_t)(((uint32_t)(s * 32) + acol) ^ aswz[mi]));
#pragma unroll
            for (int p = 0; p < 4; p++)
                ldsm4(bfr[p], b_base[p] + bufoff + (uint32_t)(((uint32_t)(s * 32) + bcol) ^ bswz[p]));
#pragma unroll
            for (int mi = 0; mi < 2; mi++)
#pragma unroll
                for (int ni = 0; ni < 8; ni++)
                    mma16816(acc[mi][ni], af[mi], &bfr[ni >> 1][(ni & 1) * 2]);
        }
        if (c + 1 < total) cp_wait0();
        __syncthreads();
    }

#pragma unroll
    for (int mi = 0; mi < 2; mi++) {
        int r0 = wm * 32 + mi * 16 + (lane >> 2);
#pragma unroll
        for (int ni = 0; ni < 8; ni++) {
            int ncol = wn * 64 + ni * 8 + (lane & 3) * 2;
            float b0 = bias ? bias[bn + ncol]     : 0.f;
            float b1 = bias ? bias[bn + ncol + 1] : 0.f;
            float v00 = acc[mi][ni][0] + b0, v01 = acc[mi][ni][1] + b1;
            float v10 = acc[mi][ni][2] + b0, v11 = acc[mi][ni][3] + b1;
            if (out_mode == 0) {
                float* base = Cf + (size_t)(bn >> 7) * M * HD;
                *(float2*)(base + (size_t)(bm + r0) * HD + (ncol & 127))     = make_float2(v00, v01);
                *(float2*)(base + (size_t)(bm + r0 + 8) * HD + (ncol & 127)) = make_float2(v10, v11);
            } else if (out_mode == 1) {
                *(float2*)(Cf + (size_t)(bm + r0) * N + bn + ncol)     = make_float2(v00, v01);
                *(float2*)(Cf + (size_t)(bm + r0 + 8) * N + bn + ncol) = make_float2(v10, v11);
            } else {
                __half* base = Ch + (size_t)(bn >> 7) * M * HD;
                *(__half2*)(base + (size_t)(bm + r0) * HD + (ncol & 127)) =
                    __halves2half2(__float2half_rn(v00), __float2half_rn(v01));
                *(__half2*)(base + (size_t)(bm + r0 + 8) * HD + (ncol & 127)) =
                    __halves2half2(__float2half_rn(v10), __float2half_rn(v11));
            }
        }
    }
}

__global__ void __launch_bounds__(256, 2)
gemm_tc(const __half* __restrict__ Ahi, const __half* __restrict__ Alo,
        const __half* __restrict__ Bhi, const __half* __restrict__ Blo,
        const float* __restrict__ bias, float* __restrict__ Cf, __half* __restrict__ Ch,
        int M, int N, int K, int out_mode)
{
    extern __shared__ __align__(1024) char smc[];
    gemm_body(smc, Ahi, Alo, Bhi, Blo, bias, Cf, Ch, M, N, K, out_mode,
              (int)(blockIdx.y << 7), (int)(blockIdx.x << 7));
}

// fused QKV: grid (36, 16). bx<28 -> Q (1-pass), 28..31 -> K (3-pass), 32..35 -> V (2-pass, fp16 out)
__global__ void __launch_bounds__(256, 2)
qkv_fused(const __half* __restrict__ hs_hi, const __half* __restrict__ hs_lo,
          const __half* __restrict__ wq_hi,
          const float* __restrict__ bq, float* __restrict__ pq,
          const __half* __restrict__ wk_hi, const __half* __restrict__ wk_lo,
          const float* __restrict__ bk, float* __restrict__ pk,
          const __half* __restrict__ wv_hi, const float* __restrict__ bv,
          __half* __restrict__ v16)
{
    extern __shared__ __align__(1024) char smc[];
    const int bx = blockIdx.x;
    const int bm = (int)(blockIdx.y << 7);
    if (bx < 28) {
        gemm_body(smc, hs_hi, nullptr, wq_hi, nullptr, bq, pq, nullptr,
                  S_LEN, NH * HD, HIDDEN, 0, bm, bx << 7);
    } else if (bx < 32) {
        gemm_body(smc, hs_hi, hs_lo, wk_hi, wk_lo, bk, pk, nullptr,
                  S_LEN, NKV * HD, HIDDEN, 0, bm, (bx - 28) << 7);
    } else {
        gemm_body(smc, hs_hi, hs_lo, wv_hi, nullptr, bv, nullptr, v16,
                  S_LEN, NKV * HD, HIDDEN, 2, bm, (bx - 32) << 7);
    }
}

// ---------------- merged split kernel: all 5 arrays in one launch ----------------
#define N_HS4  ((S_LEN * HIDDEN) / 4)
#define N_WQ4  ((NH * HD * HIDDEN) / 4)
#define N_WK4  ((NKV * HD * HIDDEN) / 4)
#define N_WV4  ((NKV * HD * HIDDEN) / 4)
#define N_WO4  ((HIDDEN * NH * HD) / 4)
#define N_ALL4 (N_HS4 + N_WQ4 + N_WK4 + N_WV4 + N_WO4)

__device__ __forceinline__ void split_hilo4(const float* x, __half* hi, __half* lo, int i) {
    float4 v = ((const float4*)x)[i];
    __half h0 = __float2half_rn(v.x), h1 = __float2half_rn(v.y);
    __half h2 = __float2half_rn(v.z), h3 = __float2half_rn(v.w);
    __half2* hp = (__half2*)hi;
    hp[i*2]   = __halves2half2(h0, h1);
    hp[i*2+1] = __halves2half2(h2, h3);
    __half2* lp = (__half2*)lo;
    lp[i*2]   = __halves2half2(__float2half_rn(v.x - __half2float(h0)),
                               __float2half_rn(v.y - __half2float(h1)));
    lp[i*2+1] = __halves2half2(__float2half_rn(v.z - __half2float(h2)),
                               __float2half_rn(v.w - __half2float(h3)));
}
__device__ __forceinline__ void split_hi4(const float* x, __half* hi, int i) {
    float4 v = ((const float4*)x)[i];
    __half2* hp = (__half2*)hi;
    hp[i*2]   = __halves2half2(__float2half_rn(v.x), __float2half_rn(v.y));
    hp[i*2+1] = __halves2half2(__float2half_rn(v.z), __float2half_rn(v.w));
}

__global__ void split_all(const float* __restrict__ hs, __half* __restrict__ hs_hi, __half* __restrict__ hs_lo,
                          const float* __restrict__ Wq, __half* __restrict__ wq_hi,
                          const float* __restrict__ Wk, __half* __restrict__ wk_hi, __half* __restrict__ wk_lo,
                          const float* __restrict__ Wv, __half* __restrict__ wv_hi,
                          const float* __restrict__ Wo, __half* __restrict__ wo_hi)
{
    int i = blockIdx.x * blockDim.x + threadIdx.x;
    if (i < N_HS4) {
        split_hilo4(hs, hs_hi, hs_lo, i);
    } else if (i < N_HS4 + N_WQ4) {
        split_hi4(Wq, wq_hi, i - N_HS4);
    } else if (i < N_HS4 + N_WQ4 + N_WK4) {
        split_hilo4(Wk, wk_hi, wk_lo, i - N_HS4 - N_WQ4);
    } else if (i < N_HS4 + N_WQ4 + N_WK4 + N_WV4) {
        split_hi4(Wv, wv_hi, i - N_HS4 - N_WQ4 - N_WK4);
    } else if (i < N_ALL4) {
        split_hi4(Wo, wo_hi, i - N_HS4 - N_WQ4 - N_WK4 - N_WV4);
    }
}

// RoPE, hi-only output (for Q and K)
__global__ void rope_hi(const float* __restrict__ buf,
                        const float* __restrict__ cosb,
                        const float* __restrict__ sinb,
                        __half* __restrict__ hi, int nheads)
{
    int i = blockIdx.x * blockDim.x + threadIdx.x;
    int total = nheads * S_LEN * 64;
    if (i >= total) return;
    int d = i & 63;
    int s = (i >> 6) & (S_LEN - 1);
    int h = i >> 17;
    const float* row = buf + ((size_t)h * S_LEN + s) * HD;
    float c1 = cosb[s * HD + d];
    float c2 = cosb[s * HD + d + 64];
    float s1 = sinb[s * HD + d];
    float s2 = sinb[s * HD + d + 64];
    float x1 = row[d];
    float x2 = row[d + 64];
    size_t o = ((size_t)h * S_LEN + s) * HD;
    hi[o + d]      = __float2half_rn(x1 * c1 - x2 * s1);
    hi[o + d + 64] = __float2half_rn(x2 * c2 + x1 * s2);
}

// ---------------- HMMA flash attention (causal, GQA) ----------------
// 128 threads = 4 warps; warp w owns q rows [w*16, w*16+16). BM=BN=64, D=128.
// Single-pass QK and PV, fp32 accum; K/V double-buffered via cp.async. 3 CTAs/SM.
#define ATT_STRIDE  136
#define ATT_ROWB    (ATT_STRIDE * 2)
#define ATT_BUFB    (64 * ATT_ROWB)
#define ATT_SMEM    (4 * ATT_BUFB)

__global__ void __launch_bounds__(128, 3)
attn_hmma(const __half* __restrict__ Qh,
          const __half* __restrict__ Kh,
          const __half* __restrict__ V,
          __half* __restrict__ AOh)
{
    extern __shared__ __align__(1024) char sa[];
    const uint32_t sbase = smem_u32(sa);

    const int qb  = (int)gridDim.x - 1 - (int)blockIdx.x;
    const int h   = blockIdx.y;
    const int kvh = h / GROUPS;
    const int tid = threadIdx.x, wid = tid >> 5, lane = tid & 31;

    int crow[8], cc16[8];
#pragma unroll
    for (int j = 0; j < 8; j++) {
        int v = tid + j * 128;
        crow[j] = v >> 4;
        cc16[j] = v & 15;
    }

    // ---- stage Q through buffer 0, extract A-fragments ----
    uint32_t qhf[8][4];
    const uint32_t a_addr = sbase + (uint32_t)((wid * 16 + (lane & 15)) * ATT_ROWB + (lane >> 4) * 16);
    {
        const __half* Qg = Qh + ((size_t)h * S_LEN + qb * 64) * HD;
#pragma unroll
        for (int j = 0; j < 8; j++)
            *(uint4*)(sa + crow[j] * ATT_ROWB + cc16[j] * 16) =
                *(const uint4*)(Qg + (size_t)crow[j] * HD + cc16[j] * 8);
        __syncthreads();
#pragma unroll
        for (int k = 0; k < 8; k++) ldsm4(qhf[k], a_addr + k * 32);
        __syncthreads();
    }

    const uint32_t kb_off = (uint32_t)((((lane >> 4) & 1) * 8 + (lane & 7)) * ATT_ROWB
                                       + ((lane >> 3) & 1) * 16);
    const uint32_t vb_off = (uint32_t)(((((lane >> 3) & 1) * 8) + (lane & 7)) * ATT_ROWB
                                       + (lane >> 4) * 16);

    float o[16][4];
#pragma unroll
    for (int dg = 0; dg < 16; dg++)
#pragma unroll
        for (int q = 0; q < 4; q++) o[dg][q] = 0.f;
    float m0 = -1e30f, m1 = -1e30f, l0 = 0.f, l1 = 0.f;

    // prologue: tile 0 -> buffer 0
    {
        const __half* Kg = Kh + ((size_t)kvh * S_LEN) * HD;
        const __half* Vg = V  + ((size_t)kvh * S_LEN) * HD;
#pragma unroll
        for (int j = 0; j < 8; j++) {
            uint32_t doff = (uint32_t)(crow[j] * ATT_ROWB + cc16[j] * 16);
            size_t goff = (size_t)crow[j] * HD + cc16[j] * 8;
            cp16(sbase + doff,            Kg + goff);
            cp16(sbase + ATT_BUFB + doff, Vg + goff);
        }
        cp_commit();
        cp_wait0();
    }
    __syncthreads();

    for (int kt = 0; kt <= qb; kt++) {
        const int buf = kt & 1;
        if (kt < qb) {
            const __half* Kg = Kh + ((size_t)kvh * S_LEN + (kt + 1) * 64) * HD;
            const __half* Vg = V  + ((size_t)kvh * S_LEN + (kt + 1) * 64) * HD;
            const uint32_t nboff = (uint32_t)((buf ^ 1) * 2 * ATT_BUFB);
#pragma unroll
            for (int j = 0; j < 8; j++) {
                uint32_t doff = (uint32_t)(crow[j] * ATT_ROWB + cc16[j] * 16);
                size_t goff = (size_t)crow[j] * HD + cc16[j] * 8;
                cp16(sbase + nboff + doff,            Kg + goff);
                cp16(sbase + nboff + ATT_BUFB + doff, Vg + goff);
            }
            cp_commit();
        }

        const uint32_t kbase = sbase + (uint32_t)(buf * 2 * ATT_BUFB);
        const uint32_t vbase = kbase + ATT_BUFB;

        // ---- S = Q K^T ----
        float sreg[8][4];
#pragma unroll
        for (int nt = 0; nt < 8; nt++)
#pragma unroll
            for (int q = 0; q < 4; q++) sreg[nt][q] = 0.f;

#pragma unroll
        for (int k = 0; k < 8; k++) {
            uint32_t kfh[4][4];
#pragma unroll
            for (int g = 0; g < 4; g++)
                ldsm4(kfh[g], kbase + kb_off + (uint32_t)(g * 16 * ATT_ROWB) + (uint32_t)(k * 32));
#pragma unroll
            for (int nt = 0; nt < 8; nt++)
                mma16816(sreg[nt], qhf[k], &kfh[nt >> 1][(nt & 1) * 2]);
        }

        if (kt == qb) {
            int r0 = wid * 16 + (lane >> 2);
            int r1 = r0 + 8;
#pragma unroll
            for (int nt = 0; nt < 8; nt++) {
                int cb = nt * 8 + (lane & 3) * 2;
                if (cb     > r0) sreg[nt][0] = -1e30f;
                if (cb + 1 > r0) sreg[nt][1] = -1e30f;
                if (cb     > r1) sreg[nt][2] = -1e30f;
                if (cb + 1 > r1) sreg[nt][3] = -1e30f;
            }
        }

        // ---- online softmax (raw-domain max; exp2 with folded scaling) ----
        float rmax0 = -1e30f, rmax1 = -1e30f;
#pragma unroll
        for (int nt = 0; nt < 8; nt++) {
            rmax0 = fmaxf(rmax0, fmaxf(sreg[nt][0], sreg[nt][1]));
            rmax1 = fmaxf(rmax1, fmaxf(sreg[nt][2], sreg[nt][3]));
        }
        rmax0 = fmaxf(rmax0, __shfl_xor_sync(0xffffffffu, rmax0, 1));
        rmax0 = fmaxf(rmax0, __shfl_xor_sync(0xffffffffu, rmax0, 2));
        rmax1 = fmaxf(rmax1, __shfl_xor_sync(0xffffffffu, rmax1, 1));
        rmax1 = fmaxf(rmax1, __shfl_xor_sync(0xffffffffu, rmax1, 2));
        float mn0 = fmaxf(m0, rmax0), mn1 = fmaxf(m1, rmax1);
        float corr0 = fexp2((m0 - mn0) * C2EXP);
        float corr1 = fexp2((m1 - mn1) * C2EXP);
        m0 = mn0; m1 = mn1;
        const float mc0 = m0 * C2EXP, mc1 = m1 * C2EXP;

        float rs0 = 0.f, rs1 = 0.f;
        uint32_t pah[4][4];
#pragma unroll
        for (int nt = 0; nt < 8; nt++) {
            float p0 = fexp2(fmaf(sreg[nt][0], C2EXP, -mc0));
            float p1 = fexp2(fmaf(sreg[nt][1], C2EXP, -mc0));
            float p2 = fexp2(fmaf(sreg[nt][2], C2EXP, -mc1));
            float p3 = fexp2(fmaf(sreg[nt][3], C2EXP, -mc1));
            rs0 += p0 + p1; rs1 += p2 + p3;
            int t = nt >> 1, pc = (nt & 1) * 2;
            pah[t][pc + 0] = packh2(__float2half_rn(p0), __float2half_rn(p1));
            pah[t][pc + 1] = packh2(__float2half_rn(p2), __float2half_rn(p3));
        }
        rs0 += __shfl_xor_sync(0xffffffffu, rs0, 1);
        rs0 += __shfl_xor_sync(0xffffffffu, rs0, 2);
        rs1 += __shfl_xor_sync(0xffffffffu, rs1, 1);
        rs1 += __shfl_xor_sync(0xffffffffu, rs1, 2);
        l0 = l0 * corr0 + rs0;
        l1 = l1 * corr1 + rs1;

#pragma unroll
        for (int dg = 0; dg < 16; dg++) {
            o[dg][0] *= corr0; o[dg][1] *= corr0;
            o[dg][2] *= corr1; o[dg][3] *= corr1;
        }

        // ---- O += P V ----
#pragma unroll
        for (int t = 0; t < 4; t++) {
#pragma unroll
            for (int pp = 0; pp < 8; pp++) {
                uint32_t vf[4];
                ldsm4t(vf, vbase + vb_off + (uint32_t)(t * 16 * ATT_ROWB) + (uint32_t)(pp * 32));
                mma16816(o[2 * pp],     pah[t], &vf[0]);
                mma16816(o[2 * pp + 1], pah[t], &vf[2]);
            }
        }

        if (kt < qb) cp_wait0();
        __syncthreads();
    }

    // ---- write AO (fp16), layout [s][h*128+d] ----
    float inv0 = 1.f / l0, inv1 = 1.f / l1;
    int r0g = qb * 64 + wid * 16 + (lane >> 2);
    size_t base0 = (size_t)r0g * (NH * HD) + (size_t)h * HD;
    size_t base1 = base0 + (size_t)8 * (NH * HD);
    int coff = (lane & 3) * 2;
#pragma unroll
    for (int dg = 0; dg < 16; dg++) {
        float x0 = o[dg][0] * inv0, x1 = o[dg][1] * inv0;
        float x2 = o[dg][2] * inv1, x3 = o[dg][3] * inv1;
        *(__half2*)(AOh + base0 + dg * 8 + coff) =
            __halves2half2(__float2half_rn(x0), __float2half_rn(x1));
        *(__half2*)(AOh + base1 + dg * 8 + coff) =
            __halves2half2(__float2half_rn(x2), __float2half_rn(x3));
    }
}

// ---------------- launch ----------------
extern "C" void kernel_launch(void* const* d_in, const int* in_sizes, int n_in,
                              void* d_out, int out_size)
{
    const float* hs   = (const float*)d_in[0];
    const float* cosb = (const float*)d_in[1];
    const float* sinb = (const float*)d_in[2];
    const float* Wq   = (const float*)d_in[3];
    const float* bq   = (const float*)d_in[4];
    const float* Wk   = (const float*)d_in[5];
    const float* bk   = (const float*)d_in[6];
    const float* Wv   = (const float*)d_in[7];
    const float* bv   = (const float*)d_in[8];
    const float* Wo   = (const float*)d_in[9];
    float* out = (float*)d_out;

    float *pq, *pk;
    cudaGetSymbolAddress((void**)&pq, g_q);
    cudaGetSymbolAddress((void**)&pk, g_k);

    __half *qh, *kh, *v16, *aoh;
    cudaGetSymbolAddress((void**)&qh,  g_qh);
    cudaGetSymbolAddress((void**)&kh,  g_kh);
    cudaGetSymbolAddress((void**)&v16, g_v16);
    cudaGetSymbolAddress((void**)&aoh, g_aoh);

    __half *hs_hi, *hs_lo, *wq_hi, *wk_hi, *wk_lo, *wv_hi, *wo_hi;
    cudaGetSymbolAddress((void**)&hs_hi, g_hs_hi);
    cudaGetSymbolAddress((void**)&hs_lo, g_hs_lo);
    cudaGetSymbolAddress((void**)&wq_hi, g_wq_hi);
    cudaGetSymbolAddress((void**)&wk_hi, g_wk_hi);
    cudaGetSymbolAddress((void**)&wk_lo, g_wk_lo);
    cudaGetSymbolAddress((void**)&wv_hi, g_wv_hi);
    cudaGetSymbolAddress((void**)&wo_hi, g_wo_hi);

    // one merged split launch
    split_all<<<(N_ALL4 + 255) / 256, 256>>>(hs, hs_hi, hs_lo, Wq, wq_hi,
                                             Wk, wk_hi, wk_lo, Wv, wv_hi, Wo, wo_hi);

    cudaFuncSetAttribute(qkv_fused, cudaFuncAttributeMaxDynamicSharedMemorySize, GEMM_SMEM);
    cudaFuncSetAttribute(gemm_tc,   cudaFuncAttributeMaxDynamicSharedMemorySize, GEMM_SMEM);

    // fused QKV projections (Q 1-pass fp32; K 3-pass fp32; V 2-pass fp16)
    qkv_fused<<<dim3(36, 16), 256, GEMM_SMEM>>>(hs_hi, hs_lo,
                                                wq_hi, bq, pq,
                                                wk_hi, wk_lo, bk, pk,
                                                wv_hi, bv, v16);

    // RoPE: Q, K -> fp16 hi only
    rope_hi<<<(NH  * S_LEN * 64 + 255) / 256, 256>>>(pq, cosb, sinb, qh, NH);
    rope_hi<<<(NKV * S_LEN * 64 + 255) / 256, 256>>>(pk, cosb, sinb, kh, NKV);

    // HMMA flash attention
    cudaFuncSetAttribute(attn_hmma, cudaFuncAttributeMaxDynamicSharedMemorySize, ATT_SMEM);
    attn_hmma<<<dim3(S_LEN / 64, NH), 128, ATT_SMEM>>>(qh, kh, v16, aoh);

    // O projection (1-pass: AOh * Wo_hi), fp32 row-major out
    gemm_tc<<<dim3(NH, 16), 256, GEMM_SMEM>>>(aoh, nullptr, wo_hi, nullptr, nullptr, out, nullptr,
                                              S_LEN, HIDDEN, NH * HD, 1);
}